// round 1
// baseline (speedup 1.0000x reference)
#include <cuda_runtime.h>
#include <math.h>

#define NRES 384
#define NNPIX (NRES*NRES)          // 147456
#define CH 128
#define NH 4
#define KD 32
#define QSCALE 0.17677669529663689f  // 1/sqrt(32)

// ---------------- scratch (device globals; no allocation allowed) ----------
__device__ __align__(16) float g_x  [(size_t)NNPIX*CH];  // layernormed input
__device__ __align__(16) float g_nb [(size_t)NH*NNPIX];  // triangle bias [h][q][k]
__device__ __align__(16) float g_q  [(size_t)NNPIX*CH];
__device__ __align__(16) float g_k  [(size_t)NNPIX*CH];
__device__ __align__(16) float g_v  [(size_t)NNPIX*CH];
__device__ __align__(16) float g_g  [(size_t)NNPIX*CH];  // sigmoid gate
__device__ __align__(16) float g_att[(size_t)NNPIX*CH];  // gated attention out

// ---------------- kernel 1: LayerNorm + nonbatched bias --------------------
// one warp per pixel; lane holds 4 channels as float4
__global__ __launch_bounds__(256) void ln_nb_kernel(
    const float* __restrict__ pact, const float* __restrict__ lns,
    const float* __restrict__ lnb, const float* __restrict__ f2w)
{
    const int warp = threadIdx.x >> 5, lane = threadIdx.x & 31;
    const size_t p = (size_t)blockIdx.x * 8 + warp;
    float4 v = ((const float4*)(pact + p*CH))[lane];
    float s = v.x + v.y + v.z + v.w;
    #pragma unroll
    for (int o = 16; o; o >>= 1) s += __shfl_xor_sync(0xffffffffu, s, o);
    const float mu = s * (1.0f/CH);
    const float dx = v.x-mu, dy = v.y-mu, dz = v.z-mu, dw = v.w-mu;
    float ss = dx*dx + dy*dy + dz*dz + dw*dw;
    #pragma unroll
    for (int o = 16; o; o >>= 1) ss += __shfl_xor_sync(0xffffffffu, ss, o);
    const float inv = rsqrtf(ss * (1.0f/CH) + 1e-5f);
    const float4 sc = ((const float4*)lns)[lane];
    const float4 bi = ((const float4*)lnb)[lane];
    float4 xn;
    xn.x = dx*inv*sc.x + bi.x;
    xn.y = dy*inv*sc.y + bi.y;
    xn.z = dz*inv*sc.z + bi.z;
    xn.w = dw*inv*sc.w + bi.w;
    ((float4*)(g_x + p*CH))[lane] = xn;

    // nb[h] = sum_c xn[c] * f2w[c][h]; f2w is [128][4] -> one float4 per c
    const float4* w4 = (const float4*)f2w;
    const float4 w0 = w4[lane*4+0], w1 = w4[lane*4+1],
                 w2 = w4[lane*4+2], w3 = w4[lane*4+3];
    float n0 = xn.x*w0.x + xn.y*w1.x + xn.z*w2.x + xn.w*w3.x;
    float n1 = xn.x*w0.y + xn.y*w1.y + xn.z*w2.y + xn.w*w3.y;
    float n2 = xn.x*w0.z + xn.y*w1.z + xn.z*w2.z + xn.w*w3.z;
    float n3 = xn.x*w0.w + xn.y*w1.w + xn.z*w2.w + xn.w*w3.w;
    #pragma unroll
    for (int o = 16; o; o >>= 1) {
        n0 += __shfl_xor_sync(0xffffffffu, n0, o);
        n1 += __shfl_xor_sync(0xffffffffu, n1, o);
        n2 += __shfl_xor_sync(0xffffffffu, n2, o);
        n3 += __shfl_xor_sync(0xffffffffu, n3, o);
    }
    if (lane == 0) {
        g_nb[0*(size_t)NNPIX + p] = n0;
        g_nb[1*(size_t)NNPIX + p] = n1;
        g_nb[2*(size_t)NNPIX + p] = n2;
        g_nb[3*(size_t)NNPIX + p] = n3;
    }
}

// ---------------- kernel 2: q/k/v/gate projections --------------------------
// 64-row tile of X in smem (129-padded), full 128x128 W in smem.
// thread (r = tid/4, cq = tid%4) owns output float4 columns cq+4j, j=0..7.
__global__ __launch_bounds__(256) void proj_kernel(
    const float* __restrict__ qw, const float* __restrict__ kw,
    const float* __restrict__ vw, const float* __restrict__ gw,
    const float* __restrict__ gb)
{
    extern __shared__ float sm[];
    float* xs = sm;               // [64][129]
    float* ws = sm + 64*129;      // [128][128]
    const int tid = threadIdx.x;
    const int r0  = blockIdx.x * 64;

    for (int i = tid; i < 64*32; i += 256) {
        const int r = i >> 5, c4 = i & 31;
        float4 v = ((const float4*)(g_x + (size_t)(r0 + r)*CH))[c4];
        float* d = xs + r*129 + c4*4;
        d[0]=v.x; d[1]=v.y; d[2]=v.z; d[3]=v.w;
    }

    const int r = tid >> 2, cq = tid & 3;
    for (int m = 0; m < 4; ++m) {
        const float* W = (m==0) ? qw : (m==1) ? kw : (m==2) ? vw : gw;
        __syncthreads();
        for (int i = tid; i < 128*32; i += 256)
            ((float4*)ws)[i] = ((const float4*)W)[i];
        __syncthreads();

        float4 acc[8];
        #pragma unroll
        for (int j = 0; j < 8; ++j) acc[j] = make_float4(0.f,0.f,0.f,0.f);

        #pragma unroll 4
        for (int k = 0; k < 128; ++k) {
            const float xv = xs[r*129 + k];
            const float4* wr = (const float4*)(ws + k*128);
            #pragma unroll
            for (int j = 0; j < 8; ++j) {
                const float4 w = wr[cq + 4*j];
                acc[j].x += xv*w.x; acc[j].y += xv*w.y;
                acc[j].z += xv*w.z; acc[j].w += xv*w.w;
            }
        }

        float* outp = (m==0) ? g_q : (m==1) ? g_k : (m==2) ? g_v : g_g;
        const size_t rowoff = (size_t)(r0 + r)*CH;
        #pragma unroll
        for (int j = 0; j < 8; ++j) {
            float4 a = acc[j];
            if (m == 0) { a.x*=QSCALE; a.y*=QSCALE; a.z*=QSCALE; a.w*=QSCALE; }
            if (m == 3) {
                const float4 bb = ((const float4*)gb)[cq + 4*j];
                a.x = 1.f/(1.f + __expf(-(a.x + bb.x)));
                a.y = 1.f/(1.f + __expf(-(a.y + bb.y)));
                a.z = 1.f/(1.f + __expf(-(a.z + bb.z)));
                a.w = 1.f/(1.f + __expf(-(a.w + bb.w)));
            }
            ((float4*)(outp + rowoff))[cq + 4*j] = a;
        }
    }
}

// ---------------- kernel 3: per-(row,head) softmax attention ----------------
__global__ __launch_bounds__(256) void attn_kernel(const float* __restrict__ mask)
{
    extern __shared__ float sm[];
    float* ks   = sm;                 // [384][33] (padded)
    float* vs   = sm + 384*33;        // [384][32]
    float* wb   = vs + 384*32;        // [8][384] per-warp softmax weights
    float* mrow = wb + 8*384;         // [384] mask bias
    const int b = blockIdx.x, h = blockIdx.y;
    const int tid = threadIdx.x, warp = tid >> 5, lane = tid & 31;

    for (int i = tid; i < 384*8; i += 256) {
        const int row = i >> 3, c4 = i & 7;
        const size_t base = ((size_t)(b*NRES) + row)*CH + h*KD;
        float4 kv = ((const float4*)(g_k + base))[c4];
        float* kd = ks + row*33 + c4*4;
        kd[0]=kv.x; kd[1]=kv.y; kd[2]=kv.z; kd[3]=kv.w;
        ((float4*)(vs + row*32))[c4] = ((const float4*)(g_v + base))[c4];
    }
    for (int i = tid; i < NRES; i += 256)
        mrow[i] = 1e9f * (mask[(size_t)b*NRES + i] - 1.f);
    __syncthreads();

    float* myw = wb + warp*NRES;
    for (int q = warp; q < NRES; q += 8) {
        const float qd = g_q[((size_t)(b*NRES)+q)*CH + h*KD + lane];
        float lg[12];
        #pragma unroll
        for (int t = 0; t < 12; ++t) lg[t] = 0.f;
        #pragma unroll 4
        for (int d = 0; d < 32; ++d) {
            const float qb = __shfl_sync(0xffffffffu, qd, d);
            #pragma unroll
            for (int t = 0; t < 12; ++t)
                lg[t] += qb * ks[(lane + 32*t)*33 + d];
        }
        const float* nbp = g_nb + ((size_t)h*NRES + q)*NRES;
        float mx = -1e30f;
        #pragma unroll
        for (int t = 0; t < 12; ++t) {
            const int j = lane + 32*t;
            lg[t] += mrow[j] + nbp[j];
            mx = fmaxf(mx, lg[t]);
        }
        #pragma unroll
        for (int o = 16; o; o >>= 1) mx = fmaxf(mx, __shfl_xor_sync(0xffffffffu, mx, o));
        float s = 0.f;
        #pragma unroll
        for (int t = 0; t < 12; ++t) { lg[t] = __expf(lg[t] - mx); s += lg[t]; }
        #pragma unroll
        for (int o = 16; o; o >>= 1) s += __shfl_xor_sync(0xffffffffu, s, o);
        const float invs = 1.f / s;
        #pragma unroll
        for (int t = 0; t < 12; ++t) myw[lane + 32*t] = lg[t] * invs;
        __syncwarp();

        float a0=0.f, a1=0.f, a2=0.f, a3=0.f;
        for (int j = 0; j < NRES; j += 4) {
            a0 += myw[j+0] * vs[(j+0)*32 + lane];
            a1 += myw[j+1] * vs[(j+1)*32 + lane];
            a2 += myw[j+2] * vs[(j+2)*32 + lane];
            a3 += myw[j+3] * vs[(j+3)*32 + lane];
        }
        const size_t oi = ((size_t)(b*NRES)+q)*CH + h*KD + lane;
        g_att[oi] = ((a0+a1)+(a2+a3)) * g_g[oi];
        __syncwarp();
    }
}

// ---------------- kernel 4: output projection -------------------------------
__global__ __launch_bounds__(256) void out_kernel(
    const float* __restrict__ ow, const float* __restrict__ ob,
    float* __restrict__ out)
{
    extern __shared__ float sm[];
    float* xs = sm;               // [64][129]
    float* ws = sm + 64*129;      // [128][128]
    const int tid = threadIdx.x;
    const int r0  = blockIdx.x * 64;

    for (int i = tid; i < 64*32; i += 256) {
        const int r = i >> 5, c4 = i & 31;
        float4 v = ((const float4*)(g_att + (size_t)(r0 + r)*CH))[c4];
        float* d = xs + r*129 + c4*4;
        d[0]=v.x; d[1]=v.y; d[2]=v.z; d[3]=v.w;
    }
    for (int i = tid; i < 128*32; i += 256)
        ((float4*)ws)[i] = ((const float4*)ow)[i];
    __syncthreads();

    const int r = tid >> 2, cq = tid & 3;
    float4 acc[8];
    #pragma unroll
    for (int j = 0; j < 8; ++j) acc[j] = make_float4(0.f,0.f,0.f,0.f);

    #pragma unroll 4
    for (int k = 0; k < 128; ++k) {
        const float xv = xs[r*129 + k];
        const float4* wr = (const float4*)(ws + k*128);
        #pragma unroll
        for (int j = 0; j < 8; ++j) {
            const float4 w = wr[cq + 4*j];
            acc[j].x += xv*w.x; acc[j].y += xv*w.y;
            acc[j].z += xv*w.z; acc[j].w += xv*w.w;
        }
    }
    const size_t rowoff = (size_t)(r0 + r)*CH;
    #pragma unroll
    for (int j = 0; j < 8; ++j) {
        const float4 bb = ((const float4*)ob)[cq + 4*j];
        float4 a = acc[j];
        a.x += bb.x; a.y += bb.y; a.z += bb.z; a.w += bb.w;
        ((float4*)(out + rowoff))[cq + 4*j] = a;
    }
}

// ---------------- launcher ---------------------------------------------------
extern "C" void kernel_launch(void* const* d_in, const int* in_sizes, int n_in,
                              void* d_out, int out_size)
{
    const float* pact = (const float*)d_in[0];
    const float* mask = (const float*)d_in[1];
    const float* lns  = (const float*)d_in[2];
    const float* lnb  = (const float*)d_in[3];
    const float* f2w  = (const float*)d_in[4];
    const float* qw   = (const float*)d_in[5];
    const float* kw   = (const float*)d_in[6];
    const float* vw   = (const float*)d_in[7];
    const float* gw   = (const float*)d_in[8];
    const float* gb   = (const float*)d_in[9];
    const float* ow   = (const float*)d_in[10];
    const float* ob   = (const float*)d_in[11];
    float* out = (float*)d_out;

    const int PROJ_SMEM = (64*129 + 128*128) * 4;          // 98560 B
    const int ATTN_SMEM = (384*33 + 384*32 + 8*384 + 384) * 4;  // 113664 B

    cudaFuncSetAttribute(proj_kernel, cudaFuncAttributeMaxDynamicSharedMemorySize, PROJ_SMEM);
    cudaFuncSetAttribute(attn_kernel, cudaFuncAttributeMaxDynamicSharedMemorySize, ATTN_SMEM);
    cudaFuncSetAttribute(out_kernel,  cudaFuncAttributeMaxDynamicSharedMemorySize, PROJ_SMEM);

    ln_nb_kernel<<<NNPIX/8, 256>>>(pact, lns, lnb, f2w);
    proj_kernel<<<NNPIX/64, 256, PROJ_SMEM>>>(qw, kw, vw, gw, gb);
    attn_kernel<<<dim3(NRES, NH), 256, ATTN_SMEM>>>(mask);
    out_kernel<<<NNPIX/64, 256, PROJ_SMEM>>>(ow, ob, out);
}

// round 2
// speedup vs baseline: 1.8450x; 1.8450x over previous
#include <cuda_runtime.h>
#include <math.h>

#define NRES 384
#define NNPIX (NRES*NRES)          // 147456
#define CH 128
#define NH 4
#define KD 32
#define QSCALE 0.17677669529663689f  // 1/sqrt(32)

#define PADA 132   // X smem pad (words): bank = 4*gr+gc -> conflict-free
#define PADB 136   // W smem pad (words): bank = 8*gc+gr -> conflict-free
#define PADV 388   // transposed V pad (words), float4-aligned, conflict-free

// ---------------- scratch (device globals; no allocation allowed) ----------
__device__ __align__(16) float g_x  [(size_t)NNPIX*CH];
__device__ __align__(16) float g_nb [(size_t)NH*NNPIX];
__device__ __align__(16) float g_q  [(size_t)NNPIX*CH];
__device__ __align__(16) float g_k  [(size_t)NNPIX*CH];
__device__ __align__(16) float g_v  [(size_t)NNPIX*CH];
__device__ __align__(16) float g_g  [(size_t)NNPIX*CH];
__device__ __align__(16) float g_att[(size_t)NNPIX*CH];

// ---------------- tf32 mma helpers -----------------------------------------
__device__ __forceinline__ unsigned f2tf32(float f) {
    unsigned u;
    asm("cvt.rna.tf32.f32 %0, %1;" : "=r"(u) : "f"(f));
    return u;
}
__device__ __forceinline__ void mma_tf32(float c[4], const unsigned a[4], const unsigned b[2]) {
    asm volatile(
        "mma.sync.aligned.m16n8k8.row.col.f32.tf32.tf32.f32 "
        "{%0,%1,%2,%3}, {%4,%5,%6,%7}, {%8,%9}, {%0,%1,%2,%3};"
        : "+f"(c[0]), "+f"(c[1]), "+f"(c[2]), "+f"(c[3])
        : "r"(a[0]), "r"(a[1]), "r"(a[2]), "r"(a[3]), "r"(b[0]), "r"(b[1]));
}

// ---------------- kernel 1: LayerNorm + nonbatched bias --------------------
__global__ __launch_bounds__(256) void ln_nb_kernel(
    const float* __restrict__ pact, const float* __restrict__ lns,
    const float* __restrict__ lnb, const float* __restrict__ f2w)
{
    const int warp = threadIdx.x >> 5, lane = threadIdx.x & 31;
    const size_t p = (size_t)blockIdx.x * 8 + warp;
    float4 v = ((const float4*)(pact + p*CH))[lane];
    float s = v.x + v.y + v.z + v.w;
    #pragma unroll
    for (int o = 16; o; o >>= 1) s += __shfl_xor_sync(0xffffffffu, s, o);
    const float mu = s * (1.0f/CH);
    const float dx = v.x-mu, dy = v.y-mu, dz = v.z-mu, dw = v.w-mu;
    float ss = dx*dx + dy*dy + dz*dz + dw*dw;
    #pragma unroll
    for (int o = 16; o; o >>= 1) ss += __shfl_xor_sync(0xffffffffu, ss, o);
    const float inv = rsqrtf(ss * (1.0f/CH) + 1e-5f);
    const float4 sc = ((const float4*)lns)[lane];
    const float4 bi = ((const float4*)lnb)[lane];
    float4 xn;
    xn.x = dx*inv*sc.x + bi.x;
    xn.y = dy*inv*sc.y + bi.y;
    xn.z = dz*inv*sc.z + bi.z;
    xn.w = dw*inv*sc.w + bi.w;
    ((float4*)(g_x + p*CH))[lane] = xn;

    const float4* w4 = (const float4*)f2w;
    const float4 w0 = w4[lane*4+0], w1 = w4[lane*4+1],
                 w2 = w4[lane*4+2], w3 = w4[lane*4+3];
    float n0 = xn.x*w0.x + xn.y*w1.x + xn.z*w2.x + xn.w*w3.x;
    float n1 = xn.x*w0.y + xn.y*w1.y + xn.z*w2.y + xn.w*w3.y;
    float n2 = xn.x*w0.z + xn.y*w1.z + xn.z*w2.z + xn.w*w3.z;
    float n3 = xn.x*w0.w + xn.y*w1.w + xn.z*w2.w + xn.w*w3.w;
    #pragma unroll
    for (int o = 16; o; o >>= 1) {
        n0 += __shfl_xor_sync(0xffffffffu, n0, o);
        n1 += __shfl_xor_sync(0xffffffffu, n1, o);
        n2 += __shfl_xor_sync(0xffffffffu, n2, o);
        n3 += __shfl_xor_sync(0xffffffffu, n3, o);
    }
    if (lane == 0) {
        g_nb[0*(size_t)NNPIX + p] = n0;
        g_nb[1*(size_t)NNPIX + p] = n1;
        g_nb[2*(size_t)NNPIX + p] = n2;
        g_nb[3*(size_t)NNPIX + p] = n3;
    }
}

// ---------------- kernel 2: q/k/v/gate via tf32 mma -------------------------
// block: 256 thr (8 warps: 4 m-tiles x 2 n-tiles), tile M=128, N=128.
// warp tile: 32x64 -> c[2 mfrag][8 nfrag][4].
__global__ __launch_bounds__(256) void proj_mma_kernel(
    const float* __restrict__ qw, const float* __restrict__ kw,
    const float* __restrict__ vw, const float* __restrict__ gw,
    const float* __restrict__ gb)
{
    extern __shared__ unsigned smu[];
    unsigned* xs = smu;               // [128][PADA] tf32 bits
    unsigned* ws = smu + 128*PADA;    // [128][PADB] tf32 bits
    const int tid = threadIdx.x;
    const int warp = tid >> 5, lane = tid & 31;
    const int gr = lane >> 2, gc = lane & 3;
    const int mw = warp & 3, nw = warp >> 2;
    const int rw0 = mw * 32, nw0 = nw * 64;
    const int r0 = blockIdx.x * 128;

    for (int i = tid; i < 128*32; i += 256) {
        const int r = i >> 5, c4 = i & 31;
        float4 v = ((const float4*)(g_x + (size_t)(r0 + r)*CH))[c4];
        unsigned* d = xs + r*PADA + c4*4;
        d[0]=f2tf32(v.x); d[1]=f2tf32(v.y); d[2]=f2tf32(v.z); d[3]=f2tf32(v.w);
    }

    for (int m = 0; m < 4; ++m) {
        const float* W = (m==0) ? qw : (m==1) ? kw : (m==2) ? vw : gw;
        __syncthreads();
        for (int i = tid; i < 128*32; i += 256) {
            const int k = i >> 5, c4 = i & 31;
            float4 v = ((const float4*)(W + (size_t)k*CH))[c4];
            unsigned* d = ws + k*PADB + c4*4;
            d[0]=f2tf32(v.x); d[1]=f2tf32(v.y); d[2]=f2tf32(v.z); d[3]=f2tf32(v.w);
        }
        __syncthreads();

        float c[2][8][4];
        #pragma unroll
        for (int mi = 0; mi < 2; ++mi)
            #pragma unroll
            for (int ni = 0; ni < 8; ++ni)
                #pragma unroll
                for (int t = 0; t < 4; ++t) c[mi][ni][t] = 0.f;

        #pragma unroll 4
        for (int kk = 0; kk < 16; ++kk) {
            const int k0 = kk * 8;
            unsigned a[2][4];
            #pragma unroll
            for (int mi = 0; mi < 2; ++mi) {
                const int rb = rw0 + mi*16;
                a[mi][0] = xs[(rb+gr  )*PADA + k0+gc  ];
                a[mi][1] = xs[(rb+gr+8)*PADA + k0+gc  ];
                a[mi][2] = xs[(rb+gr  )*PADA + k0+gc+4];
                a[mi][3] = xs[(rb+gr+8)*PADA + k0+gc+4];
            }
            unsigned b[8][2];
            #pragma unroll
            for (int ni = 0; ni < 8; ++ni) {
                const int n0 = nw0 + ni*8 + gr;
                b[ni][0] = ws[(k0+gc  )*PADB + n0];
                b[ni][1] = ws[(k0+gc+4)*PADB + n0];
            }
            #pragma unroll
            for (int mi = 0; mi < 2; ++mi)
                #pragma unroll
                for (int ni = 0; ni < 8; ++ni)
                    mma_tf32(c[mi][ni], a[mi], b[ni]);
        }

        float* outp = (m==0) ? g_q : (m==1) ? g_k : (m==2) ? g_v : g_g;
        #pragma unroll
        for (int mi = 0; mi < 2; ++mi) {
            const int row0 = r0 + rw0 + mi*16 + gr;
            #pragma unroll
            for (int ni = 0; ni < 8; ++ni) {
                const int col = nw0 + ni*8 + (lane & 3)*2;
                float v0x = c[mi][ni][0], v0y = c[mi][ni][1];
                float v1x = c[mi][ni][2], v1y = c[mi][ni][3];
                if (m == 0) { v0x*=QSCALE; v0y*=QSCALE; v1x*=QSCALE; v1y*=QSCALE; }
                if (m == 3) {
                    const float2 bb = *(const float2*)(gb + col);
                    v0x = 1.f/(1.f + __expf(-(v0x + bb.x)));
                    v0y = 1.f/(1.f + __expf(-(v0y + bb.y)));
                    v1x = 1.f/(1.f + __expf(-(v1x + bb.x)));
                    v1y = 1.f/(1.f + __expf(-(v1y + bb.y)));
                }
                *(float2*)(outp + (size_t)row0*CH + col)     = make_float2(v0x, v0y);
                *(float2*)(outp + (size_t)(row0+8)*CH + col) = make_float2(v1x, v1y);
            }
        }
    }
}

// ---------------- kernel 3: attention (4 q-rows per warp group) -------------
__global__ __launch_bounds__(256) void attn_kernel(const float* __restrict__ mask)
{
    extern __shared__ float sm[];
    float* ks   = sm;                         // [384][33]
    float* vs_t = sm + 384*33;                // [32][PADV] transposed V
    float* wb   = vs_t + 32*PADV;             // [8 warps][384][4]
    float* mrow = wb + 8*384*4;               // [384]
    const int b = blockIdx.x, h = blockIdx.y;
    const int tid = threadIdx.x, warp = tid >> 5, lane = tid & 31;

    for (int i = tid; i < 384*8; i += 256) {
        const int row = i >> 3, c4 = i & 7;
        const size_t base = ((size_t)(b*NRES) + row)*CH + h*KD;
        float4 kv = ((const float4*)(g_k + base))[c4];
        float* kd = ks + row*33 + c4*4;
        kd[0]=kv.x; kd[1]=kv.y; kd[2]=kv.z; kd[3]=kv.w;
        float4 vv = ((const float4*)(g_v + base))[c4];
        vs_t[(c4*4+0)*PADV + row] = vv.x;
        vs_t[(c4*4+1)*PADV + row] = vv.y;
        vs_t[(c4*4+2)*PADV + row] = vv.z;
        vs_t[(c4*4+3)*PADV + row] = vv.w;
    }
    for (int i = tid; i < NRES; i += 256)
        mrow[i] = 1e9f * (mask[(size_t)b*NRES + i] - 1.f);
    __syncthreads();

    float* mywb = wb + warp*384*4;
    float4* mywb4 = (float4*)mywb;
    const float4* vt = (const float4*)(vs_t + lane*PADV);

    for (int i = 0; i < 12; ++i) {
        const int q0 = i*32 + warp*4;
        float qd[4];
        #pragma unroll
        for (int r = 0; r < 4; ++r)
            qd[r] = g_q[((size_t)(b*NRES)+q0+r)*CH + h*KD + lane];

        float lg[4][12];
        #pragma unroll
        for (int r = 0; r < 4; ++r)
            #pragma unroll
            for (int t = 0; t < 12; ++t) lg[r][t] = 0.f;

        #pragma unroll 4
        for (int d = 0; d < 32; ++d) {
            float qb0 = __shfl_sync(0xffffffffu, qd[0], d);
            float qb1 = __shfl_sync(0xffffffffu, qd[1], d);
            float qb2 = __shfl_sync(0xffffffffu, qd[2], d);
            float qb3 = __shfl_sync(0xffffffffu, qd[3], d);
            #pragma unroll
            for (int t = 0; t < 12; ++t) {
                const float kv = ks[(lane + 32*t)*33 + d];
                lg[0][t] += qb0 * kv;
                lg[1][t] += qb1 * kv;
                lg[2][t] += qb2 * kv;
                lg[3][t] += qb3 * kv;
            }
        }

        float invs[4];
        #pragma unroll
        for (int r = 0; r < 4; ++r) {
            const float* nbp = g_nb + ((size_t)h*NNPIX) + (size_t)(q0+r)*NRES;
            float mx = -1e30f;
            #pragma unroll
            for (int t = 0; t < 12; ++t) {
                const int j = lane + 32*t;
                lg[r][t] += mrow[j] + nbp[j];
                mx = fmaxf(mx, lg[r][t]);
            }
            #pragma unroll
            for (int o = 16; o; o >>= 1)
                mx = fmaxf(mx, __shfl_xor_sync(0xffffffffu, mx, o));
            float s = 0.f;
            #pragma unroll
            for (int t = 0; t < 12; ++t) { lg[r][t] = __expf(lg[r][t] - mx); s += lg[r][t]; }
            #pragma unroll
            for (int o = 16; o; o >>= 1) s += __shfl_xor_sync(0xffffffffu, s, o);
            invs[r] = 1.f / s;
        }
        #pragma unroll
        for (int t = 0; t < 12; ++t) {
            float4 w4;
            w4.x = lg[0][t]*invs[0]; w4.y = lg[1][t]*invs[1];
            w4.z = lg[2][t]*invs[2]; w4.w = lg[3][t]*invs[3];
            mywb4[lane + 32*t] = w4;
        }
        __syncwarp();

        float a0=0.f, a1=0.f, a2=0.f, a3=0.f;
        #pragma unroll 2
        for (int j = 0; j < NRES; j += 4) {
            const float4 w0 = mywb4[j+0], w1 = mywb4[j+1],
                         w2 = mywb4[j+2], w3 = mywb4[j+3];
            const float4 v = vt[j >> 2];
            a0 += w0.x*v.x + w1.x*v.y + w2.x*v.z + w3.x*v.w;
            a1 += w0.y*v.x + w1.y*v.y + w2.y*v.z + w3.y*v.w;
            a2 += w0.z*v.x + w1.z*v.y + w2.z*v.z + w3.z*v.w;
            a3 += w0.w*v.x + w1.w*v.y + w2.w*v.z + w3.w*v.w;
        }
        const size_t ob = ((size_t)(b*NRES)+q0)*CH + h*KD + lane;
        g_att[ob        ] = a0 * g_g[ob        ];
        g_att[ob + CH   ] = a1 * g_g[ob + CH   ];
        g_att[ob + 2*CH ] = a2 * g_g[ob + 2*CH ];
        g_att[ob + 3*CH ] = a3 * g_g[ob + 3*CH ];
        __syncwarp();
    }
}

// ---------------- kernel 4: output projection via tf32 mma ------------------
__global__ __launch_bounds__(256) void out_mma_kernel(
    const float* __restrict__ ow, const float* __restrict__ ob,
    float* __restrict__ out)
{
    extern __shared__ unsigned smu[];
    unsigned* xs = smu;
    unsigned* ws = smu + 128*PADA;
    const int tid = threadIdx.x;
    const int warp = tid >> 5, lane = tid & 31;
    const int gr = lane >> 2, gc = lane & 3;
    const int mw = warp & 3, nw = warp >> 2;
    const int rw0 = mw * 32, nw0 = nw * 64;
    const int r0 = blockIdx.x * 128;

    for (int i = tid; i < 128*32; i += 256) {
        const int r = i >> 5, c4 = i & 31;
        float4 v = ((const float4*)(g_att + (size_t)(r0 + r)*CH))[c4];
        unsigned* d = xs + r*PADA + c4*4;
        d[0]=f2tf32(v.x); d[1]=f2tf32(v.y); d[2]=f2tf32(v.z); d[3]=f2tf32(v.w);
    }
    for (int i = tid; i < 128*32; i += 256) {
        const int k = i >> 5, c4 = i & 31;
        float4 v = ((const float4*)(ow + (size_t)k*CH))[c4];
        unsigned* d = ws + k*PADB + c4*4;
        d[0]=f2tf32(v.x); d[1]=f2tf32(v.y); d[2]=f2tf32(v.z); d[3]=f2tf32(v.w);
    }
    __syncthreads();

    float c[2][8][4];
    #pragma unroll
    for (int mi = 0; mi < 2; ++mi)
        #pragma unroll
        for (int ni = 0; ni < 8; ++ni)
            #pragma unroll
            for (int t = 0; t < 4; ++t) c[mi][ni][t] = 0.f;

    #pragma unroll 4
    for (int kk = 0; kk < 16; ++kk) {
        const int k0 = kk * 8;
        unsigned a[2][4];
        #pragma unroll
        for (int mi = 0; mi < 2; ++mi) {
            const int rb = rw0 + mi*16;
            a[mi][0] = xs[(rb+gr  )*PADA + k0+gc  ];
            a[mi][1] = xs[(rb+gr+8)*PADA + k0+gc  ];
            a[mi][2] = xs[(rb+gr  )*PADA + k0+gc+4];
            a[mi][3] = xs[(rb+gr+8)*PADA + k0+gc+4];
        }
        unsigned b[8][2];
        #pragma unroll
        for (int ni = 0; ni < 8; ++ni) {
            const int n0 = nw0 + ni*8 + gr;
            b[ni][0] = ws[(k0+gc  )*PADB + n0];
            b[ni][1] = ws[(k0+gc+4)*PADB + n0];
        }
        #pragma unroll
        for (int mi = 0; mi < 2; ++mi)
            #pragma unroll
            for (int ni = 0; ni < 8; ++ni)
                mma_tf32(c[mi][ni], a[mi], b[ni]);
    }

    #pragma unroll
    for (int mi = 0; mi < 2; ++mi) {
        const int row0 = r0 + rw0 + mi*16 + gr;
        #pragma unroll
        for (int ni = 0; ni < 8; ++ni) {
            const int col = nw0 + ni*8 + (lane & 3)*2;
            const float2 bb = *(const float2*)(ob + col);
            *(float2*)(out + (size_t)row0*CH + col) =
                make_float2(c[mi][ni][0] + bb.x, c[mi][ni][1] + bb.y);
            *(float2*)(out + (size_t)(row0+8)*CH + col) =
                make_float2(c[mi][ni][2] + bb.x, c[mi][ni][3] + bb.y);
        }
    }
}

// ---------------- launcher ---------------------------------------------------
extern "C" void kernel_launch(void* const* d_in, const int* in_sizes, int n_in,
                              void* d_out, int out_size)
{
    const float* pact = (const float*)d_in[0];
    const float* mask = (const float*)d_in[1];
    const float* lns  = (const float*)d_in[2];
    const float* lnb  = (const float*)d_in[3];
    const float* f2w  = (const float*)d_in[4];
    const float* qw   = (const float*)d_in[5];
    const float* kw   = (const float*)d_in[6];
    const float* vw   = (const float*)d_in[7];
    const float* gw   = (const float*)d_in[8];
    const float* gb   = (const float*)d_in[9];
    const float* ow   = (const float*)d_in[10];
    const float* ob   = (const float*)d_in[11];
    float* out = (float*)d_out;

    const int GEMM_SMEM = (128*PADA + 128*PADB) * 4;                 // 137216
    const int ATTN_SMEM = (384*33 + 32*PADV + 8*384*4 + 384) * 4;    // 151040

    cudaFuncSetAttribute(proj_mma_kernel, cudaFuncAttributeMaxDynamicSharedMemorySize, GEMM_SMEM);
    cudaFuncSetAttribute(out_mma_kernel,  cudaFuncAttributeMaxDynamicSharedMemorySize, GEMM_SMEM);
    cudaFuncSetAttribute(attn_kernel,     cudaFuncAttributeMaxDynamicSharedMemorySize, ATTN_SMEM);

    ln_nb_kernel<<<NNPIX/8, 256>>>(pact, lns, lnb, f2w);
    proj_mma_kernel<<<NNPIX/128, 256, GEMM_SMEM>>>(qw, kw, vw, gw, gb);
    attn_kernel<<<dim3(NRES, NH), 256, ATTN_SMEM>>>(mask);
    out_mma_kernel<<<NNPIX/128, 256, GEMM_SMEM>>>(ow, ob, out);
}

// round 3
// speedup vs baseline: 4.0662x; 2.2040x over previous
#include <cuda_runtime.h>
#include <math.h>

#define NRES 384
#define NNPIX (NRES*NRES)          // 147456
#define CH 128
#define NH 4
#define KD 32
#define QSCALE 0.17677669529663689f  // 1/sqrt(32)

#define PADA 132   // X smem pad (words)
#define PADB 136   // W smem pad (words)
#define PADK 392   // Kt pad: B-frag bank = 8*gc+gr -> conflict-free
#define PADVT 388  // Vt pad: B-frag bank = 4*gr+gc -> conflict-free
#define PADP 68    // P stage pad: A-frag bank = 4*gr+gc -> conflict-free

// ---------------- scratch ----------------------------------------------------
__device__ __align__(16) float g_x  [(size_t)NNPIX*CH];
__device__ __align__(16) float g_nb [(size_t)NH*NNPIX];
__device__ __align__(16) float g_q  [(size_t)NNPIX*CH];
__device__ __align__(16) float g_k  [(size_t)NNPIX*CH];
__device__ __align__(16) float g_v  [(size_t)NNPIX*CH];
__device__ __align__(16) float g_g  [(size_t)NNPIX*CH];
__device__ __align__(16) float g_att[(size_t)NNPIX*CH];

// ---------------- tf32 mma helpers -------------------------------------------
__device__ __forceinline__ unsigned f2tf32(float f) {
    unsigned u;
    asm("cvt.rna.tf32.f32 %0, %1;" : "=r"(u) : "f"(f));
    return u;
}
__device__ __forceinline__ void mma_tf32(float c[4], const unsigned a[4], const unsigned b[2]) {
    asm volatile(
        "mma.sync.aligned.m16n8k8.row.col.f32.tf32.tf32.f32 "
        "{%0,%1,%2,%3}, {%4,%5,%6,%7}, {%8,%9}, {%0,%1,%2,%3};"
        : "+f"(c[0]), "+f"(c[1]), "+f"(c[2]), "+f"(c[3])
        : "r"(a[0]), "r"(a[1]), "r"(a[2]), "r"(a[3]), "r"(b[0]), "r"(b[1]));
}

// ---------------- kernel 1: LayerNorm + nonbatched bias ----------------------
__global__ __launch_bounds__(256) void ln_nb_kernel(
    const float* __restrict__ pact, const float* __restrict__ lns,
    const float* __restrict__ lnb, const float* __restrict__ f2w)
{
    const int warp = threadIdx.x >> 5, lane = threadIdx.x & 31;
    const size_t p = (size_t)blockIdx.x * 8 + warp;
    float4 v = ((const float4*)(pact + p*CH))[lane];
    float s = v.x + v.y + v.z + v.w;
    #pragma unroll
    for (int o = 16; o; o >>= 1) s += __shfl_xor_sync(0xffffffffu, s, o);
    const float mu = s * (1.0f/CH);
    const float dx = v.x-mu, dy = v.y-mu, dz = v.z-mu, dw = v.w-mu;
    float ss = dx*dx + dy*dy + dz*dz + dw*dw;
    #pragma unroll
    for (int o = 16; o; o >>= 1) ss += __shfl_xor_sync(0xffffffffu, ss, o);
    const float inv = rsqrtf(ss * (1.0f/CH) + 1e-5f);
    const float4 sc = ((const float4*)lns)[lane];
    const float4 bi = ((const float4*)lnb)[lane];
    float4 xn;
    xn.x = dx*inv*sc.x + bi.x;
    xn.y = dy*inv*sc.y + bi.y;
    xn.z = dz*inv*sc.z + bi.z;
    xn.w = dw*inv*sc.w + bi.w;
    ((float4*)(g_x + p*CH))[lane] = xn;

    const float4* w4 = (const float4*)f2w;
    const float4 w0 = w4[lane*4+0], w1 = w4[lane*4+1],
                 w2 = w4[lane*4+2], w3 = w4[lane*4+3];
    float n0 = xn.x*w0.x + xn.y*w1.x + xn.z*w2.x + xn.w*w3.x;
    float n1 = xn.x*w0.y + xn.y*w1.y + xn.z*w2.y + xn.w*w3.y;
    float n2 = xn.x*w0.z + xn.y*w1.z + xn.z*w2.z + xn.w*w3.z;
    float n3 = xn.x*w0.w + xn.y*w1.w + xn.z*w2.w + xn.w*w3.w;
    #pragma unroll
    for (int o = 16; o; o >>= 1) {
        n0 += __shfl_xor_sync(0xffffffffu, n0, o);
        n1 += __shfl_xor_sync(0xffffffffu, n1, o);
        n2 += __shfl_xor_sync(0xffffffffu, n2, o);
        n3 += __shfl_xor_sync(0xffffffffu, n3, o);
    }
    if (lane == 0) {
        g_nb[0*(size_t)NNPIX + p] = n0;
        g_nb[1*(size_t)NNPIX + p] = n1;
        g_nb[2*(size_t)NNPIX + p] = n2;
        g_nb[3*(size_t)NNPIX + p] = n3;
    }
}

// ---------------- kernel 2: q/k/v/gate via tf32 mma (M=64 tile) --------------
// 8 warps: 2 m-warps x 4 n-warps; warp tile 32x32.
__global__ __launch_bounds__(256) void proj_mma_kernel(
    const float* __restrict__ qw, const float* __restrict__ kw,
    const float* __restrict__ vw, const float* __restrict__ gw,
    const float* __restrict__ gb)
{
    extern __shared__ unsigned smu[];
    unsigned* xs = smu;               // [64][PADA]
    unsigned* ws = smu + 64*PADA;     // [128][PADB]
    const int tid = threadIdx.x;
    const int warp = tid >> 5, lane = tid & 31;
    const int gr = lane >> 2, gc = lane & 3;
    const int mw = warp & 1, nw = warp >> 1;
    const int rw0 = mw * 32, nw0 = nw * 32;
    const int r0 = blockIdx.x * 64;

    for (int i = tid; i < 64*32; i += 256) {
        const int r = i >> 5, c4 = i & 31;
        float4 v = ((const float4*)(g_x + (size_t)(r0 + r)*CH))[c4];
        unsigned* d = xs + r*PADA + c4*4;
        d[0]=f2tf32(v.x); d[1]=f2tf32(v.y); d[2]=f2tf32(v.z); d[3]=f2tf32(v.w);
    }

    for (int m = 0; m < 4; ++m) {
        const float* W = (m==0) ? qw : (m==1) ? kw : (m==2) ? vw : gw;
        __syncthreads();
        for (int i = tid; i < 128*32; i += 256) {
            const int k = i >> 5, c4 = i & 31;
            float4 v = ((const float4*)(W + (size_t)k*CH))[c4];
            unsigned* d = ws + k*PADB + c4*4;
            d[0]=f2tf32(v.x); d[1]=f2tf32(v.y); d[2]=f2tf32(v.z); d[3]=f2tf32(v.w);
        }
        __syncthreads();

        float c[2][4][4];
        #pragma unroll
        for (int mi = 0; mi < 2; ++mi)
            #pragma unroll
            for (int ni = 0; ni < 4; ++ni)
                #pragma unroll
                for (int t = 0; t < 4; ++t) c[mi][ni][t] = 0.f;

        #pragma unroll 4
        for (int kk = 0; kk < 16; ++kk) {
            const int k0 = kk * 8;
            unsigned a[2][4];
            #pragma unroll
            for (int mi = 0; mi < 2; ++mi) {
                const int rb = rw0 + mi*16;
                a[mi][0] = xs[(rb+gr  )*PADA + k0+gc  ];
                a[mi][1] = xs[(rb+gr+8)*PADA + k0+gc  ];
                a[mi][2] = xs[(rb+gr  )*PADA + k0+gc+4];
                a[mi][3] = xs[(rb+gr+8)*PADA + k0+gc+4];
            }
            unsigned b[4][2];
            #pragma unroll
            for (int ni = 0; ni < 4; ++ni) {
                const int n0 = nw0 + ni*8 + gr;
                b[ni][0] = ws[(k0+gc  )*PADB + n0];
                b[ni][1] = ws[(k0+gc+4)*PADB + n0];
            }
            #pragma unroll
            for (int mi = 0; mi < 2; ++mi)
                #pragma unroll
                for (int ni = 0; ni < 4; ++ni)
                    mma_tf32(c[mi][ni], a[mi], b[ni]);
        }

        float* outp = (m==0) ? g_q : (m==1) ? g_k : (m==2) ? g_v : g_g;
        #pragma unroll
        for (int mi = 0; mi < 2; ++mi) {
            const int row0 = r0 + rw0 + mi*16 + gr;
            #pragma unroll
            for (int ni = 0; ni < 4; ++ni) {
                const int col = nw0 + ni*8 + gc*2;
                float v0x = c[mi][ni][0], v0y = c[mi][ni][1];
                float v1x = c[mi][ni][2], v1y = c[mi][ni][3];
                if (m == 0) { v0x*=QSCALE; v0y*=QSCALE; v1x*=QSCALE; v1y*=QSCALE; }
                if (m == 3) {
                    const float2 bb = *(const float2*)(gb + col);
                    v0x = 1.f/(1.f + __expf(-(v0x + bb.x)));
                    v0y = 1.f/(1.f + __expf(-(v0y + bb.y)));
                    v1x = 1.f/(1.f + __expf(-(v1x + bb.x)));
                    v1y = 1.f/(1.f + __expf(-(v1y + bb.y)));
                }
                *(float2*)(outp + (size_t)row0*CH + col)     = make_float2(v0x, v0y);
                *(float2*)(outp + (size_t)(row0+8)*CH + col) = make_float2(v1x, v1y);
            }
        }
    }
}

// ---------------- kernel 3: flash attention via tf32 mma ---------------------
// block = (b, h); 8 warps x 16 q-rows x 3 passes; keys in 6 chunks of 64.
__global__ __launch_bounds__(256, 1) void attn_mma_kernel(const float* __restrict__ mask)
{
    extern __shared__ unsigned sm_u[];
    unsigned* Kt = sm_u;                       // [32][PADK]  tf32
    unsigned* Vt = Kt + 32*PADK;               // [32][PADVT] tf32
    unsigned* Ps = Vt + 32*PADVT;              // [8][16][PADP] tf32
    float* mrow  = (float*)(Ps + 8*16*PADP);   // [384]
    const int b = blockIdx.x, h = blockIdx.y;
    const int tid = threadIdx.x, warp = tid >> 5, lane = tid & 31;
    const int gr = lane >> 2, gc = lane & 3;

    for (int i = tid; i < 384*8; i += 256) {
        const int row = i >> 3, c4 = i & 7;
        const size_t base = ((size_t)(b*NRES)+row)*CH + h*KD;
        float4 kv = *(const float4*)(g_k + base + c4*4);
        Kt[(c4*4+0)*PADK + row] = f2tf32(kv.x);
        Kt[(c4*4+1)*PADK + row] = f2tf32(kv.y);
        Kt[(c4*4+2)*PADK + row] = f2tf32(kv.z);
        Kt[(c4*4+3)*PADK + row] = f2tf32(kv.w);
        float4 vv = *(const float4*)(g_v + base + c4*4);
        Vt[(c4*4+0)*PADVT + row] = f2tf32(vv.x);
        Vt[(c4*4+1)*PADVT + row] = f2tf32(vv.y);
        Vt[(c4*4+2)*PADVT + row] = f2tf32(vv.z);
        Vt[(c4*4+3)*PADVT + row] = f2tf32(vv.w);
    }
    for (int i = tid; i < NRES; i += 256)
        mrow[i] = 1e9f * (mask[(size_t)b*NRES + i] - 1.f);
    __syncthreads();

    unsigned* Pw = Ps + warp*16*PADP;

    for (int p = 0; p < 3; ++p) {
        const int q0 = p*128 + warp*16;
        // Q fragments (held in registers across all key chunks)
        unsigned qa[4][4];
        const float* qbase = g_q + ((size_t)(b*NRES)+q0)*CH + h*KD;
        #pragma unroll
        for (int kc = 0; kc < 4; ++kc) {
            qa[kc][0] = f2tf32(qbase[gr*CH     + kc*8+gc  ]);
            qa[kc][1] = f2tf32(qbase[(gr+8)*CH + kc*8+gc  ]);
            qa[kc][2] = f2tf32(qbase[gr*CH     + kc*8+gc+4]);
            qa[kc][3] = f2tf32(qbase[(gr+8)*CH + kc*8+gc+4]);
        }
        const float* nb0 = g_nb + (size_t)h*NNPIX + (size_t)(q0+gr)*NRES;
        const float* nb1 = nb0 + (size_t)8*NRES;

        float m0 = -1e30f, m1 = -1e30f, sum0 = 0.f, sum1 = 0.f;
        float O[4][4];
        #pragma unroll
        for (int vt = 0; vt < 4; ++vt)
            #pragma unroll
            for (int t = 0; t < 4; ++t) O[vt][t] = 0.f;

        for (int c = 0; c < 6; ++c) {
            const int c0 = c*64;
            float s[8][4];
            #pragma unroll
            for (int t = 0; t < 8; ++t)
                #pragma unroll
                for (int j = 0; j < 4; ++j) s[t][j] = 0.f;

            #pragma unroll
            for (int t = 0; t < 8; ++t) {
                const int n0 = c0 + t*8;
                #pragma unroll
                for (int kc = 0; kc < 4; ++kc) {
                    unsigned bf[2];
                    bf[0] = Kt[(kc*8+gc  )*PADK + n0+gr];
                    bf[1] = Kt[(kc*8+gc+4)*PADK + n0+gr];
                    mma_tf32(s[t], qa[kc], bf);
                }
            }
            // bias + chunk row-max
            float mc0 = -1e30f, mc1 = -1e30f;
            #pragma unroll
            for (int t = 0; t < 8; ++t) {
                const int col = c0 + t*8 + gc*2;
                const float2 mr  = *(const float2*)(mrow + col);
                const float2 nlo = *(const float2*)(nb0 + col);
                const float2 nhi = *(const float2*)(nb1 + col);
                s[t][0] += mr.x + nlo.x; s[t][1] += mr.y + nlo.y;
                s[t][2] += mr.x + nhi.x; s[t][3] += mr.y + nhi.y;
                mc0 = fmaxf(mc0, fmaxf(s[t][0], s[t][1]));
                mc1 = fmaxf(mc1, fmaxf(s[t][2], s[t][3]));
            }
            mc0 = fmaxf(mc0, __shfl_xor_sync(0xffffffffu, mc0, 1));
            mc0 = fmaxf(mc0, __shfl_xor_sync(0xffffffffu, mc0, 2));
            mc1 = fmaxf(mc1, __shfl_xor_sync(0xffffffffu, mc1, 1));
            mc1 = fmaxf(mc1, __shfl_xor_sync(0xffffffffu, mc1, 2));
            const float mn0 = fmaxf(m0, mc0), mn1 = fmaxf(m1, mc1);
            const float al0 = __expf(m0 - mn0), al1 = __expf(m1 - mn1);
            m0 = mn0; m1 = mn1;
            sum0 *= al0; sum1 *= al1;
            #pragma unroll
            for (int vt = 0; vt < 4; ++vt) {
                O[vt][0] *= al0; O[vt][1] *= al0;
                O[vt][2] *= al1; O[vt][3] *= al1;
            }
            float cs0 = 0.f, cs1 = 0.f;
            #pragma unroll
            for (int t = 0; t < 8; ++t) {
                s[t][0] = __expf(s[t][0] - mn0);
                s[t][1] = __expf(s[t][1] - mn0);
                s[t][2] = __expf(s[t][2] - mn1);
                s[t][3] = __expf(s[t][3] - mn1);
                cs0 += s[t][0] + s[t][1];
                cs1 += s[t][2] + s[t][3];
            }
            cs0 += __shfl_xor_sync(0xffffffffu, cs0, 1);
            cs0 += __shfl_xor_sync(0xffffffffu, cs0, 2);
            cs1 += __shfl_xor_sync(0xffffffffu, cs1, 1);
            cs1 += __shfl_xor_sync(0xffffffffu, cs1, 2);
            sum0 += cs0; sum1 += cs1;

            __syncwarp();
            #pragma unroll
            for (int t = 0; t < 8; ++t) {
                const int cl = t*8 + gc*2;
                *(uint2*)(Pw + gr*PADP + cl) =
                    make_uint2(f2tf32(s[t][0]), f2tf32(s[t][1]));
                *(uint2*)(Pw + (gr+8)*PADP + cl) =
                    make_uint2(f2tf32(s[t][2]), f2tf32(s[t][3]));
            }
            __syncwarp();
            #pragma unroll
            for (int kc = 0; kc < 8; ++kc) {
                unsigned pa[4];
                pa[0] = Pw[gr*PADP     + kc*8+gc  ];
                pa[1] = Pw[(gr+8)*PADP + kc*8+gc  ];
                pa[2] = Pw[gr*PADP     + kc*8+gc+4];
                pa[3] = Pw[(gr+8)*PADP + kc*8+gc+4];
                #pragma unroll
                for (int vt = 0; vt < 4; ++vt) {
                    unsigned bf[2];
                    bf[0] = Vt[(vt*8+gr)*PADVT + c0 + kc*8+gc  ];
                    bf[1] = Vt[(vt*8+gr)*PADVT + c0 + kc*8+gc+4];
                    mma_tf32(O[vt], pa, bf);
                }
            }
        }

        const float inv0 = 1.f / sum0, inv1 = 1.f / sum1;
        const size_t orow0 = ((size_t)(b*NRES)+q0+gr)*CH + h*KD;
        const size_t orow1 = orow0 + (size_t)8*CH;
        #pragma unroll
        for (int vt = 0; vt < 4; ++vt) {
            const int cl = vt*8 + gc*2;
            const float2 g0 = *(const float2*)(g_g + orow0 + cl);
            const float2 g1 = *(const float2*)(g_g + orow1 + cl);
            *(float2*)(g_att + orow0 + cl) =
                make_float2(O[vt][0]*inv0*g0.x, O[vt][1]*inv0*g0.y);
            *(float2*)(g_att + orow1 + cl) =
                make_float2(O[vt][2]*inv1*g1.x, O[vt][3]*inv1*g1.y);
        }
    }
}

// ---------------- kernel 4: output projection via tf32 mma (M=64) ------------
__global__ __launch_bounds__(256) void out_mma_kernel(
    const float* __restrict__ ow, const float* __restrict__ ob,
    float* __restrict__ out)
{
    extern __shared__ unsigned smu[];
    unsigned* xs = smu;
    unsigned* ws = smu + 64*PADA;
    const int tid = threadIdx.x;
    const int warp = tid >> 5, lane = tid & 31;
    const int gr = lane >> 2, gc = lane & 3;
    const int mw = warp & 1, nw = warp >> 1;
    const int rw0 = mw * 32, nw0 = nw * 32;
    const int r0 = blockIdx.x * 64;

    for (int i = tid; i < 64*32; i += 256) {
        const int r = i >> 5, c4 = i & 31;
        float4 v = ((const float4*)(g_att + (size_t)(r0 + r)*CH))[c4];
        unsigned* d = xs + r*PADA + c4*4;
        d[0]=f2tf32(v.x); d[1]=f2tf32(v.y); d[2]=f2tf32(v.z); d[3]=f2tf32(v.w);
    }
    for (int i = tid; i < 128*32; i += 256) {
        const int k = i >> 5, c4 = i & 31;
        float4 v = ((const float4*)(ow + (size_t)k*CH))[c4];
        unsigned* d = ws + k*PADB + c4*4;
        d[0]=f2tf32(v.x); d[1]=f2tf32(v.y); d[2]=f2tf32(v.z); d[3]=f2tf32(v.w);
    }
    __syncthreads();

    float c[2][4][4];
    #pragma unroll
    for (int mi = 0; mi < 2; ++mi)
        #pragma unroll
        for (int ni = 0; ni < 4; ++ni)
            #pragma unroll
            for (int t = 0; t < 4; ++t) c[mi][ni][t] = 0.f;

    #pragma unroll 4
    for (int kk = 0; kk < 16; ++kk) {
        const int k0 = kk * 8;
        unsigned a[2][4];
        #pragma unroll
        for (int mi = 0; mi < 2; ++mi) {
            const int rb = rw0 + mi*16;
            a[mi][0] = xs[(rb+gr  )*PADA + k0+gc  ];
            a[mi][1] = xs[(rb+gr+8)*PADA + k0+gc  ];
            a[mi][2] = xs[(rb+gr  )*PADA + k0+gc+4];
            a[mi][3] = xs[(rb+gr+8)*PADA + k0+gc+4];
        }
        unsigned b[4][2];
        #pragma unroll
        for (int ni = 0; ni < 4; ++ni) {
            const int n0 = nw0 + ni*8 + gr;
            b[ni][0] = ws[(k0+gc  )*PADB + n0];
            b[ni][1] = ws[(k0+gc+4)*PADB + n0];
        }
        #pragma unroll
        for (int mi = 0; mi < 2; ++mi)
            #pragma unroll
            for (int ni = 0; ni < 4; ++ni)
                mma_tf32(c[mi][ni], a[mi], b[ni]);
    }

    #pragma unroll
    for (int mi = 0; mi < 2; ++mi) {
        const int row0 = r0 + rw0 + mi*16 + gr;
        #pragma unroll
        for (int ni = 0; ni < 4; ++ni) {
            const int col = nw0 + ni*8 + gc*2;
            const float2 bb = *(const float2*)(ob + col);
            *(float2*)(out + (size_t)row0*CH + col) =
                make_float2(c[mi][ni][0] + bb.x, c[mi][ni][1] + bb.y);
            *(float2*)(out + (size_t)(row0+8)*CH + col) =
                make_float2(c[mi][ni][2] + bb.x, c[mi][ni][3] + bb.y);
        }
    }
}

// ---------------- launcher ---------------------------------------------------
extern "C" void kernel_launch(void* const* d_in, const int* in_sizes, int n_in,
                              void* d_out, int out_size)
{
    const float* pact = (const float*)d_in[0];
    const float* mask = (const float*)d_in[1];
    const float* lns  = (const float*)d_in[2];
    const float* lnb  = (const float*)d_in[3];
    const float* f2w  = (const float*)d_in[4];
    const float* qw   = (const float*)d_in[5];
    const float* kw   = (const float*)d_in[6];
    const float* vw   = (const float*)d_in[7];
    const float* gw   = (const float*)d_in[8];
    const float* gb   = (const float*)d_in[9];
    const float* ow   = (const float*)d_in[10];
    const float* ob   = (const float*)d_in[11];
    float* out = (float*)d_out;

    const int GEMM_SMEM = (64*PADA + 128*PADB) * 4;                          // 103424
    const int ATTN_SMEM = (32*PADK + 32*PADVT + 8*16*PADP + NRES) * 4;       // 136192

    cudaFuncSetAttribute(proj_mma_kernel, cudaFuncAttributeMaxDynamicSharedMemorySize, GEMM_SMEM);
    cudaFuncSetAttribute(out_mma_kernel,  cudaFuncAttributeMaxDynamicSharedMemorySize, GEMM_SMEM);
    cudaFuncSetAttribute(attn_mma_kernel, cudaFuncAttributeMaxDynamicSharedMemorySize, ATTN_SMEM);

    ln_nb_kernel<<<NNPIX/8, 256>>>(pact, lns, lnb, f2w);
    proj_mma_kernel<<<NNPIX/64, 256, GEMM_SMEM>>>(qw, kw, vw, gw, gb);
    attn_mma_kernel<<<dim3(NRES, NH), 256, ATTN_SMEM>>>(mask);
    out_mma_kernel<<<NNPIX/64, 256, GEMM_SMEM>>>(ow, ob, out);
}

// round 4
// speedup vs baseline: 5.2060x; 1.2803x over previous
#include <cuda_runtime.h>
#include <math.h>

#define NRES 384
#define NNPIX (NRES*NRES)          // 147456
#define CH 128
#define NH 4
#define KD 32
#define QSCALE 0.17677669529663689f  // 1/sqrt(32)

#define PADA 132   // X smem pad (words)
#define PADB 136   // W smem pad (words)
#define PADK 392   // Kt pad: B-frag bank = 8*gc+gr -> conflict-free
#define PADVT 388  // Vt pad: B-frag bank = 4*gr+gc -> conflict-free

// ---------------- scratch ----------------------------------------------------
__device__ __align__(16) float g_nb [(size_t)NH*NNPIX];
__device__ __align__(16) float g_q  [(size_t)NNPIX*CH];
__device__ __align__(16) float g_k  [(size_t)NNPIX*CH];
__device__ __align__(16) float g_v  [(size_t)NNPIX*CH];
__device__ __align__(16) float g_g  [(size_t)NNPIX*CH];
__device__ __align__(16) float g_att[(size_t)NNPIX*CH];

// ---------------- tf32 mma helpers -------------------------------------------
__device__ __forceinline__ unsigned f2tf32(float f) {
    unsigned u;
    asm("cvt.rna.tf32.f32 %0, %1;" : "=r"(u) : "f"(f));
    return u;
}
__device__ __forceinline__ void mma_tf32(float c[4], const unsigned a[4], const unsigned b[2]) {
    asm volatile(
        "mma.sync.aligned.m16n8k8.row.col.f32.tf32.tf32.f32 "
        "{%0,%1,%2,%3}, {%4,%5,%6,%7}, {%8,%9}, {%0,%1,%2,%3};"
        : "+f"(c[0]), "+f"(c[1]), "+f"(c[2]), "+f"(c[3])
        : "r"(a[0]), "r"(a[1]), "r"(a[2]), "r"(a[3]), "r"(b[0]), "r"(b[1]));
}

// ---------------- kernel 1: fused LN + nb-bias + q/k/v/gate projections ------
// 8 warps: 2 m-warps x 4 n-warps; warp tile 32x32. LN done in-register at load.
__global__ __launch_bounds__(256) void lnproj_mma_kernel(
    const float* __restrict__ pact, const float* __restrict__ lns,
    const float* __restrict__ lnb, const float* __restrict__ f2w,
    const float* __restrict__ qw, const float* __restrict__ kw,
    const float* __restrict__ vw, const float* __restrict__ gw,
    const float* __restrict__ gb)
{
    extern __shared__ unsigned smu[];
    unsigned* xs = smu;               // [64][PADA]
    unsigned* ws = smu + 64*PADA;     // [128][PADB]
    const int tid = threadIdx.x;
    const int warp = tid >> 5, lane = tid & 31;
    const int gr = lane >> 2, gc = lane & 3;
    const int mw = warp & 1, nw = warp >> 1;
    const int rw0 = mw * 32, nw0 = nw * 32;
    const int r0 = blockIdx.x * 64;

    // ---- stage 1: per-row LayerNorm + nb bias; write tf32 X tile to smem ----
    {
        const float4 sc = ((const float4*)lns)[lane];
        const float4 bi = ((const float4*)lnb)[lane];
        const float4* w4 = (const float4*)f2w;
        const float4 w0 = w4[lane*4+0], w1 = w4[lane*4+1],
                     w2 = w4[lane*4+2], w3 = w4[lane*4+3];
        #pragma unroll 2
        for (int k = 0; k < 8; ++k) {
            const int r = k*8 + warp;
            const size_t p = (size_t)(r0 + r);
            float4 v = ((const float4*)(pact + p*CH))[lane];
            float s = v.x + v.y + v.z + v.w;
            #pragma unroll
            for (int o = 16; o; o >>= 1) s += __shfl_xor_sync(0xffffffffu, s, o);
            const float mu = s * (1.0f/CH);
            const float dx = v.x-mu, dy = v.y-mu, dz = v.z-mu, dw = v.w-mu;
            float ss = dx*dx + dy*dy + dz*dz + dw*dw;
            #pragma unroll
            for (int o = 16; o; o >>= 1) ss += __shfl_xor_sync(0xffffffffu, ss, o);
            const float inv = rsqrtf(ss * (1.0f/CH) + 1e-5f);
            float4 xn;
            xn.x = dx*inv*sc.x + bi.x;
            xn.y = dy*inv*sc.y + bi.y;
            xn.z = dz*inv*sc.z + bi.z;
            xn.w = dw*inv*sc.w + bi.w;
            unsigned* d = xs + r*PADA + lane*4;
            d[0]=f2tf32(xn.x); d[1]=f2tf32(xn.y); d[2]=f2tf32(xn.z); d[3]=f2tf32(xn.w);

            float n0 = xn.x*w0.x + xn.y*w1.x + xn.z*w2.x + xn.w*w3.x;
            float n1 = xn.x*w0.y + xn.y*w1.y + xn.z*w2.y + xn.w*w3.y;
            float n2 = xn.x*w0.z + xn.y*w1.z + xn.z*w2.z + xn.w*w3.z;
            float n3 = xn.x*w0.w + xn.y*w1.w + xn.z*w2.w + xn.w*w3.w;
            #pragma unroll
            for (int o = 16; o; o >>= 1) {
                n0 += __shfl_xor_sync(0xffffffffu, n0, o);
                n1 += __shfl_xor_sync(0xffffffffu, n1, o);
                n2 += __shfl_xor_sync(0xffffffffu, n2, o);
                n3 += __shfl_xor_sync(0xffffffffu, n3, o);
            }
            if (lane == 0) {
                g_nb[0*(size_t)NNPIX + p] = n0;
                g_nb[1*(size_t)NNPIX + p] = n1;
                g_nb[2*(size_t)NNPIX + p] = n2;
                g_nb[3*(size_t)NNPIX + p] = n3;
            }
        }
    }

    // ---- stage 2: four W passes --------------------------------------------
    for (int m = 0; m < 4; ++m) {
        const float* W = (m==0) ? qw : (m==1) ? kw : (m==2) ? vw : gw;
        __syncthreads();
        for (int i = tid; i < 128*32; i += 256) {
            const int k = i >> 5, c4 = i & 31;
            float4 v = ((const float4*)(W + (size_t)k*CH))[c4];
            unsigned* d = ws + k*PADB + c4*4;
            d[0]=f2tf32(v.x); d[1]=f2tf32(v.y); d[2]=f2tf32(v.z); d[3]=f2tf32(v.w);
        }
        __syncthreads();

        float c[2][4][4];
        #pragma unroll
        for (int mi = 0; mi < 2; ++mi)
            #pragma unroll
            for (int ni = 0; ni < 4; ++ni)
                #pragma unroll
                for (int t = 0; t < 4; ++t) c[mi][ni][t] = 0.f;

        #pragma unroll 4
        for (int kk = 0; kk < 16; ++kk) {
            const int k0 = kk * 8;
            unsigned a[2][4];
            #pragma unroll
            for (int mi = 0; mi < 2; ++mi) {
                const int rb = rw0 + mi*16;
                a[mi][0] = xs[(rb+gr  )*PADA + k0+gc  ];
                a[mi][1] = xs[(rb+gr+8)*PADA + k0+gc  ];
                a[mi][2] = xs[(rb+gr  )*PADA + k0+gc+4];
                a[mi][3] = xs[(rb+gr+8)*PADA + k0+gc+4];
            }
            unsigned b[4][2];
            #pragma unroll
            for (int ni = 0; ni < 4; ++ni) {
                const int n0 = nw0 + ni*8 + gr;
                b[ni][0] = ws[(k0+gc  )*PADB + n0];
                b[ni][1] = ws[(k0+gc+4)*PADB + n0];
            }
            #pragma unroll
            for (int mi = 0; mi < 2; ++mi)
                #pragma unroll
                for (int ni = 0; ni < 4; ++ni)
                    mma_tf32(c[mi][ni], a[mi], b[ni]);
        }

        float* outp = (m==0) ? g_q : (m==1) ? g_k : (m==2) ? g_v : g_g;
        #pragma unroll
        for (int mi = 0; mi < 2; ++mi) {
            const int row0 = r0 + rw0 + mi*16 + gr;
            #pragma unroll
            for (int ni = 0; ni < 4; ++ni) {
                const int col = nw0 + ni*8 + gc*2;
                float v0x = c[mi][ni][0], v0y = c[mi][ni][1];
                float v1x = c[mi][ni][2], v1y = c[mi][ni][3];
                if (m == 0) { v0x*=QSCALE; v0y*=QSCALE; v1x*=QSCALE; v1y*=QSCALE; }
                if (m == 3) {
                    const float2 bb = *(const float2*)(gb + col);
                    v0x = 1.f/(1.f + __expf(-(v0x + bb.x)));
                    v0y = 1.f/(1.f + __expf(-(v0y + bb.y)));
                    v1x = 1.f/(1.f + __expf(-(v1x + bb.x)));
                    v1y = 1.f/(1.f + __expf(-(v1y + bb.y)));
                }
                *(float2*)(outp + (size_t)row0*CH + col)     = make_float2(v0x, v0y);
                *(float2*)(outp + (size_t)(row0+8)*CH + col) = make_float2(v1x, v1y);
            }
        }
    }
}

// ---------------- kernel 2: flash attention via tf32 mma ---------------------
// block = (b, h); 8 warps x 16 q-rows x 3 passes; keys in 6 chunks of 64.
// P (C-frag) -> A-frag via quad shuffles; no smem staging buffer.
__global__ __launch_bounds__(256, 2) void attn_mma_kernel(const float* __restrict__ mask)
{
    extern __shared__ unsigned sm_u[];
    unsigned* Kt = sm_u;                       // [32][PADK]  tf32
    unsigned* Vt = Kt + 32*PADK;               // [32][PADVT] tf32
    float* mrow  = (float*)(Vt + 32*PADVT);    // [384]
    const int b = blockIdx.x, h = blockIdx.y;
    const int tid = threadIdx.x, warp = tid >> 5, lane = tid & 31;
    const int gr = lane >> 2, gc = lane & 3;
    const int srcLo = (lane & ~3) | (gc >> 1);   // quad shuffle sources
    const int srcHi = srcLo + 2;
    const bool oddc = (gc & 1);

    for (int i = tid; i < 384*8; i += 256) {
        const int row = i >> 3, c4 = i & 7;
        const size_t base = ((size_t)(b*NRES)+row)*CH + h*KD;
        float4 kv = *(const float4*)(g_k + base + c4*4);
        Kt[(c4*4+0)*PADK + row] = f2tf32(kv.x);
        Kt[(c4*4+1)*PADK + row] = f2tf32(kv.y);
        Kt[(c4*4+2)*PADK + row] = f2tf32(kv.z);
        Kt[(c4*4+3)*PADK + row] = f2tf32(kv.w);
        float4 vv = *(const float4*)(g_v + base + c4*4);
        Vt[(c4*4+0)*PADVT + row] = f2tf32(vv.x);
        Vt[(c4*4+1)*PADVT + row] = f2tf32(vv.y);
        Vt[(c4*4+2)*PADVT + row] = f2tf32(vv.z);
        Vt[(c4*4+3)*PADVT + row] = f2tf32(vv.w);
    }
    for (int i = tid; i < NRES; i += 256)
        mrow[i] = 1e9f * (mask[(size_t)b*NRES + i] - 1.f);
    __syncthreads();

    for (int p = 0; p < 3; ++p) {
        const int q0 = p*128 + warp*16;
        unsigned qa[4][4];
        const float* qbase = g_q + ((size_t)(b*NRES)+q0)*CH + h*KD;
        #pragma unroll
        for (int kc = 0; kc < 4; ++kc) {
            qa[kc][0] = f2tf32(qbase[gr*CH     + kc*8+gc  ]);
            qa[kc][1] = f2tf32(qbase[(gr+8)*CH + kc*8+gc  ]);
            qa[kc][2] = f2tf32(qbase[gr*CH     + kc*8+gc+4]);
            qa[kc][3] = f2tf32(qbase[(gr+8)*CH + kc*8+gc+4]);
        }
        const float* nb0 = g_nb + (size_t)h*NNPIX + (size_t)(q0+gr)*NRES;
        const float* nb1 = nb0 + (size_t)8*NRES;

        float m0 = -1e30f, m1 = -1e30f, sum0 = 0.f, sum1 = 0.f;
        float O[4][4];
        #pragma unroll
        for (int vt = 0; vt < 4; ++vt)
            #pragma unroll
            for (int t = 0; t < 4; ++t) O[vt][t] = 0.f;

        for (int c = 0; c < 6; ++c) {
            const int c0 = c*64;
            float s[8][4];
            #pragma unroll
            for (int t = 0; t < 8; ++t)
                #pragma unroll
                for (int j = 0; j < 4; ++j) s[t][j] = 0.f;

            #pragma unroll
            for (int t = 0; t < 8; ++t) {
                const int n0 = c0 + t*8;
                #pragma unroll
                for (int kc = 0; kc < 4; ++kc) {
                    unsigned bf[2];
                    bf[0] = Kt[(kc*8+gc  )*PADK + n0+gr];
                    bf[1] = Kt[(kc*8+gc+4)*PADK + n0+gr];
                    mma_tf32(s[t], qa[kc], bf);
                }
            }
            // bias + chunk row-max
            float mc0 = -1e30f, mc1 = -1e30f;
            #pragma unroll
            for (int t = 0; t < 8; ++t) {
                const int col = c0 + t*8 + gc*2;
                const float2 mr  = *(const float2*)(mrow + col);
                const float2 nlo = *(const float2*)(nb0 + col);
                const float2 nhi = *(const float2*)(nb1 + col);
                s[t][0] += mr.x + nlo.x; s[t][1] += mr.y + nlo.y;
                s[t][2] += mr.x + nhi.x; s[t][3] += mr.y + nhi.y;
                mc0 = fmaxf(mc0, fmaxf(s[t][0], s[t][1]));
                mc1 = fmaxf(mc1, fmaxf(s[t][2], s[t][3]));
            }
            mc0 = fmaxf(mc0, __shfl_xor_sync(0xffffffffu, mc0, 1));
            mc0 = fmaxf(mc0, __shfl_xor_sync(0xffffffffu, mc0, 2));
            mc1 = fmaxf(mc1, __shfl_xor_sync(0xffffffffu, mc1, 1));
            mc1 = fmaxf(mc1, __shfl_xor_sync(0xffffffffu, mc1, 2));
            const float mn0 = fmaxf(m0, mc0), mn1 = fmaxf(m1, mc1);
            const float al0 = __expf(m0 - mn0), al1 = __expf(m1 - mn1);
            m0 = mn0; m1 = mn1;
            sum0 *= al0; sum1 *= al1;
            #pragma unroll
            for (int vt = 0; vt < 4; ++vt) {
                O[vt][0] *= al0; O[vt][1] *= al0;
                O[vt][2] *= al1; O[vt][3] *= al1;
            }
            float cs0 = 0.f, cs1 = 0.f;
            #pragma unroll
            for (int t = 0; t < 8; ++t) {
                s[t][0] = __expf(s[t][0] - mn0);
                s[t][1] = __expf(s[t][1] - mn0);
                s[t][2] = __expf(s[t][2] - mn1);
                s[t][3] = __expf(s[t][3] - mn1);
                cs0 += s[t][0] + s[t][1];
                cs1 += s[t][2] + s[t][3];
            }
            cs0 += __shfl_xor_sync(0xffffffffu, cs0, 1);
            cs0 += __shfl_xor_sync(0xffffffffu, cs0, 2);
            cs1 += __shfl_xor_sync(0xffffffffu, cs1, 1);
            cs1 += __shfl_xor_sync(0xffffffffu, cs1, 2);
            sum0 += cs0; sum1 += cs1;

            // P (C-frag) -> A-frag conversion via quad shuffles, then PV mma.
            #pragma unroll
            for (int kc = 0; kc < 8; ++kc) {
                float e0 = __shfl_sync(0xffffffffu, s[kc][0], srcLo);
                float e1 = __shfl_sync(0xffffffffu, s[kc][1], srcLo);
                float f0 = __shfl_sync(0xffffffffu, s[kc][0], srcHi);
                float f1 = __shfl_sync(0xffffffffu, s[kc][1], srcHi);
                float g0 = __shfl_sync(0xffffffffu, s[kc][2], srcLo);
                float g1 = __shfl_sync(0xffffffffu, s[kc][3], srcLo);
                float h0 = __shfl_sync(0xffffffffu, s[kc][2], srcHi);
                float h1 = __shfl_sync(0xffffffffu, s[kc][3], srcHi);
                unsigned pa[4];
                pa[0] = f2tf32(oddc ? e1 : e0);
                pa[1] = f2tf32(oddc ? g1 : g0);
                pa[2] = f2tf32(oddc ? f1 : f0);
                pa[3] = f2tf32(oddc ? h1 : h0);
                #pragma unroll
                for (int vt = 0; vt < 4; ++vt) {
                    unsigned bf[2];
                    bf[0] = Vt[(vt*8+gr)*PADVT + c0 + kc*8+gc  ];
                    bf[1] = Vt[(vt*8+gr)*PADVT + c0 + kc*8+gc+4];
                    mma_tf32(O[vt], pa, bf);
                }
            }
        }

        const float inv0 = 1.f / sum0, inv1 = 1.f / sum1;
        const size_t orow0 = ((size_t)(b*NRES)+q0+gr)*CH + h*KD;
        const size_t orow1 = orow0 + (size_t)8*CH;
        #pragma unroll
        for (int vt = 0; vt < 4; ++vt) {
            const int cl = vt*8 + gc*2;
            const float2 g0 = *(const float2*)(g_g + orow0 + cl);
            const float2 g1 = *(const float2*)(g_g + orow1 + cl);
            *(float2*)(g_att + orow0 + cl) =
                make_float2(O[vt][0]*inv0*g0.x, O[vt][1]*inv0*g0.y);
            *(float2*)(g_att + orow1 + cl) =
                make_float2(O[vt][2]*inv1*g1.x, O[vt][3]*inv1*g1.y);
        }
    }
}

// ---------------- kernel 3: output projection via tf32 mma (M=64) ------------
__global__ __launch_bounds__(256) void out_mma_kernel(
    const float* __restrict__ ow, const float* __restrict__ ob,
    float* __restrict__ out)
{
    extern __shared__ unsigned smu[];
    unsigned* xs = smu;
    unsigned* ws = smu + 64*PADA;
    const int tid = threadIdx.x;
    const int warp = tid >> 5, lane = tid & 31;
    const int gr = lane >> 2, gc = lane & 3;
    const int mw = warp & 1, nw = warp >> 1;
    const int rw0 = mw * 32, nw0 = nw * 32;
    const int r0 = blockIdx.x * 64;

    for (int i = tid; i < 64*32; i += 256) {
        const int r = i >> 5, c4 = i & 31;
        float4 v = ((const float4*)(g_att + (size_t)(r0 + r)*CH))[c4];
        unsigned* d = xs + r*PADA + c4*4;
        d[0]=f2tf32(v.x); d[1]=f2tf32(v.y); d[2]=f2tf32(v.z); d[3]=f2tf32(v.w);
    }
    for (int i = tid; i < 128*32; i += 256) {
        const int k = i >> 5, c4 = i & 31;
        float4 v = ((const float4*)(ow + (size_t)k*CH))[c4];
        unsigned* d = ws + k*PADB + c4*4;
        d[0]=f2tf32(v.x); d[1]=f2tf32(v.y); d[2]=f2tf32(v.z); d[3]=f2tf32(v.w);
    }
    __syncthreads();

    float c[2][4][4];
    #pragma unroll
    for (int mi = 0; mi < 2; ++mi)
        #pragma unroll
        for (int ni = 0; ni < 4; ++ni)
            #pragma unroll
            for (int t = 0; t < 4; ++t) c[mi][ni][t] = 0.f;

    #pragma unroll 4
    for (int kk = 0; kk < 16; ++kk) {
        const int k0 = kk * 8;
        unsigned a[2][4];
        #pragma unroll
        for (int mi = 0; mi < 2; ++mi) {
            const int rb = rw0 + mi*16;
            a[mi][0] = xs[(rb+gr  )*PADA + k0+gc  ];
            a[mi][1] = xs[(rb+gr+8)*PADA + k0+gc  ];
            a[mi][2] = xs[(rb+gr  )*PADA + k0+gc+4];
            a[mi][3] = xs[(rb+gr+8)*PADA + k0+gc+4];
        }
        unsigned b[4][2];
        #pragma unroll
        for (int ni = 0; ni < 4; ++ni) {
            const int n0 = nw0 + ni*8 + gr;
            b[ni][0] = ws[(k0+gc  )*PADB + n0];
            b[ni][1] = ws[(k0+gc+4)*PADB + n0];
        }
        #pragma unroll
        for (int mi = 0; mi < 2; ++mi)
            #pragma unroll
            for (int ni = 0; ni < 4; ++ni)
                mma_tf32(c[mi][ni], a[mi], b[ni]);
    }

    #pragma unroll
    for (int mi = 0; mi < 2; ++mi) {
        const int row0 = r0 + rw0 + mi*16 + gr;
        #pragma unroll
        for (int ni = 0; ni < 4; ++ni) {
            const int col = nw0 + ni*8 + gc*2;
            const float2 bb = *(const float2*)(ob + col);
            *(float2*)(out + (size_t)row0*CH + col) =
                make_float2(c[mi][ni][0] + bb.x, c[mi][ni][1] + bb.y);
            *(float2*)(out + (size_t)(row0+8)*CH + col) =
                make_float2(c[mi][ni][2] + bb.x, c[mi][ni][3] + bb.y);
        }
    }
}

// ---------------- launcher ---------------------------------------------------
extern "C" void kernel_launch(void* const* d_in, const int* in_sizes, int n_in,
                              void* d_out, int out_size)
{
    const float* pact = (const float*)d_in[0];
    const float* mask = (const float*)d_in[1];
    const float* lns  = (const float*)d_in[2];
    const float* lnb  = (const float*)d_in[3];
    const float* f2w  = (const float*)d_in[4];
    const float* qw   = (const float*)d_in[5];
    const float* kw   = (const float*)d_in[6];
    const float* vw   = (const float*)d_in[7];
    const float* gw   = (const float*)d_in[8];
    const float* gb   = (const float*)d_in[9];
    const float* ow   = (const float*)d_in[10];
    const float* ob   = (const float*)d_in[11];
    float* out = (float*)d_out;

    const int GEMM_SMEM = (64*PADA + 128*PADB) * 4;             // 103424
    const int ATTN_SMEM = (32*PADK + 32*PADVT + NRES) * 4;      // 101376

    cudaFuncSetAttribute(lnproj_mma_kernel, cudaFuncAttributeMaxDynamicSharedMemorySize, GEMM_SMEM);
    cudaFuncSetAttribute(out_mma_kernel,    cudaFuncAttributeMaxDynamicSharedMemorySize, GEMM_SMEM);
    cudaFuncSetAttribute(attn_mma_kernel,   cudaFuncAttributeMaxDynamicSharedMemorySize, ATTN_SMEM);

    lnproj_mma_kernel<<<NNPIX/64, 256, GEMM_SMEM>>>(pact, lns, lnb, f2w, qw, kw, vw, gw, gb);
    attn_mma_kernel<<<dim3(NRES, NH), 256, ATTN_SMEM>>>(mask);
    out_mma_kernel<<<NNPIX/64, 256, GEMM_SMEM>>>(ow, ob, out);
}

// round 5
// speedup vs baseline: 5.8464x; 1.1230x over previous
#include <cuda_runtime.h>
#include <cuda_fp16.h>
#include <math.h>

#define NRES 384
#define NNPIX (NRES*NRES)          // 147456
#define CH 128
#define NH 4
#define KD 32
#define QSCALE 0.17677669529663689f  // 1/sqrt(32)

#define PADA 132   // X smem pad (words)
#define PADB 136   // W smem pad (words)
#define PADK 392   // Kt pad: B-frag bank = 8*gc+gr -> conflict-free
#define PADH 196   // Vs pad (half2 words per d-row): bank = 4*gr+gc -> conflict-free

// ---------------- scratch ----------------------------------------------------
__device__ __align__(16) float g_nb [(size_t)NH*NNPIX];
__device__ __align__(16) float g_q  [(size_t)NNPIX*CH];
__device__ __align__(16) float g_k  [(size_t)NNPIX*CH];
__device__ __align__(16) float g_v  [(size_t)NNPIX*CH];
__device__ __align__(16) float g_g  [(size_t)NNPIX*CH];
__device__ __align__(16) float g_att[(size_t)NNPIX*CH];

// ---------------- mma helpers -------------------------------------------------
__device__ __forceinline__ unsigned f2tf32(float f) {
    unsigned u;
    asm("cvt.rna.tf32.f32 %0, %1;" : "=r"(u) : "f"(f));
    return u;
}
__device__ __forceinline__ unsigned h2pack(float lo, float hi) {
    unsigned u;
    asm("cvt.rn.f16x2.f32 %0, %1, %2;" : "=r"(u) : "f"(hi), "f"(lo));
    return u;
}
__device__ __forceinline__ void mma_tf32(float c[4], const unsigned a[4], const unsigned b[2]) {
    asm volatile(
        "mma.sync.aligned.m16n8k8.row.col.f32.tf32.tf32.f32 "
        "{%0,%1,%2,%3}, {%4,%5,%6,%7}, {%8,%9}, {%0,%1,%2,%3};"
        : "+f"(c[0]), "+f"(c[1]), "+f"(c[2]), "+f"(c[3])
        : "r"(a[0]), "r"(a[1]), "r"(a[2]), "r"(a[3]), "r"(b[0]), "r"(b[1]));
}
__device__ __forceinline__ void mma_f16(float c[4], const unsigned a[4], unsigned b0, unsigned b1) {
    asm volatile(
        "mma.sync.aligned.m16n8k16.row.col.f32.f16.f16.f32 "
        "{%0,%1,%2,%3}, {%4,%5,%6,%7}, {%8,%9}, {%0,%1,%2,%3};"
        : "+f"(c[0]), "+f"(c[1]), "+f"(c[2]), "+f"(c[3])
        : "r"(a[0]), "r"(a[1]), "r"(a[2]), "r"(a[3]), "r"(b0), "r"(b1));
}

// ---------------- kernel 1: fused LN + nb-bias + q/k/v/gate projections ------
__global__ __launch_bounds__(256) void lnproj_mma_kernel(
    const float* __restrict__ pact, const float* __restrict__ lns,
    const float* __restrict__ lnb, const float* __restrict__ f2w,
    const float* __restrict__ qw, const float* __restrict__ kw,
    const float* __restrict__ vw, const float* __restrict__ gw,
    const float* __restrict__ gb)
{
    extern __shared__ unsigned smu[];
    unsigned* xs = smu;               // [64][PADA]
    unsigned* ws = smu + 64*PADA;     // [128][PADB]
    const int tid = threadIdx.x;
    const int warp = tid >> 5, lane = tid & 31;
    const int gr = lane >> 2, gc = lane & 3;
    const int mw = warp & 1, nw = warp >> 1;
    const int rw0 = mw * 32, nw0 = nw * 32;
    const int r0 = blockIdx.x * 64;

    // ---- stage 1: per-row LayerNorm + nb bias; write tf32 X tile to smem ----
    {
        const float4 sc = ((const float4*)lns)[lane];
        const float4 bi = ((const float4*)lnb)[lane];
        const float4* w4 = (const float4*)f2w;
        const float4 w0 = w4[lane*4+0], w1 = w4[lane*4+1],
                     w2 = w4[lane*4+2], w3 = w4[lane*4+3];
        #pragma unroll 2
        for (int k = 0; k < 8; ++k) {
            const int r = k*8 + warp;
            const size_t p = (size_t)(r0 + r);
            float4 v = ((const float4*)(pact + p*CH))[lane];
            float s = v.x + v.y + v.z + v.w;
            #pragma unroll
            for (int o = 16; o; o >>= 1) s += __shfl_xor_sync(0xffffffffu, s, o);
            const float mu = s * (1.0f/CH);
            const float dx = v.x-mu, dy = v.y-mu, dz = v.z-mu, dw = v.w-mu;
            float ss = dx*dx + dy*dy + dz*dz + dw*dw;
            #pragma unroll
            for (int o = 16; o; o >>= 1) ss += __shfl_xor_sync(0xffffffffu, ss, o);
            const float inv = rsqrtf(ss * (1.0f/CH) + 1e-5f);
            float4 xn;
            xn.x = dx*inv*sc.x + bi.x;
            xn.y = dy*inv*sc.y + bi.y;
            xn.z = dz*inv*sc.z + bi.z;
            xn.w = dw*inv*sc.w + bi.w;
            unsigned* d = xs + r*PADA + lane*4;
            d[0]=f2tf32(xn.x); d[1]=f2tf32(xn.y); d[2]=f2tf32(xn.z); d[3]=f2tf32(xn.w);

            float n0 = xn.x*w0.x + xn.y*w1.x + xn.z*w2.x + xn.w*w3.x;
            float n1 = xn.x*w0.y + xn.y*w1.y + xn.z*w2.y + xn.w*w3.y;
            float n2 = xn.x*w0.z + xn.y*w1.z + xn.z*w2.z + xn.w*w3.z;
            float n3 = xn.x*w0.w + xn.y*w1.w + xn.z*w2.w + xn.w*w3.w;
            #pragma unroll
            for (int o = 16; o; o >>= 1) {
                n0 += __shfl_xor_sync(0xffffffffu, n0, o);
                n1 += __shfl_xor_sync(0xffffffffu, n1, o);
                n2 += __shfl_xor_sync(0xffffffffu, n2, o);
                n3 += __shfl_xor_sync(0xffffffffu, n3, o);
            }
            if (lane == 0) {
                g_nb[0*(size_t)NNPIX + p] = n0;
                g_nb[1*(size_t)NNPIX + p] = n1;
                g_nb[2*(size_t)NNPIX + p] = n2;
                g_nb[3*(size_t)NNPIX + p] = n3;
            }
        }
    }

    // ---- stage 2: four W passes --------------------------------------------
    for (int m = 0; m < 4; ++m) {
        const float* W = (m==0) ? qw : (m==1) ? kw : (m==2) ? vw : gw;
        __syncthreads();
        for (int i = tid; i < 128*32; i += 256) {
            const int k = i >> 5, c4 = i & 31;
            float4 v = ((const float4*)(W + (size_t)k*CH))[c4];
            unsigned* d = ws + k*PADB + c4*4;
            d[0]=f2tf32(v.x); d[1]=f2tf32(v.y); d[2]=f2tf32(v.z); d[3]=f2tf32(v.w);
        }
        __syncthreads();

        float c[2][4][4];
        #pragma unroll
        for (int mi = 0; mi < 2; ++mi)
            #pragma unroll
            for (int ni = 0; ni < 4; ++ni)
                #pragma unroll
                for (int t = 0; t < 4; ++t) c[mi][ni][t] = 0.f;

        #pragma unroll 4
        for (int kk = 0; kk < 16; ++kk) {
            const int k0 = kk * 8;
            unsigned a[2][4];
            #pragma unroll
            for (int mi = 0; mi < 2; ++mi) {
                const int rb = rw0 + mi*16;
                a[mi][0] = xs[(rb+gr  )*PADA + k0+gc  ];
                a[mi][1] = xs[(rb+gr+8)*PADA + k0+gc  ];
                a[mi][2] = xs[(rb+gr  )*PADA + k0+gc+4];
                a[mi][3] = xs[(rb+gr+8)*PADA + k0+gc+4];
            }
            unsigned b[4][2];
            #pragma unroll
            for (int ni = 0; ni < 4; ++ni) {
                const int n0 = nw0 + ni*8 + gr;
                b[ni][0] = ws[(k0+gc  )*PADB + n0];
                b[ni][1] = ws[(k0+gc+4)*PADB + n0];
            }
            #pragma unroll
            for (int mi = 0; mi < 2; ++mi)
                #pragma unroll
                for (int ni = 0; ni < 4; ++ni)
                    mma_tf32(c[mi][ni], a[mi], b[ni]);
        }

        float* outp = (m==0) ? g_q : (m==1) ? g_k : (m==2) ? g_v : g_g;
        #pragma unroll
        for (int mi = 0; mi < 2; ++mi) {
            const int row0 = r0 + rw0 + mi*16 + gr;
            #pragma unroll
            for (int ni = 0; ni < 4; ++ni) {
                const int col = nw0 + ni*8 + gc*2;
                float v0x = c[mi][ni][0], v0y = c[mi][ni][1];
                float v1x = c[mi][ni][2], v1y = c[mi][ni][3];
                if (m == 0) { v0x*=QSCALE; v0y*=QSCALE; v1x*=QSCALE; v1y*=QSCALE; }
                if (m == 3) {
                    const float2 bb = *(const float2*)(gb + col);
                    v0x = 1.f/(1.f + __expf(-(v0x + bb.x)));
                    v0y = 1.f/(1.f + __expf(-(v0y + bb.y)));
                    v1x = 1.f/(1.f + __expf(-(v1x + bb.x)));
                    v1y = 1.f/(1.f + __expf(-(v1y + bb.y)));
                }
                *(float2*)(outp + (size_t)row0*CH + col)     = make_float2(v0x, v0y);
                *(float2*)(outp + (size_t)(row0+8)*CH + col) = make_float2(v1x, v1y);
            }
        }
    }
}

// ---------------- kernel 2: flash attention, QK tf32 + PV fp16 ---------------
// block = (b, h); 8 warps x 16 q-rows x 3 passes; keys in 6 chunks of 64.
// P C-frag maps directly to fp16 m16n8k16 A-frag (no shuffles).
__global__ __launch_bounds__(256, 2) void attn_mma_kernel(const float* __restrict__ mask)
{
    extern __shared__ unsigned sm_u[];
    unsigned* Kt = sm_u;                       // [32][PADK]  tf32
    unsigned* Vs = Kt + 32*PADK;               // [32][PADH]  half2 (key-pairs)
    float* mrow  = (float*)(Vs + 32*PADH);     // [384]
    const int b = blockIdx.x, h = blockIdx.y;
    const int tid = threadIdx.x, warp = tid >> 5, lane = tid & 31;
    const int gr = lane >> 2, gc = lane & 3;

    // stage K (tf32, d-major) ------------------------------------------------
    for (int i = tid; i < 384*8; i += 256) {
        const int row = i >> 3, c4 = i & 7;
        const size_t base = ((size_t)(b*NRES)+row)*CH + h*KD;
        float4 kv = *(const float4*)(g_k + base + c4*4);
        Kt[(c4*4+0)*PADK + row] = f2tf32(kv.x);
        Kt[(c4*4+1)*PADK + row] = f2tf32(kv.y);
        Kt[(c4*4+2)*PADK + row] = f2tf32(kv.z);
        Kt[(c4*4+3)*PADK + row] = f2tf32(kv.w);
    }
    // stage V (half2 packed along key dim: low = even key) -------------------
    for (int i = tid; i < 192*8; i += 256) {
        const int kp = i >> 3, c4 = i & 7;
        const size_t base = ((size_t)(b*NRES)+2*kp)*CH + h*KD;
        float4 v0 = *(const float4*)(g_v + base + c4*4);
        float4 v1 = *(const float4*)(g_v + base + CH + c4*4);
        Vs[(c4*4+0)*PADH + kp] = h2pack(v0.x, v1.x);
        Vs[(c4*4+1)*PADH + kp] = h2pack(v0.y, v1.y);
        Vs[(c4*4+2)*PADH + kp] = h2pack(v0.z, v1.z);
        Vs[(c4*4+3)*PADH + kp] = h2pack(v0.w, v1.w);
    }
    for (int i = tid; i < NRES; i += 256)
        mrow[i] = 1e9f * (mask[(size_t)b*NRES + i] - 1.f);
    __syncthreads();

    for (int p = 0; p < 3; ++p) {
        const int q0 = p*128 + warp*16;
        unsigned qa[4][4];
        const float* qbase = g_q + ((size_t)(b*NRES)+q0)*CH + h*KD;
        #pragma unroll
        for (int kc = 0; kc < 4; ++kc) {
            qa[kc][0] = f2tf32(qbase[gr*CH     + kc*8+gc  ]);
            qa[kc][1] = f2tf32(qbase[(gr+8)*CH + kc*8+gc  ]);
            qa[kc][2] = f2tf32(qbase[gr*CH     + kc*8+gc+4]);
            qa[kc][3] = f2tf32(qbase[(gr+8)*CH + kc*8+gc+4]);
        }
        const float* nb0 = g_nb + (size_t)h*NNPIX + (size_t)(q0+gr)*NRES;
        const float* nb1 = nb0 + (size_t)8*NRES;

        float m0 = -1e30f, m1 = -1e30f, sum0 = 0.f, sum1 = 0.f;
        float O[4][4];
        #pragma unroll
        for (int vt = 0; vt < 4; ++vt)
            #pragma unroll
            for (int t = 0; t < 4; ++t) O[vt][t] = 0.f;

        for (int c = 0; c < 6; ++c) {
            const int c0 = c*64;
            float s[8][4];
            #pragma unroll
            for (int t = 0; t < 8; ++t)
                #pragma unroll
                for (int j = 0; j < 4; ++j) s[t][j] = 0.f;

            #pragma unroll
            for (int t = 0; t < 8; ++t) {
                const int n0 = c0 + t*8;
                #pragma unroll
                for (int kc = 0; kc < 4; ++kc) {
                    unsigned bf[2];
                    bf[0] = Kt[(kc*8+gc  )*PADK + n0+gr];
                    bf[1] = Kt[(kc*8+gc+4)*PADK + n0+gr];
                    mma_tf32(s[t], qa[kc], bf);
                }
            }
            // bias + chunk row-max
            float mc0 = -1e30f, mc1 = -1e30f;
            #pragma unroll
            for (int t = 0; t < 8; ++t) {
                const int col = c0 + t*8 + gc*2;
                const float2 mr  = *(const float2*)(mrow + col);
                const float2 nlo = *(const float2*)(nb0 + col);
                const float2 nhi = *(const float2*)(nb1 + col);
                s[t][0] += mr.x + nlo.x; s[t][1] += mr.y + nlo.y;
                s[t][2] += mr.x + nhi.x; s[t][3] += mr.y + nhi.y;
                mc0 = fmaxf(mc0, fmaxf(s[t][0], s[t][1]));
                mc1 = fmaxf(mc1, fmaxf(s[t][2], s[t][3]));
            }
            mc0 = fmaxf(mc0, __shfl_xor_sync(0xffffffffu, mc0, 1));
            mc0 = fmaxf(mc0, __shfl_xor_sync(0xffffffffu, mc0, 2));
            mc1 = fmaxf(mc1, __shfl_xor_sync(0xffffffffu, mc1, 1));
            mc1 = fmaxf(mc1, __shfl_xor_sync(0xffffffffu, mc1, 2));
            const float mn0 = fmaxf(m0, mc0), mn1 = fmaxf(m1, mc1);
            const float al0 = __expf(m0 - mn0), al1 = __expf(m1 - mn1);
            m0 = mn0; m1 = mn1;
            sum0 *= al0; sum1 *= al1;
            #pragma unroll
            for (int vt = 0; vt < 4; ++vt) {
                O[vt][0] *= al0; O[vt][1] *= al0;
                O[vt][2] *= al1; O[vt][3] *= al1;
            }
            float cs0 = 0.f, cs1 = 0.f;
            #pragma unroll
            for (int t = 0; t < 8; ++t) {
                s[t][0] = __expf(s[t][0] - mn0);
                s[t][1] = __expf(s[t][1] - mn0);
                s[t][2] = __expf(s[t][2] - mn1);
                s[t][3] = __expf(s[t][3] - mn1);
                cs0 += s[t][0] + s[t][1];
                cs1 += s[t][2] + s[t][3];
            }
            cs0 += __shfl_xor_sync(0xffffffffu, cs0, 1);
            cs0 += __shfl_xor_sync(0xffffffffu, cs0, 2);
            cs1 += __shfl_xor_sync(0xffffffffu, cs1, 1);
            cs1 += __shfl_xor_sync(0xffffffffu, cs1, 2);
            sum0 += cs0; sum1 += cs1;

            // PV: P C-frags pack directly into fp16 A-frags (no shuffles)
            #pragma unroll
            for (int kc16 = 0; kc16 < 4; ++kc16) {
                const int e = 2*kc16, o = e+1;
                unsigned pa[4];
                pa[0] = h2pack(s[e][0], s[e][1]);
                pa[1] = h2pack(s[e][2], s[e][3]);
                pa[2] = h2pack(s[o][0], s[o][1]);
                pa[3] = h2pack(s[o][2], s[o][3]);
                const int kpb = (c0 >> 1) + kc16*8;
                #pragma unroll
                for (int vt = 0; vt < 4; ++vt) {
                    const unsigned* vrow = Vs + (vt*8+gr)*PADH + kpb;
                    mma_f16(O[vt], pa, vrow[gc], vrow[gc+4]);
                }
            }
        }

        const float inv0 = 1.f / sum0, inv1 = 1.f / sum1;
        const size_t orow0 = ((size_t)(b*NRES)+q0+gr)*CH + h*KD;
        const size_t orow1 = orow0 + (size_t)8*CH;
        #pragma unroll
        for (int vt = 0; vt < 4; ++vt) {
            const int cl = vt*8 + gc*2;
            const float2 g0 = *(const float2*)(g_g + orow0 + cl);
            const float2 g1 = *(const float2*)(g_g + orow1 + cl);
            *(float2*)(g_att + orow0 + cl) =
                make_float2(O[vt][0]*inv0*g0.x, O[vt][1]*inv0*g0.y);
            *(float2*)(g_att + orow1 + cl) =
                make_float2(O[vt][2]*inv1*g1.x, O[vt][3]*inv1*g1.y);
        }
    }
}

// ---------------- kernel 3: output projection via tf32 mma (M=64) ------------
__global__ __launch_bounds__(256) void out_mma_kernel(
    const float* __restrict__ ow, const float* __restrict__ ob,
    float* __restrict__ out)
{
    extern __shared__ unsigned smu[];
    unsigned* xs = smu;
    unsigned* ws = smu + 64*PADA;
    const int tid = threadIdx.x;
    const int warp = tid >> 5, lane = tid & 31;
    const int gr = lane >> 2, gc = lane & 3;
    const int mw = warp & 1, nw = warp >> 1;
    const int rw0 = mw * 32, nw0 = nw * 32;
    const int r0 = blockIdx.x * 64;

    for (int i = tid; i < 64*32; i += 256) {
        const int r = i >> 5, c4 = i & 31;
        float4 v = ((const float4*)(g_att + (size_t)(r0 + r)*CH))[c4];
        unsigned* d = xs + r*PADA + c4*4;
        d[0]=f2tf32(v.x); d[1]=f2tf32(v.y); d[2]=f2tf32(v.z); d[3]=f2tf32(v.w);
    }
    for (int i = tid; i < 128*32; i += 256) {
        const int k = i >> 5, c4 = i & 31;
        float4 v = ((const float4*)(ow + (size_t)k*CH))[c4];
        unsigned* d = ws + k*PADB + c4*4;
        d[0]=f2tf32(v.x); d[1]=f2tf32(v.y); d[2]=f2tf32(v.z); d[3]=f2tf32(v.w);
    }
    __syncthreads();

    float c[2][4][4];
    #pragma unroll
    for (int mi = 0; mi < 2; ++mi)
        #pragma unroll
        for (int ni = 0; ni < 4; ++ni)
            #pragma unroll
            for (int t = 0; t < 4; ++t) c[mi][ni][t] = 0.f;

    #pragma unroll 4
    for (int kk = 0; kk < 16; ++kk) {
        const int k0 = kk * 8;
        unsigned a[2][4];
        #pragma unroll
        for (int mi = 0; mi < 2; ++mi) {
            const int rb = rw0 + mi*16;
            a[mi][0] = xs[(rb+gr  )*PADA + k0+gc  ];
            a[mi][1] = xs[(rb+gr+8)*PADA + k0+gc  ];
            a[mi][2] = xs[(rb+gr  )*PADA + k0+gc+4];
            a[mi][3] = xs[(rb+gr+8)*PADA + k0+gc+4];
        }
        unsigned b[4][2];
        #pragma unroll
        for (int ni = 0; ni < 4; ++ni) {
            const int n0 = nw0 + ni*8 + gr;
            b[ni][0] = ws[(k0+gc  )*PADB + n0];
            b[ni][1] = ws[(k0+gc+4)*PADB + n0];
        }
        #pragma unroll
        for (int mi = 0; mi < 2; ++mi)
            #pragma unroll
            for (int ni = 0; ni < 4; ++ni)
                mma_tf32(c[mi][ni], a[mi], b[ni]);
    }

    #pragma unroll
    for (int mi = 0; mi < 2; ++mi) {
        const int row0 = r0 + rw0 + mi*16 + gr;
        #pragma unroll
        for (int ni = 0; ni < 4; ++ni) {
            const int col = nw0 + ni*8 + gc*2;
            const float2 bb = *(const float2*)(ob + col);
            *(float2*)(out + (size_t)row0*CH + col) =
                make_float2(c[mi][ni][0] + bb.x, c[mi][ni][1] + bb.y);
            *(float2*)(out + (size_t)(row0+8)*CH + col) =
                make_float2(c[mi][ni][2] + bb.x, c[mi][ni][3] + bb.y);
        }
    }
}

// ---------------- launcher ---------------------------------------------------
extern "C" void kernel_launch(void* const* d_in, const int* in_sizes, int n_in,
                              void* d_out, int out_size)
{
    const float* pact = (const float*)d_in[0];
    const float* mask = (const float*)d_in[1];
    const float* lns  = (const float*)d_in[2];
    const float* lnb  = (const float*)d_in[3];
    const float* f2w  = (const float*)d_in[4];
    const float* qw   = (const float*)d_in[5];
    const float* kw   = (const float*)d_in[6];
    const float* vw   = (const float*)d_in[7];
    const float* gw   = (const float*)d_in[8];
    const float* gb   = (const float*)d_in[9];
    const float* ow   = (const float*)d_in[10];
    const float* ob   = (const float*)d_in[11];
    float* out = (float*)d_out;

    const int GEMM_SMEM = (64*PADA + 128*PADB) * 4;             // 103424
    const int ATTN_SMEM = (32*PADK + 32*PADH + NRES) * 4;       // 76800

    cudaFuncSetAttribute(lnproj_mma_kernel, cudaFuncAttributeMaxDynamicSharedMemorySize, GEMM_SMEM);
    cudaFuncSetAttribute(out_mma_kernel,    cudaFuncAttributeMaxDynamicSharedMemorySize, GEMM_SMEM);
    cudaFuncSetAttribute(attn_mma_kernel,   cudaFuncAttributeMaxDynamicSharedMemorySize, ATTN_SMEM);

    lnproj_mma_kernel<<<NNPIX/64, 256, GEMM_SMEM>>>(pact, lns, lnb, f2w, qw, kw, vw, gw, gb);
    attn_mma_kernel<<<dim3(NRES, NH), 256, ATTN_SMEM>>>(mask);
    out_mma_kernel<<<NNPIX/64, 256, GEMM_SMEM>>>(ow, ob, out);
}

// round 6
// speedup vs baseline: 7.8726x; 1.3466x over previous
#include <cuda_runtime.h>
#include <cuda_fp16.h>
#include <math.h>

#define NRES 384
#define NNPIX (NRES*NRES)          // 147456
#define CH 128
#define NH 4
#define KD 32
#define QSCALE 0.17677669529663689f  // 1/sqrt(32)

#define PADA2 68   // X half2 pad: A-frag bank = 4*gr+gc -> conflict-free
#define PADB2 136  // W half2 pad: B-frag bank = 8*gc+gr -> conflict-free
#define PADK2 392  // K half2 pad: B-frag bank = 8*gc+gr -> conflict-free
#define PADH 196   // V half2 pad (key pairs): bank = 4*gr+gc -> conflict-free

// ---------------- scratch ----------------------------------------------------
__device__ __align__(16) float g_nb [(size_t)NH*NNPIX];
__device__ __align__(16) float g_q  [(size_t)NNPIX*CH];
__device__ __align__(16) float g_k  [(size_t)NNPIX*CH];
__device__ __align__(16) float g_v  [(size_t)NNPIX*CH];
__device__ __align__(16) float g_g  [(size_t)NNPIX*CH];
__device__ __align__(16) float g_att[(size_t)NNPIX*CH];

// ---------------- helpers -----------------------------------------------------
__device__ __forceinline__ unsigned h2pack(float lo, float hi) {
    unsigned u;
    asm("cvt.rn.f16x2.f32 %0, %1, %2;" : "=r"(u) : "f"(hi), "f"(lo));
    return u;
}
__device__ __forceinline__ void mma_f16(float c[4], const unsigned a[4], unsigned b0, unsigned b1) {
    asm volatile(
        "mma.sync.aligned.m16n8k16.row.col.f32.f16.f16.f32 "
        "{%0,%1,%2,%3}, {%4,%5,%6,%7}, {%8,%9}, {%0,%1,%2,%3};"
        : "+f"(c[0]), "+f"(c[1]), "+f"(c[2]), "+f"(c[3])
        : "r"(a[0]), "r"(a[1]), "r"(a[2]), "r"(a[3]), "r"(b0), "r"(b1));
}

// ---------------- kernel 1: fused LN + nb-bias + q/k/v/gate (fp16 mma) -------
// 8 warps: 2 m-warps x 4 n-warps; warp tile 32x32.
__global__ __launch_bounds__(256, 3) void lnproj_mma_kernel(
    const float* __restrict__ pact, const float* __restrict__ lns,
    const float* __restrict__ lnb, const float* __restrict__ f2w,
    const float* __restrict__ qw, const float* __restrict__ kw,
    const float* __restrict__ vw, const float* __restrict__ gw,
    const float* __restrict__ gb)
{
    extern __shared__ unsigned smu[];
    unsigned* xs = smu;               // [64 rows][PADA2] half2 (k-pairs)
    unsigned* ws = smu + 64*PADA2;    // [64 k-pairs][PADB2] half2
    const int tid = threadIdx.x;
    const int warp = tid >> 5, lane = tid & 31;
    const int gr = lane >> 2, gc = lane & 3;
    const int mw = warp & 1, nw = warp >> 1;
    const int rw0 = mw * 32, nw0 = nw * 32;
    const int r0 = blockIdx.x * 64;

    // ---- stage 1: per-row LayerNorm + nb bias; write half2 X tile -----------
    {
        const float4 sc = ((const float4*)lns)[lane];
        const float4 bi = ((const float4*)lnb)[lane];
        const float4* w4 = (const float4*)f2w;
        const float4 w0 = w4[lane*4+0], w1 = w4[lane*4+1],
                     w2 = w4[lane*4+2], w3 = w4[lane*4+3];
        #pragma unroll 2
        for (int k = 0; k < 8; ++k) {
            const int r = k*8 + warp;
            const size_t p = (size_t)(r0 + r);
            float4 v = ((const float4*)(pact + p*CH))[lane];
            float s = v.x + v.y + v.z + v.w;
            #pragma unroll
            for (int o = 16; o; o >>= 1) s += __shfl_xor_sync(0xffffffffu, s, o);
            const float mu = s * (1.0f/CH);
            const float dx = v.x-mu, dy = v.y-mu, dz = v.z-mu, dw = v.w-mu;
            float ss = dx*dx + dy*dy + dz*dz + dw*dw;
            #pragma unroll
            for (int o = 16; o; o >>= 1) ss += __shfl_xor_sync(0xffffffffu, ss, o);
            const float inv = rsqrtf(ss * (1.0f/CH) + 1e-5f);
            float4 xn;
            xn.x = dx*inv*sc.x + bi.x;
            xn.y = dy*inv*sc.y + bi.y;
            xn.z = dz*inv*sc.z + bi.z;
            xn.w = dw*inv*sc.w + bi.w;
            unsigned* d = xs + r*PADA2 + lane*2;
            d[0] = h2pack(xn.x, xn.y);
            d[1] = h2pack(xn.z, xn.w);

            float n0 = xn.x*w0.x + xn.y*w1.x + xn.z*w2.x + xn.w*w3.x;
            float n1 = xn.x*w0.y + xn.y*w1.y + xn.z*w2.y + xn.w*w3.y;
            float n2 = xn.x*w0.z + xn.y*w1.z + xn.z*w2.z + xn.w*w3.z;
            float n3 = xn.x*w0.w + xn.y*w1.w + xn.z*w2.w + xn.w*w3.w;
            #pragma unroll
            for (int o = 16; o; o >>= 1) {
                n0 += __shfl_xor_sync(0xffffffffu, n0, o);
                n1 += __shfl_xor_sync(0xffffffffu, n1, o);
                n2 += __shfl_xor_sync(0xffffffffu, n2, o);
                n3 += __shfl_xor_sync(0xffffffffu, n3, o);
            }
            if (lane == 0) {
                g_nb[0*(size_t)NNPIX + p] = n0;
                g_nb[1*(size_t)NNPIX + p] = n1;
                g_nb[2*(size_t)NNPIX + p] = n2;
                g_nb[3*(size_t)NNPIX + p] = n3;
            }
        }
    }

    // ---- stage 2: four W passes --------------------------------------------
    for (int m = 0; m < 4; ++m) {
        const float* W = (m==0) ? qw : (m==1) ? kw : (m==2) ? vw : gw;
        __syncthreads();
        // pack W[k][n] -> ws[k/2][n] half2(k even, k odd)
        for (int i = tid; i < 64*32; i += 256) {
            const int k2 = i >> 5, c4 = i & 31;
            float4 va = ((const float4*)(W + (size_t)(2*k2  )*CH))[c4];
            float4 vb = ((const float4*)(W + (size_t)(2*k2+1)*CH))[c4];
            unsigned* d = ws + k2*PADB2 + c4*4;
            d[0] = h2pack(va.x, vb.x);
            d[1] = h2pack(va.y, vb.y);
            d[2] = h2pack(va.z, vb.z);
            d[3] = h2pack(va.w, vb.w);
        }
        __syncthreads();

        float c[2][4][4];
        #pragma unroll
        for (int mi = 0; mi < 2; ++mi)
            #pragma unroll
            for (int ni = 0; ni < 4; ++ni)
                #pragma unroll
                for (int t = 0; t < 4; ++t) c[mi][ni][t] = 0.f;

        #pragma unroll
        for (int t = 0; t < 8; ++t) {          // 8 k16-tiles
            const int p0 = t * 8;              // k-pair base
            unsigned a[2][4];
            #pragma unroll
            for (int mi = 0; mi < 2; ++mi) {
                const int rb = rw0 + mi*16;
                a[mi][0] = xs[(rb+gr  )*PADA2 + p0+gc  ];
                a[mi][1] = xs[(rb+gr+8)*PADA2 + p0+gc  ];
                a[mi][2] = xs[(rb+gr  )*PADA2 + p0+gc+4];
                a[mi][3] = xs[(rb+gr+8)*PADA2 + p0+gc+4];
            }
            unsigned b[4][2];
            #pragma unroll
            for (int ni = 0; ni < 4; ++ni) {
                const int n0 = nw0 + ni*8 + gr;
                b[ni][0] = ws[(p0+gc  )*PADB2 + n0];
                b[ni][1] = ws[(p0+gc+4)*PADB2 + n0];
            }
            #pragma unroll
            for (int mi = 0; mi < 2; ++mi)
                #pragma unroll
                for (int ni = 0; ni < 4; ++ni)
                    mma_f16(c[mi][ni], a[mi], b[ni][0], b[ni][1]);
        }

        float* outp = (m==0) ? g_q : (m==1) ? g_k : (m==2) ? g_v : g_g;
        #pragma unroll
        for (int mi = 0; mi < 2; ++mi) {
            const int row0 = r0 + rw0 + mi*16 + gr;
            #pragma unroll
            for (int ni = 0; ni < 4; ++ni) {
                const int col = nw0 + ni*8 + gc*2;
                float v0x = c[mi][ni][0], v0y = c[mi][ni][1];
                float v1x = c[mi][ni][2], v1y = c[mi][ni][3];
                if (m == 0) { v0x*=QSCALE; v0y*=QSCALE; v1x*=QSCALE; v1y*=QSCALE; }
                if (m == 3) {
                    const float2 bb = *(const float2*)(gb + col);
                    v0x = 1.f/(1.f + __expf(-(v0x + bb.x)));
                    v0y = 1.f/(1.f + __expf(-(v0y + bb.y)));
                    v1x = 1.f/(1.f + __expf(-(v1x + bb.x)));
                    v1y = 1.f/(1.f + __expf(-(v1y + bb.y)));
                }
                *(float2*)(outp + (size_t)row0*CH + col)     = make_float2(v0x, v0y);
                *(float2*)(outp + (size_t)(row0+8)*CH + col) = make_float2(v1x, v1y);
            }
        }
    }
}

// ---------------- kernel 2: flash attention, all-fp16 mma --------------------
// block = (b, h); 8 warps x 16 q-rows x 3 passes; keys in 6 chunks of 64.
__global__ __launch_bounds__(256, 3) void attn_mma_kernel(const float* __restrict__ mask)
{
    extern __shared__ unsigned sm_u[];
    unsigned* Kd2 = sm_u;                      // [16 d-pairs][PADK2] half2
    unsigned* Vs  = Kd2 + 16*PADK2;            // [32 d][PADH] half2 (key-pairs)
    float* mrow   = (float*)(Vs + 32*PADH);    // [384]
    const int b = blockIdx.x, h = blockIdx.y;
    const int tid = threadIdx.x, warp = tid >> 5, lane = tid & 31;
    const int gr = lane >> 2, gc = lane & 3;

    // stage K: half2 packed along d (pairs d, d+1), row = d-pair, col = key
    for (int i = tid; i < 384*4; i += 256) {
        const int key = i >> 2, q4 = i & 3;
        const float* base = g_k + ((size_t)(b*NRES)+key)*CH + h*KD + q4*8;
        float4 va = *(const float4*)(base);
        float4 vb = *(const float4*)(base + 4);
        Kd2[(q4*4+0)*PADK2 + key] = h2pack(va.x, va.y);
        Kd2[(q4*4+1)*PADK2 + key] = h2pack(va.z, va.w);
        Kd2[(q4*4+2)*PADK2 + key] = h2pack(vb.x, vb.y);
        Kd2[(q4*4+3)*PADK2 + key] = h2pack(vb.z, vb.w);
    }
    // stage V: half2 packed along key dim (low = even key)
    for (int i = tid; i < 192*8; i += 256) {
        const int kp = i >> 3, c4 = i & 7;
        const size_t base = ((size_t)(b*NRES)+2*kp)*CH + h*KD;
        float4 v0 = *(const float4*)(g_v + base + c4*4);
        float4 v1 = *(const float4*)(g_v + base + CH + c4*4);
        Vs[(c4*4+0)*PADH + kp] = h2pack(v0.x, v1.x);
        Vs[(c4*4+1)*PADH + kp] = h2pack(v0.y, v1.y);
        Vs[(c4*4+2)*PADH + kp] = h2pack(v0.z, v1.z);
        Vs[(c4*4+3)*PADH + kp] = h2pack(v0.w, v1.w);
    }
    for (int i = tid; i < NRES; i += 256)
        mrow[i] = 1e9f * (mask[(size_t)b*NRES + i] - 1.f);
    __syncthreads();

    for (int p = 0; p < 3; ++p) {
        const int q0 = p*128 + warp*16;
        // Q fp16 A-frags: 2 k16-tiles
        unsigned qa[2][4];
        const float* qbase = g_q + ((size_t)(b*NRES)+q0)*CH + h*KD;
        #pragma unroll
        for (int kc = 0; kc < 2; ++kc) {
            const float* qlo = qbase + gr*CH     + kc*16;
            const float* qhi = qbase + (gr+8)*CH + kc*16;
            qa[kc][0] = h2pack(qlo[2*gc  ], qlo[2*gc+1]);
            qa[kc][1] = h2pack(qhi[2*gc  ], qhi[2*gc+1]);
            qa[kc][2] = h2pack(qlo[2*gc+8], qlo[2*gc+9]);
            qa[kc][3] = h2pack(qhi[2*gc+8], qhi[2*gc+9]);
        }
        const float* nb0 = g_nb + (size_t)h*NNPIX + (size_t)(q0+gr)*NRES;
        const float* nb1 = nb0 + (size_t)8*NRES;

        float m0 = -1e30f, m1 = -1e30f, sum0 = 0.f, sum1 = 0.f;
        float O[4][4];
        #pragma unroll
        for (int vt = 0; vt < 4; ++vt)
            #pragma unroll
            for (int t = 0; t < 4; ++t) O[vt][t] = 0.f;

        for (int c = 0; c < 6; ++c) {
            const int c0 = c*64;
            float s[8][4];
            #pragma unroll
            for (int t = 0; t < 8; ++t)
                #pragma unroll
                for (int j = 0; j < 4; ++j) s[t][j] = 0.f;

            #pragma unroll
            for (int t = 0; t < 8; ++t) {
                const int n0 = c0 + t*8 + gr;
                #pragma unroll
                for (int kc = 0; kc < 2; ++kc) {
                    mma_f16(s[t], qa[kc],
                            Kd2[(kc*8+gc  )*PADK2 + n0],
                            Kd2[(kc*8+gc+4)*PADK2 + n0]);
                }
            }
            // bias + chunk row-max
            float mc0 = -1e30f, mc1 = -1e30f;
            #pragma unroll
            for (int t = 0; t < 8; ++t) {
                const int col = c0 + t*8 + gc*2;
                const float2 mr  = *(const float2*)(mrow + col);
                const float2 nlo = *(const float2*)(nb0 + col);
                const float2 nhi = *(const float2*)(nb1 + col);
                s[t][0] += mr.x + nlo.x; s[t][1] += mr.y + nlo.y;
                s[t][2] += mr.x + nhi.x; s[t][3] += mr.y + nhi.y;
                mc0 = fmaxf(mc0, fmaxf(s[t][0], s[t][1]));
                mc1 = fmaxf(mc1, fmaxf(s[t][2], s[t][3]));
            }
            mc0 = fmaxf(mc0, __shfl_xor_sync(0xffffffffu, mc0, 1));
            mc0 = fmaxf(mc0, __shfl_xor_sync(0xffffffffu, mc0, 2));
            mc1 = fmaxf(mc1, __shfl_xor_sync(0xffffffffu, mc1, 1));
            mc1 = fmaxf(mc1, __shfl_xor_sync(0xffffffffu, mc1, 2));
            const float mn0 = fmaxf(m0, mc0), mn1 = fmaxf(m1, mc1);
            const float al0 = __expf(m0 - mn0), al1 = __expf(m1 - mn1);
            m0 = mn0; m1 = mn1;
            sum0 *= al0; sum1 *= al1;
            #pragma unroll
            for (int vt = 0; vt < 4; ++vt) {
                O[vt][0] *= al0; O[vt][1] *= al0;
                O[vt][2] *= al1; O[vt][3] *= al1;
            }
            float cs0 = 0.f, cs1 = 0.f;
            #pragma unroll
            for (int t = 0; t < 8; ++t) {
                s[t][0] = __expf(s[t][0] - mn0);
                s[t][1] = __expf(s[t][1] - mn0);
                s[t][2] = __expf(s[t][2] - mn1);
                s[t][3] = __expf(s[t][3] - mn1);
                cs0 += s[t][0] + s[t][1];
                cs1 += s[t][2] + s[t][3];
            }
            cs0 += __shfl_xor_sync(0xffffffffu, cs0, 1);
            cs0 += __shfl_xor_sync(0xffffffffu, cs0, 2);
            cs1 += __shfl_xor_sync(0xffffffffu, cs1, 1);
            cs1 += __shfl_xor_sync(0xffffffffu, cs1, 2);
            sum0 += cs0; sum1 += cs1;

            // PV: P C-frags pack directly into fp16 A-frags (no shuffles)
            #pragma unroll
            for (int kc16 = 0; kc16 < 4; ++kc16) {
                const int e = 2*kc16, o = e+1;
                unsigned pa[4];
                pa[0] = h2pack(s[e][0], s[e][1]);
                pa[1] = h2pack(s[e][2], s[e][3]);
                pa[2] = h2pack(s[o][0], s[o][1]);
                pa[3] = h2pack(s[o][2], s[o][3]);
                const int kpb = (c0 >> 1) + kc16*8;
                #pragma unroll
                for (int vt = 0; vt < 4; ++vt) {
                    const unsigned* vrow = Vs + (vt*8+gr)*PADH + kpb;
                    mma_f16(O[vt], pa, vrow[gc], vrow[gc+4]);
                }
            }
        }

        const float inv0 = 1.f / sum0, inv1 = 1.f / sum1;
        const size_t orow0 = ((size_t)(b*NRES)+q0+gr)*CH + h*KD;
        const size_t orow1 = orow0 + (size_t)8*CH;
        #pragma unroll
        for (int vt = 0; vt < 4; ++vt) {
            const int cl = vt*8 + gc*2;
            const float2 g0 = *(const float2*)(g_g + orow0 + cl);
            const float2 g1 = *(const float2*)(g_g + orow1 + cl);
            *(float2*)(g_att + orow0 + cl) =
                make_float2(O[vt][0]*inv0*g0.x, O[vt][1]*inv0*g0.y);
            *(float2*)(g_att + orow1 + cl) =
                make_float2(O[vt][2]*inv1*g1.x, O[vt][3]*inv1*g1.y);
        }
    }
}

// ---------------- kernel 3: output projection (fp16 mma) ---------------------
__global__ __launch_bounds__(256, 3) void out_mma_kernel(
    const float* __restrict__ ow, const float* __restrict__ ob,
    float* __restrict__ out)
{
    extern __shared__ unsigned smu[];
    unsigned* xs = smu;               // [64][PADA2]
    unsigned* ws = smu + 64*PADA2;    // [64][PADB2]
    const int tid = threadIdx.x;
    const int warp = tid >> 5, lane = tid & 31;
    const int gr = lane >> 2, gc = lane & 3;
    const int mw = warp & 1, nw = warp >> 1;
    const int rw0 = mw * 32, nw0 = nw * 32;
    const int r0 = blockIdx.x * 64;

    for (int i = tid; i < 64*32; i += 256) {
        const int r = i >> 5, c4 = i & 31;
        float4 v = ((const float4*)(g_att + (size_t)(r0 + r)*CH))[c4];
        unsigned* d = xs + r*PADA2 + c4*2;
        d[0] = h2pack(v.x, v.y);
        d[1] = h2pack(v.z, v.w);
    }
    for (int i = tid; i < 64*32; i += 256) {
        const int k2 = i >> 5, c4 = i & 31;
        float4 va = ((const float4*)(ow + (size_t)(2*k2  )*CH))[c4];
        float4 vb = ((const float4*)(ow + (size_t)(2*k2+1)*CH))[c4];
        unsigned* d = ws + k2*PADB2 + c4*4;
        d[0] = h2pack(va.x, vb.x);
        d[1] = h2pack(va.y, vb.y);
        d[2] = h2pack(va.z, vb.z);
        d[3] = h2pack(va.w, vb.w);
    }
    __syncthreads();

    float c[2][4][4];
    #pragma unroll
    for (int mi = 0; mi < 2; ++mi)
        #pragma unroll
        for (int ni = 0; ni < 4; ++ni)
            #pragma unroll
            for (int t = 0; t < 4; ++t) c[mi][ni][t] = 0.f;

    #pragma unroll
    for (int t = 0; t < 8; ++t) {
        const int p0 = t * 8;
        unsigned a[2][4];
        #pragma unroll
        for (int mi = 0; mi < 2; ++mi) {
            const int rb = rw0 + mi*16;
            a[mi][0] = xs[(rb+gr  )*PADA2 + p0+gc  ];
            a[mi][1] = xs[(rb+gr+8)*PADA2 + p0+gc  ];
            a[mi][2] = xs[(rb+gr  )*PADA2 + p0+gc+4];
            a[mi][3] = xs[(rb+gr+8)*PADA2 + p0+gc+4];
        }
        unsigned b[4][2];
        #pragma unroll
        for (int ni = 0; ni < 4; ++ni) {
            const int n0 = nw0 + ni*8 + gr;
            b[ni][0] = ws[(p0+gc  )*PADB2 + n0];
            b[ni][1] = ws[(p0+gc+4)*PADB2 + n0];
        }
        #pragma unroll
        for (int mi = 0; mi < 2; ++mi)
            #pragma unroll
            for (int ni = 0; ni < 4; ++ni)
                mma_f16(c[mi][ni], a[mi], b[ni][0], b[ni][1]);
    }

    #pragma unroll
    for (int mi = 0; mi < 2; ++mi) {
        const int row0 = r0 + rw0 + mi*16 + gr;
        #pragma unroll
        for (int ni = 0; ni < 4; ++ni) {
            const int col = nw0 + ni*8 + gc*2;
            const float2 bb = *(const float2*)(ob + col);
            *(float2*)(out + (size_t)row0*CH + col) =
                make_float2(c[mi][ni][0] + bb.x, c[mi][ni][1] + bb.y);
            *(float2*)(out + (size_t)(row0+8)*CH + col) =
                make_float2(c[mi][ni][2] + bb.x, c[mi][ni][3] + bb.y);
        }
    }
}

// ---------------- launcher ---------------------------------------------------
extern "C" void kernel_launch(void* const* d_in, const int* in_sizes, int n_in,
                              void* d_out, int out_size)
{
    const float* pact = (const float*)d_in[0];
    const float* mask = (const float*)d_in[1];
    const float* lns  = (const float*)d_in[2];
    const float* lnb  = (const float*)d_in[3];
    const float* f2w  = (const float*)d_in[4];
    const float* qw   = (const float*)d_in[5];
    const float* kw   = (const float*)d_in[6];
    const float* vw   = (const float*)d_in[7];
    const float* gw   = (const float*)d_in[8];
    const float* gb   = (const float*)d_in[9];
    const float* ow   = (const float*)d_in[10];
    const float* ob   = (const float*)d_in[11];
    float* out = (float*)d_out;

    const int GEMM_SMEM = (64*PADA2 + 64*PADB2) * 4;              // 52224
    const int ATTN_SMEM = (16*PADK2 + 32*PADH + NRES) * 4;        // 51712

    cudaFuncSetAttribute(lnproj_mma_kernel, cudaFuncAttributeMaxDynamicSharedMemorySize, GEMM_SMEM);
    cudaFuncSetAttribute(out_mma_kernel,    cudaFuncAttributeMaxDynamicSharedMemorySize, GEMM_SMEM);
    cudaFuncSetAttribute(attn_mma_kernel,   cudaFuncAttributeMaxDynamicSharedMemorySize, ATTN_SMEM);

    lnproj_mma_kernel<<<NNPIX/64, 256, GEMM_SMEM>>>(pact, lns, lnb, f2w, qw, kw, vw, gw, gb);
    attn_mma_kernel<<<dim3(NRES, NH), 256, ATTN_SMEM>>>(mask);
    out_mma_kernel<<<NNPIX/64, 256, GEMM_SMEM>>>(ow, ob, out);
}

// round 9
// speedup vs baseline: 8.3723x; 1.0635x over previous
#include <cuda_runtime.h>
#include <cuda_fp16.h>
#include <math.h>

#define NRES 384
#define NNPIX (NRES*NRES)          // 147456
#define CH 128
#define NH 4
#define KD 32
#define QSCALE 0.17677669529663689f  // 1/sqrt(32)

#define PADA2 68   // X half2 pad: A-frag bank = 4*gr+gc -> conflict-free
#define PADB2 136  // W half2 pad: B-frag bank = 8*gc+gr -> conflict-free
#define PADK2 392  // K half2 pad: B-frag bank = 8*gc+gr -> conflict-free
#define PADH 196   // V half2 pad (key pairs): bank = 4*gr+gc -> conflict-free

// ---------------- scratch (fp16 intermediates) --------------------------------
__device__ __align__(16) float   g_nb [(size_t)NH*NNPIX];
__device__ __align__(16) __half  g_q  [(size_t)NNPIX*CH];
__device__ __align__(16) __half  g_k  [(size_t)NNPIX*CH];
__device__ __align__(16) __half  g_v  [(size_t)NNPIX*CH];
__device__ __align__(16) __half  g_g  [(size_t)NNPIX*CH];
__device__ __align__(16) __half  g_att[(size_t)NNPIX*CH];

// ---------------- helpers -----------------------------------------------------
__device__ __forceinline__ unsigned h2pack(float lo, float hi) {
    unsigned u;
    asm("cvt.rn.f16x2.f32 %0, %1, %2;" : "=r"(u) : "f"(hi), "f"(lo));
    return u;
}
__device__ __forceinline__ float2 h2unpack(unsigned u) {
    __half2 h = *(__half2*)&u;
    return __half22float2(h);
}
__device__ __forceinline__ void mma_f16(float c[4], const unsigned a[4], unsigned b0, unsigned b1) {
    asm volatile(
        "mma.sync.aligned.m16n8k16.row.col.f32.f16.f16.f32 "
        "{%0,%1,%2,%3}, {%4,%5,%6,%7}, {%8,%9}, {%0,%1,%2,%3};"
        : "+f"(c[0]), "+f"(c[1]), "+f"(c[2]), "+f"(c[3])
        : "r"(a[0]), "r"(a[1]), "r"(a[2]), "r"(a[3]), "r"(b0), "r"(b1));
}

// ---------------- kernel 1: fused LN + nb-bias + q/k/v/gate (fp16 mma) -------
__global__ __launch_bounds__(256, 3) void lnproj_mma_kernel(
    const float* __restrict__ pact, const float* __restrict__ lns,
    const float* __restrict__ lnb, const float* __restrict__ f2w,
    const float* __restrict__ qw, const float* __restrict__ kw,
    const float* __restrict__ vw, const float* __restrict__ gw,
    const float* __restrict__ gb)
{
    extern __shared__ unsigned smu[];
    unsigned* xs = smu;               // [64 rows][PADA2] half2 (k-pairs)
    unsigned* ws = smu + 64*PADA2;    // [64 k-pairs][PADB2] half2
    const int tid = threadIdx.x;
    const int warp = tid >> 5, lane = tid & 31;
    const int gr = lane >> 2, gc = lane & 3;
    const int mw = warp & 1, nw = warp >> 1;
    const int rw0 = mw * 32, nw0 = nw * 32;
    const int r0 = blockIdx.x * 64;

    // ---- stage 1: per-row LayerNorm + nb bias; write half2 X tile -----------
    {
        const float4 sc = ((const float4*)lns)[lane];
        const float4 bi = ((const float4*)lnb)[lane];
        const float4* w4 = (const float4*)f2w;
        const float4 w0 = w4[lane*4+0], w1 = w4[lane*4+1],
                     w2 = w4[lane*4+2], w3 = w4[lane*4+3];
        #pragma unroll 2
        for (int k = 0; k < 8; ++k) {
            const int r = k*8 + warp;
            const size_t p = (size_t)(r0 + r);
            float4 v = ((const float4*)(pact + p*CH))[lane];
            float s = v.x + v.y + v.z + v.w;
            #pragma unroll
            for (int o = 16; o; o >>= 1) s += __shfl_xor_sync(0xffffffffu, s, o);
            const float mu = s * (1.0f/CH);
            const float dx = v.x-mu, dy = v.y-mu, dz = v.z-mu, dw = v.w-mu;
            float ss = dx*dx + dy*dy + dz*dz + dw*dw;
            #pragma unroll
            for (int o = 16; o; o >>= 1) ss += __shfl_xor_sync(0xffffffffu, ss, o);
            const float inv = rsqrtf(ss * (1.0f/CH) + 1e-5f);
            float4 xn;
            xn.x = dx*inv*sc.x + bi.x;
            xn.y = dy*inv*sc.y + bi.y;
            xn.z = dz*inv*sc.z + bi.z;
            xn.w = dw*inv*sc.w + bi.w;
            unsigned* d = xs + r*PADA2 + lane*2;
            d[0] = h2pack(xn.x, xn.y);
            d[1] = h2pack(xn.z, xn.w);

            float n0 = xn.x*w0.x + xn.y*w1.x + xn.z*w2.x + xn.w*w3.x;
            float n1 = xn.x*w0.y + xn.y*w1.y + xn.z*w2.y + xn.w*w3.y;
            float n2 = xn.x*w0.z + xn.y*w1.z + xn.z*w2.z + xn.w*w3.z;
            float n3 = xn.x*w0.w + xn.y*w1.w + xn.z*w2.w + xn.w*w3.w;
            #pragma unroll
            for (int o = 16; o; o >>= 1) {
                n0 += __shfl_xor_sync(0xffffffffu, n0, o);
                n1 += __shfl_xor_sync(0xffffffffu, n1, o);
                n2 += __shfl_xor_sync(0xffffffffu, n2, o);
                n3 += __shfl_xor_sync(0xffffffffu, n3, o);
            }
            if (lane == 0) {
                g_nb[0*(size_t)NNPIX + p] = n0;
                g_nb[1*(size_t)NNPIX + p] = n1;
                g_nb[2*(size_t)NNPIX + p] = n2;
                g_nb[3*(size_t)NNPIX + p] = n3;
            }
        }
    }

    // ---- stage 2: four W passes --------------------------------------------
    for (int m = 0; m < 4; ++m) {
        const float* W = (m==0) ? qw : (m==1) ? kw : (m==2) ? vw : gw;
        __syncthreads();
        // pack W[k][n] -> ws[k/2][n] half2(k even, k odd)
        for (int i = tid; i < 64*32; i += 256) {
            const int k2 = i >> 5, c4 = i & 31;
            float4 va = ((const float4*)(W + (size_t)(2*k2  )*CH))[c4];
            float4 vb = ((const float4*)(W + (size_t)(2*k2+1)*CH))[c4];
            unsigned* d = ws + k2*PADB2 + c4*4;
            d[0] = h2pack(va.x, vb.x);
            d[1] = h2pack(va.y, vb.y);
            d[2] = h2pack(va.z, vb.z);
            d[3] = h2pack(va.w, vb.w);
        }
        __syncthreads();

        float c[2][4][4];
        #pragma unroll
        for (int mi = 0; mi < 2; ++mi)
            #pragma unroll
            for (int ni = 0; ni < 4; ++ni)
                #pragma unroll
                for (int t = 0; t < 4; ++t) c[mi][ni][t] = 0.f;

        #pragma unroll
        for (int t = 0; t < 8; ++t) {
            const int p0 = t * 8;
            unsigned a[2][4];
            #pragma unroll
            for (int mi = 0; mi < 2; ++mi) {
                const int rb = rw0 + mi*16;
                a[mi][0] = xs[(rb+gr  )*PADA2 + p0+gc  ];
                a[mi][1] = xs[(rb+gr+8)*PADA2 + p0+gc  ];
                a[mi][2] = xs[(rb+gr  )*PADA2 + p0+gc+4];
                a[mi][3] = xs[(rb+gr+8)*PADA2 + p0+gc+4];
            }
            unsigned b[4][2];
            #pragma unroll
            for (int ni = 0; ni < 4; ++ni) {
                const int n0 = nw0 + ni*8 + gr;
                b[ni][0] = ws[(p0+gc  )*PADB2 + n0];
                b[ni][1] = ws[(p0+gc+4)*PADB2 + n0];
            }
            #pragma unroll
            for (int mi = 0; mi < 2; ++mi)
                #pragma unroll
                for (int ni = 0; ni < 4; ++ni)
                    mma_f16(c[mi][ni], a[mi], b[ni][0], b[ni][1]);
        }

        __half* outp = (m==0) ? g_q : (m==1) ? g_k : (m==2) ? g_v : g_g;
        #pragma unroll
        for (int mi = 0; mi < 2; ++mi) {
            const int row0 = r0 + rw0 + mi*16 + gr;
            #pragma unroll
            for (int ni = 0; ni < 4; ++ni) {
                const int col = nw0 + ni*8 + gc*2;
                float v0x = c[mi][ni][0], v0y = c[mi][ni][1];
                float v1x = c[mi][ni][2], v1y = c[mi][ni][3];
                if (m == 0) { v0x*=QSCALE; v0y*=QSCALE; v1x*=QSCALE; v1y*=QSCALE; }
                if (m == 3) {
                    const float2 bb = *(const float2*)(gb + col);
                    v0x = 1.f/(1.f + __expf(-(v0x + bb.x)));
                    v0y = 1.f/(1.f + __expf(-(v0y + bb.y)));
                    v1x = 1.f/(1.f + __expf(-(v1x + bb.x)));
                    v1y = 1.f/(1.f + __expf(-(v1y + bb.y)));
                }
                *(unsigned*)(outp + (size_t)row0*CH + col)     = h2pack(v0x, v0y);
                *(unsigned*)(outp + (size_t)(row0+8)*CH + col) = h2pack(v1x, v1y);
            }
        }
    }
}

// ---------------- kernel 2: flash attention, all-fp16 mma --------------------
__global__ __launch_bounds__(256, 3) void attn_mma_kernel(const float* __restrict__ mask)
{
    extern __shared__ unsigned sm_u[];
    unsigned* Kd2 = sm_u;                      // [16 d-pairs][PADK2] half2
    unsigned* Vs  = Kd2 + 16*PADK2;            // [32 d][PADH] half2 (key-pairs)
    float* mrow   = (float*)(Vs + 32*PADH);    // [384]
    const int b = blockIdx.x, h = blockIdx.y;
    const int tid = threadIdx.x, warp = tid >> 5, lane = tid & 31;
    const int gr = lane >> 2, gc = lane & 3;

    // stage K: d-pairs are adjacent halfs in memory -> raw uint4 copy
    for (int i = tid; i < 384*4; i += 256) {
        const int key = i >> 2, q4 = i & 3;
        const unsigned* kb = (const unsigned*)(g_k + ((size_t)(b*NRES)+key)*CH + h*KD);
        uint4 kv = ((const uint4*)kb)[q4];
        Kd2[(q4*4+0)*PADK2 + key] = kv.x;
        Kd2[(q4*4+1)*PADK2 + key] = kv.y;
        Kd2[(q4*4+2)*PADK2 + key] = kv.z;
        Kd2[(q4*4+3)*PADK2 + key] = kv.w;
    }
    // stage V: transpose to key-pair packing via byte permutes.
    for (int i = tid; i < 192*8; i += 256) {
        const int kp = i >> 3, c4 = i & 7;
        const unsigned* v0 = (const unsigned*)(g_v + ((size_t)(b*NRES)+2*kp)*CH + h*KD);
        const unsigned* v1 = (const unsigned*)(g_v + ((size_t)(b*NRES)+2*kp+1)*CH + h*KD);
        uint2 a  = ((const uint2*)v0)[c4];
        uint2 bb = ((const uint2*)v1)[c4];
        Vs[(4*c4+0)*PADH + kp] = __byte_perm(a.x, bb.x, 0x5410);
        Vs[(4*c4+1)*PADH + kp] = __byte_perm(a.x, bb.x, 0x7632);
        Vs[(4*c4+2)*PADH + kp] = __byte_perm(a.y, bb.y, 0x5410);
        Vs[(4*c4+3)*PADH + kp] = __byte_perm(a.y, bb.y, 0x7632);
    }
    for (int i = tid; i < NRES; i += 256)
        mrow[i] = 1e9f * (mask[(size_t)b*NRES + i] - 1.f);
    __syncthreads();

    for (int p = 0; p < 3; ++p) {
        const int q0 = p*128 + warp*16;
        // Q fp16 A-frags: raw 32-bit loads (d-pairs adjacent)
        unsigned qa[2][4];
        const unsigned* qlo = (const unsigned*)(g_q + ((size_t)(b*NRES)+q0+gr)*CH + h*KD);
        const unsigned* qhi = (const unsigned*)(g_q + ((size_t)(b*NRES)+q0+gr+8)*CH + h*KD);
        #pragma unroll
        for (int kc = 0; kc < 2; ++kc) {
            qa[kc][0] = qlo[kc*8 + gc];
            qa[kc][1] = qhi[kc*8 + gc];
            qa[kc][2] = qlo[kc*8 + gc + 4];
            qa[kc][3] = qhi[kc*8 + gc + 4];
        }
        const float* nb0 = g_nb + (size_t)h*NNPIX + (size_t)(q0+gr)*NRES;
        const float* nb1 = nb0 + (size_t)8*NRES;

        float m0 = -1e30f, m1 = -1e30f, sum0 = 0.f, sum1 = 0.f;
        float O[4][4];
        #pragma unroll
        for (int vt = 0; vt < 4; ++vt)
            #pragma unroll
            for (int t = 0; t < 4; ++t) O[vt][t] = 0.f;

        for (int c = 0; c < 6; ++c) {
            const int c0 = c*64;
            float s[8][4];
            #pragma unroll
            for (int t = 0; t < 8; ++t)
                #pragma unroll
                for (int j = 0; j < 4; ++j) s[t][j] = 0.f;

            #pragma unroll
            for (int t = 0; t < 8; ++t) {
                const int n0 = c0 + t*8 + gr;
                #pragma unroll
                for (int kc = 0; kc < 2; ++kc) {
                    mma_f16(s[t], qa[kc],
                            Kd2[(kc*8+gc  )*PADK2 + n0],
                            Kd2[(kc*8+gc+4)*PADK2 + n0]);
                }
            }
            // bias + chunk row-max
            float mc0 = -1e30f, mc1 = -1e30f;
            #pragma unroll
            for (int t = 0; t < 8; ++t) {
                const int col = c0 + t*8 + gc*2;
                const float2 mr  = *(const float2*)(mrow + col);
                const float2 nlo = *(const float2*)(nb0 + col);
                const float2 nhi = *(const float2*)(nb1 + col);
                s[t][0] += mr.x + nlo.x; s[t][1] += mr.y + nlo.y;
                s[t][2] += mr.x + nhi.x; s[t][3] += mr.y + nhi.y;
                mc0 = fmaxf(mc0, fmaxf(s[t][0], s[t][1]));
                mc1 = fmaxf(mc1, fmaxf(s[t][2], s[t][3]));
            }
            mc0 = fmaxf(mc0, __shfl_xor_sync(0xffffffffu, mc0, 1));
            mc0 = fmaxf(mc0, __shfl_xor_sync(0xffffffffu, mc0, 2));
            mc1 = fmaxf(mc1, __shfl_xor_sync(0xffffffffu, mc1, 1));
            mc1 = fmaxf(mc1, __shfl_xor_sync(0xffffffffu, mc1, 2));
            const float mn0 = fmaxf(m0, mc0), mn1 = fmaxf(m1, mc1);
            const float al0 = __expf(m0 - mn0), al1 = __expf(m1 - mn1);
            m0 = mn0; m1 = mn1;
            sum0 *= al0; sum1 *= al1;
            #pragma unroll
            for (int vt = 0; vt < 4; ++vt) {
                O[vt][0] *= al0; O[vt][1] *= al0;
                O[vt][2] *= al1; O[vt][3] *= al1;
            }
            float cs0 = 0.f, cs1 = 0.f;
            #pragma unroll
            for (int t = 0; t < 8; ++t) {
                s[t][0] = __expf(s[t][0] - mn0);
                s[t][1] = __expf(s[t][1] - mn0);
                s[t][2] = __expf(s[t][2] - mn1);
                s[t][3] = __expf(s[t][3] - mn1);
                cs0 += s[t][0] + s[t][1];
                cs1 += s[t][2] + s[t][3];
            }
            cs0 += __shfl_xor_sync(0xffffffffu, cs0, 1);
            cs0 += __shfl_xor_sync(0xffffffffu, cs0, 2);
            cs1 += __shfl_xor_sync(0xffffffffu, cs1, 1);
            cs1 += __shfl_xor_sync(0xffffffffu, cs1, 2);
            sum0 += cs0; sum1 += cs1;

            // PV: P C-frags pack directly into fp16 A-frags
            #pragma unroll
            for (int kc16 = 0; kc16 < 4; ++kc16) {
                const int e = 2*kc16, o = e+1;
                unsigned pa[4];
                pa[0] = h2pack(s[e][0], s[e][1]);
                pa[1] = h2pack(s[e][2], s[e][3]);
                pa[2] = h2pack(s[o][0], s[o][1]);
                pa[3] = h2pack(s[o][2], s[o][3]);
                const int kpb = (c0 >> 1) + kc16*8;
                #pragma unroll
                for (int vt = 0; vt < 4; ++vt) {
                    const unsigned* vrow = Vs + (vt*8+gr)*PADH + kpb;
                    mma_f16(O[vt], pa, vrow[gc], vrow[gc+4]);
                }
            }
        }

        const float inv0 = 1.f / sum0, inv1 = 1.f / sum1;
        const size_t orow0 = ((size_t)(b*NRES)+q0+gr)*CH + h*KD;
        const size_t orow1 = orow0 + (size_t)8*CH;
        #pragma unroll
        for (int vt = 0; vt < 4; ++vt) {
            const int cl = vt*8 + gc*2;
            const float2 g0 = h2unpack(*(const unsigned*)(g_g + orow0 + cl));
            const float2 g1 = h2unpack(*(const unsigned*)(g_g + orow1 + cl));
            *(unsigned*)(g_att + orow0 + cl) =
                h2pack(O[vt][0]*inv0*g0.x, O[vt][1]*inv0*g0.y);
            *(unsigned*)(g_att + orow1 + cl) =
                h2pack(O[vt][2]*inv1*g1.x, O[vt][3]*inv1*g1.y);
        }
    }
}

// ---------------- kernel 3: output projection (fp16 mma) ---------------------
__global__ __launch_bounds__(256, 3) void out_mma_kernel(
    const float* __restrict__ ow, const float* __restrict__ ob,
    float* __restrict__ out)
{
    extern __shared__ unsigned smu[];
    unsigned* xs = smu;               // [64][PADA2]
    unsigned* ws = smu + 64*PADA2;    // [64][PADB2]
    const int tid = threadIdx.x;
    const int warp = tid >> 5, lane = tid & 31;
    const int gr = lane >> 2, gc = lane & 3;
    const int mw = warp & 1, nw = warp >> 1;
    const int rw0 = mw * 32, nw0 = nw * 32;
    const int r0 = blockIdx.x * 64;

    // X staging: raw copy of fp16 g_att. One row = 128 halfs = 16 uint4.
    for (int i = tid; i < 64*16; i += 256) {
        const int r = i >> 4, c4 = i & 15;
        uint4 v = ((const uint4*)(g_att + (size_t)(r0 + r)*CH))[c4];
        unsigned* d = xs + r*PADA2 + c4*4;
        d[0]=v.x; d[1]=v.y; d[2]=v.z; d[3]=v.w;
    }
    for (int i = tid; i < 64*32; i += 256) {
        const int k2 = i >> 5, c4 = i & 31;
        float4 va = ((const float4*)(ow + (size_t)(2*k2  )*CH))[c4];
        float4 vb = ((const float4*)(ow + (size_t)(2*k2+1)*CH))[c4];
        unsigned* d = ws + k2*PADB2 + c4*4;
        d[0] = h2pack(va.x, vb.x);
        d[1] = h2pack(va.y, vb.y);
        d[2] = h2pack(va.z, vb.z);
        d[3] = h2pack(va.w, vb.w);
    }
    __syncthreads();

    float c[2][4][4];
    #pragma unroll
    for (int mi = 0; mi < 2; ++mi)
        #pragma unroll
        for (int ni = 0; ni < 4; ++ni)
            #pragma unroll
            for (int t = 0; t < 4; ++t) c[mi][ni][t] = 0.f;

    #pragma unroll
    for (int t = 0; t < 8; ++t) {
        const int p0 = t * 8;
        unsigned a[2][4];
        #pragma unroll
        for (int mi = 0; mi < 2; ++mi) {
            const int rb = rw0 + mi*16;
            a[mi][0] = xs[(rb+gr  )*PADA2 + p0+gc  ];
            a[mi][1] = xs[(rb+gr+8)*PADA2 + p0+gc  ];
            a[mi][2] = xs[(rb+gr  )*PADA2 + p0+gc+4];
            a[mi][3] = xs[(rb+gr+8)*PADA2 + p0+gc+4];
        }
        unsigned b[4][2];
        #pragma unroll
        for (int ni = 0; ni < 4; ++ni) {
            const int n0 = nw0 + ni*8 + gr;
            b[ni][0] = ws[(p0+gc  )*PADB2 + n0];
            b[ni][1] = ws[(p0+gc+4)*PADB2 + n0];
        }
        #pragma unroll
        for (int mi = 0; mi < 2; ++mi)
            #pragma unroll
            for (int ni = 0; ni < 4; ++ni)
                mma_f16(c[mi][ni], a[mi], b[ni][0], b[ni][1]);
    }

    #pragma unroll
    for (int mi = 0; mi < 2; ++mi) {
        const int row0 = r0 + rw0 + mi*16 + gr;
        #pragma unroll
        for (int ni = 0; ni < 4; ++ni) {
            const int col = nw0 + ni*8 + gc*2;
            const float2 bb = *(const float2*)(ob + col);
            *(float2*)(out + (size_t)row0*CH + col) =
                make_float2(c[mi][ni][0] + bb.x, c[mi][ni][1] + bb.y);
            *(float2*)(out + (size_t)(row0+8)*CH + col) =
                make_float2(c[mi][ni][2] + bb.x, c[mi][ni][3] + bb.y);
        }
    }
}

// ---------------- launcher ---------------------------------------------------
extern "C" void kernel_launch(void* const* d_in, const int* in_sizes, int n_in,
                              void* d_out, int out_size)
{
    const float* pact = (const float*)d_in[0];
    const float* mask = (const float*)d_in[1];
    const float* lns  = (const float*)d_in[2];
    const float* lnb  = (const float*)d_in[3];
    const float* f2w  = (const float*)d_in[4];
    const float* qw   = (const float*)d_in[5];
    const float* kw   = (const float*)d_in[6];
    const float* vw   = (const float*)d_in[7];
    const float* gw   = (const float*)d_in[8];
    const float* gb   = (const float*)d_in[9];
    const float* ow   = (const float*)d_in[10];
    const float* ob   = (const float*)d_in[11];
    float* out = (float*)d_out;

    const int GEMM_SMEM = (64*PADA2 + 64*PADB2) * 4;              // 52224
    const int ATTN_SMEM = (16*PADK2 + 32*PADH + NRES) * 4;        // 51712

    cudaFuncSetAttribute(lnproj_mma_kernel, cudaFuncAttributeMaxDynamicSharedMemorySize, GEMM_SMEM);
    cudaFuncSetAttribute(out_mma_kernel,    cudaFuncAttributeMaxDynamicSharedMemorySize, GEMM_SMEM);
    cudaFuncSetAttribute(attn_mma_kernel,   cudaFuncAttributeMaxDynamicSharedMemorySize, ATTN_SMEM);

    lnproj_mma_kernel<<<NNPIX/64, 256, GEMM_SMEM>>>(pact, lns, lnb, f2w, qw, kw, vw, gw, gb);
    attn_mma_kernel<<<dim3(NRES, NH), 256, ATTN_SMEM>>>(mask);
    out_mma_kernel<<<NNPIX/64, 256, GEMM_SMEM>>>(ow, ob, out);
}

// round 11
// speedup vs baseline: 9.1417x; 1.0919x over previous
#include <cuda_runtime.h>
#include <cuda_fp16.h>
#include <math.h>

#define NRES 384
#define NNPIX (NRES*NRES)          // 147456
#define CH 128
#define NH 4
#define KD 32
#define QSCALE 0.17677669529663689f  // 1/sqrt(32)

#define PADA2 68   // X half2 pad: A-frag bank = 4*gr+gc -> conflict-free
#define PADB2 136  // W half2 pad: B-frag bank = 8*gc+gr -> conflict-free
#define PADK2 392  // K half2 pad: B-frag bank = 8*gc+gr -> conflict-free
#define PADH 196   // V half2 pad (key pairs): bank = 4*gr+gc -> conflict-free

// ---------------- scratch (fp16 intermediates) --------------------------------
__device__ __align__(16) __half  g_nb [(size_t)NH*NNPIX];
__device__ __align__(16) __half  g_q  [(size_t)NNPIX*CH];
__device__ __align__(16) __half  g_k  [(size_t)NNPIX*CH];
__device__ __align__(16) __half  g_v  [(size_t)NNPIX*CH];
__device__ __align__(16) __half  g_g  [(size_t)NNPIX*CH];
__device__ __align__(16) __half  g_att[(size_t)NNPIX*CH];
__device__ __align__(16) unsigned g_wh[5*64*128];   // 5 weight mats, packed half2 [k2][n]

// ---------------- helpers -----------------------------------------------------
__device__ __forceinline__ unsigned h2pack(float lo, float hi) {
    unsigned u;
    asm("cvt.rn.f16x2.f32 %0, %1, %2;" : "=r"(u) : "f"(hi), "f"(lo));
    return u;
}
__device__ __forceinline__ float2 h2unpack(unsigned u) {
    __half2 h = *(__half2*)&u;
    return __half22float2(h);
}
__device__ __forceinline__ void mma_f16(float c[4], const unsigned a[4], unsigned b0, unsigned b1) {
    asm volatile(
        "mma.sync.aligned.m16n8k16.row.col.f32.f16.f16.f32 "
        "{%0,%1,%2,%3}, {%4,%5,%6,%7}, {%8,%9}, {%0,%1,%2,%3};"
        : "+f"(c[0]), "+f"(c[1]), "+f"(c[2]), "+f"(c[3])
        : "r"(a[0]), "r"(a[1]), "r"(a[2]), "r"(a[3]), "r"(b0), "r"(b1));
}

// ---------------- kernel 0: pack the five weight matrices to half2 ------------
__global__ __launch_bounds__(256) void wpack_kernel(
    const float* __restrict__ qw, const float* __restrict__ kw,
    const float* __restrict__ vw, const float* __restrict__ gw,
    const float* __restrict__ ow)
{
    const int i = blockIdx.x * 256 + threadIdx.x;     // [0, 5*8192)
    const int m = i >> 13;
    const int r = i & 8191;
    const int k2 = r >> 7, n = r & 127;
    const float* W = (m==0) ? qw : (m==1) ? kw : (m==2) ? vw : (m==3) ? gw : ow;
    g_wh[i] = h2pack(W[(2*k2)*CH + n], W[(2*k2+1)*CH + n]);
}

// ---------------- kernel 1: fused LN + nb-bias + q/k/v/gate (fp16 mma) -------
__global__ __launch_bounds__(256, 3) void lnproj_mma_kernel(
    const float* __restrict__ pact, const float* __restrict__ lns,
    const float* __restrict__ lnb, const float* __restrict__ f2w,
    const float* __restrict__ gb)
{
    extern __shared__ unsigned smu[];
    unsigned* xs = smu;               // [64 rows][PADA2] half2 (k-pairs)
    unsigned* ws = smu + 64*PADA2;    // [64 k-pairs][PADB2] half2
    const int tid = threadIdx.x;
    const int warp = tid >> 5, lane = tid & 31;
    const int gr = lane >> 2, gc = lane & 3;
    const int mw = warp & 1, nw = warp >> 1;
    const int rw0 = mw * 32, nw0 = nw * 32;
    const int r0 = blockIdx.x * 64;

    // ---- stage 1: per-row LayerNorm + nb bias; write half2 X tile -----------
    {
        const float4 sc = ((const float4*)lns)[lane];
        const float4 bi = ((const float4*)lnb)[lane];
        const float4* w4 = (const float4*)f2w;
        const float4 w0 = w4[lane*4+0], w1 = w4[lane*4+1],
                     w2 = w4[lane*4+2], w3 = w4[lane*4+3];
        #pragma unroll 2
        for (int k = 0; k < 8; ++k) {
            const int r = k*8 + warp;
            const size_t p = (size_t)(r0 + r);
            float4 v = ((const float4*)(pact + p*CH))[lane];
            float s = v.x + v.y + v.z + v.w;
            #pragma unroll
            for (int o = 16; o; o >>= 1) s += __shfl_xor_sync(0xffffffffu, s, o);
            const float mu = s * (1.0f/CH);
            const float dx = v.x-mu, dy = v.y-mu, dz = v.z-mu, dw = v.w-mu;
            float ss = dx*dx + dy*dy + dz*dz + dw*dw;
            #pragma unroll
            for (int o = 16; o; o >>= 1) ss += __shfl_xor_sync(0xffffffffu, ss, o);
            const float inv = rsqrtf(ss * (1.0f/CH) + 1e-5f);
            float4 xn;
            xn.x = dx*inv*sc.x + bi.x;
            xn.y = dy*inv*sc.y + bi.y;
            xn.z = dz*inv*sc.z + bi.z;
            xn.w = dw*inv*sc.w + bi.w;
            *(uint2*)(xs + r*PADA2 + lane*2) =
                make_uint2(h2pack(xn.x, xn.y), h2pack(xn.z, xn.w));

            float n0 = xn.x*w0.x + xn.y*w1.x + xn.z*w2.x + xn.w*w3.x;
            float n1 = xn.x*w0.y + xn.y*w1.y + xn.z*w2.y + xn.w*w3.y;
            float n2 = xn.x*w0.z + xn.y*w1.z + xn.z*w2.z + xn.w*w3.z;
            float n3 = xn.x*w0.w + xn.y*w1.w + xn.z*w2.w + xn.w*w3.w;
            #pragma unroll
            for (int o = 16; o; o >>= 1) {
                n0 += __shfl_xor_sync(0xffffffffu, n0, o);
                n1 += __shfl_xor_sync(0xffffffffu, n1, o);
                n2 += __shfl_xor_sync(0xffffffffu, n2, o);
                n3 += __shfl_xor_sync(0xffffffffu, n3, o);
            }
            if (lane == 0) {
                g_nb[0*(size_t)NNPIX + p] = __float2half(n0);
                g_nb[1*(size_t)NNPIX + p] = __float2half(n1);
                g_nb[2*(size_t)NNPIX + p] = __float2half(n2);
                g_nb[3*(size_t)NNPIX + p] = __float2half(n3);
            }
        }
    }

    // ---- stage 2: four W passes (W pre-packed fp16; raw copy) ---------------
    // tile = 64 k2-rows x 128 n-words = 2048 uint4 -> 64*32 iterations
    for (int m = 0; m < 4; ++m) {
        const unsigned* Wh = g_wh + m*8192;
        __syncthreads();
        for (int i = tid; i < 64*32; i += 256) {
            const int k2 = i >> 5, c4 = i & 31;
            uint4 v = ((const uint4*)(Wh + k2*128))[c4];
            unsigned* d = ws + k2*PADB2 + c4*4;
            d[0]=v.x; d[1]=v.y; d[2]=v.z; d[3]=v.w;
        }
        __syncthreads();

        float c[2][4][4];
        #pragma unroll
        for (int mi = 0; mi < 2; ++mi)
            #pragma unroll
            for (int ni = 0; ni < 4; ++ni)
                #pragma unroll
                for (int t = 0; t < 4; ++t) c[mi][ni][t] = 0.f;

        #pragma unroll
        for (int t = 0; t < 8; ++t) {
            const int p0 = t * 8;
            unsigned a[2][4];
            #pragma unroll
            for (int mi = 0; mi < 2; ++mi) {
                const int rb = rw0 + mi*16;
                a[mi][0] = xs[(rb+gr  )*PADA2 + p0+gc  ];
                a[mi][1] = xs[(rb+gr+8)*PADA2 + p0+gc  ];
                a[mi][2] = xs[(rb+gr  )*PADA2 + p0+gc+4];
                a[mi][3] = xs[(rb+gr+8)*PADA2 + p0+gc+4];
            }
            unsigned b[4][2];
            #pragma unroll
            for (int ni = 0; ni < 4; ++ni) {
                const int n0 = nw0 + ni*8 + gr;
                b[ni][0] = ws[(p0+gc  )*PADB2 + n0];
                b[ni][1] = ws[(p0+gc+4)*PADB2 + n0];
            }
            #pragma unroll
            for (int mi = 0; mi < 2; ++mi)
                #pragma unroll
                for (int ni = 0; ni < 4; ++ni)
                    mma_f16(c[mi][ni], a[mi], b[ni][0], b[ni][1]);
        }

        __half* outp = (m==0) ? g_q : (m==1) ? g_k : (m==2) ? g_v : g_g;
        #pragma unroll
        for (int mi = 0; mi < 2; ++mi) {
            const int row0 = r0 + rw0 + mi*16 + gr;
            #pragma unroll
            for (int ni = 0; ni < 4; ++ni) {
                const int col = nw0 + ni*8 + gc*2;
                float v0x = c[mi][ni][0], v0y = c[mi][ni][1];
                float v1x = c[mi][ni][2], v1y = c[mi][ni][3];
                if (m == 0) { v0x*=QSCALE; v0y*=QSCALE; v1x*=QSCALE; v1y*=QSCALE; }
                if (m == 3) {
                    const float2 bb = *(const float2*)(gb + col);
                    v0x = 1.f/(1.f + __expf(-(v0x + bb.x)));
                    v0y = 1.f/(1.f + __expf(-(v0y + bb.y)));
                    v1x = 1.f/(1.f + __expf(-(v1x + bb.x)));
                    v1y = 1.f/(1.f + __expf(-(v1y + bb.y)));
                }
                *(unsigned*)(outp + (size_t)row0*CH + col)     = h2pack(v0x, v0y);
                *(unsigned*)(outp + (size_t)(row0+8)*CH + col) = h2pack(v1x, v1y);
            }
        }
    }
}

// ---------------- kernel 2: flash attention, all-fp16 mma, max-free softmax --
__global__ __launch_bounds__(256, 3) void attn_mma_kernel(const float* __restrict__ mask)
{
    extern __shared__ unsigned sm_u[];
    unsigned* Kd2 = sm_u;                      // [16 d-pairs][PADK2] half2
    unsigned* Vs  = Kd2 + 16*PADK2;            // [32 d][PADH] half2 (key-pairs)
    float* mrow   = (float*)(Vs + 32*PADH);    // [384]
    const int b = blockIdx.x, h = blockIdx.y;
    const int tid = threadIdx.x, warp = tid >> 5, lane = tid & 31;
    const int gr = lane >> 2, gc = lane & 3;

    // stage K: d-pairs are adjacent halfs in memory -> raw uint4 copy
    for (int i = tid; i < 384*4; i += 256) {
        const int key = i >> 2, q4 = i & 3;
        const unsigned* kb = (const unsigned*)(g_k + ((size_t)(b*NRES)+key)*CH + h*KD);
        uint4 kv = ((const uint4*)kb)[q4];
        Kd2[(q4*4+0)*PADK2 + key] = kv.x;
        Kd2[(q4*4+1)*PADK2 + key] = kv.y;
        Kd2[(q4*4+2)*PADK2 + key] = kv.z;
        Kd2[(q4*4+3)*PADK2 + key] = kv.w;
    }
    // stage V: transpose to key-pair packing via byte permutes.
    for (int i = tid; i < 192*8; i += 256) {
        const int kp = i >> 3, c4 = i & 7;
        const unsigned* v0 = (const unsigned*)(g_v + ((size_t)(b*NRES)+2*kp)*CH + h*KD);
        const unsigned* v1 = (const unsigned*)(g_v + ((size_t)(b*NRES)+2*kp+1)*CH + h*KD);
        uint2 a  = ((const uint2*)v0)[c4];
        uint2 bb = ((const uint2*)v1)[c4];
        Vs[(4*c4+0)*PADH + kp] = __byte_perm(a.x, bb.x, 0x5410);
        Vs[(4*c4+1)*PADH + kp] = __byte_perm(a.x, bb.x, 0x7632);
        Vs[(4*c4+2)*PADH + kp] = __byte_perm(a.y, bb.y, 0x5410);
        Vs[(4*c4+3)*PADH + kp] = __byte_perm(a.y, bb.y, 0x7632);
    }
    for (int i = tid; i < NRES; i += 256)
        mrow[i] = 1e9f * (mask[(size_t)b*NRES + i] - 1.f);
    __syncthreads();

    for (int p = 0; p < 3; ++p) {
        const int q0 = p*128 + warp*16;
        // Q fp16 A-frags: raw 32-bit loads (d-pairs adjacent)
        unsigned qa[2][4];
        const unsigned* qlo = (const unsigned*)(g_q + ((size_t)(b*NRES)+q0+gr)*CH + h*KD);
        const unsigned* qhi = (const unsigned*)(g_q + ((size_t)(b*NRES)+q0+gr+8)*CH + h*KD);
        #pragma unroll
        for (int kc = 0; kc < 2; ++kc) {
            qa[kc][0] = qlo[kc*8 + gc];
            qa[kc][1] = qhi[kc*8 + gc];
            qa[kc][2] = qlo[kc*8 + gc + 4];
            qa[kc][3] = qhi[kc*8 + gc + 4];
        }
        const __half* nb0 = g_nb + (size_t)h*NNPIX + (size_t)(q0+gr)*NRES;
        const __half* nb1 = nb0 + (size_t)8*NRES;

        float sum0 = 0.f, sum1 = 0.f;
        float O[4][4];
        #pragma unroll
        for (int vt = 0; vt < 4; ++vt)
            #pragma unroll
            for (int t = 0; t < 4; ++t) O[vt][t] = 0.f;

        for (int c = 0; c < 6; ++c) {
            const int c0 = c*64;
            float s[8][4];
            #pragma unroll
            for (int t = 0; t < 8; ++t)
                #pragma unroll
                for (int j = 0; j < 4; ++j) s[t][j] = 0.f;

            #pragma unroll
            for (int t = 0; t < 8; ++t) {
                const int n0 = c0 + t*8 + gr;
                #pragma unroll
                for (int kc = 0; kc < 2; ++kc) {
                    mma_f16(s[t], qa[kc],
                            Kd2[(kc*8+gc  )*PADK2 + n0],
                            Kd2[(kc*8+gc+4)*PADK2 + n0]);
                }
            }
            // bias + direct exp (logits are small; softmax shift-invariant)
            #pragma unroll
            for (int t = 0; t < 8; ++t) {
                const int col = c0 + t*8 + gc*2;
                const float2 mr  = *(const float2*)(mrow + col);
                const float2 nlo = h2unpack(*(const unsigned*)(nb0 + col));
                const float2 nhi = h2unpack(*(const unsigned*)(nb1 + col));
                s[t][0] = __expf(s[t][0] + mr.x + nlo.x);
                s[t][1] = __expf(s[t][1] + mr.y + nlo.y);
                s[t][2] = __expf(s[t][2] + mr.x + nhi.x);
                s[t][3] = __expf(s[t][3] + mr.y + nhi.y);
                sum0 += s[t][0] + s[t][1];
                sum1 += s[t][2] + s[t][3];
            }

            // PV: P C-frags pack directly into fp16 A-frags
            #pragma unroll
            for (int kc16 = 0; kc16 < 4; ++kc16) {
                const int e = 2*kc16, o = e+1;
                unsigned pa[4];
                pa[0] = h2pack(s[e][0], s[e][1]);
                pa[1] = h2pack(s[e][2], s[e][3]);
                pa[2] = h2pack(s[o][0], s[o][1]);
                pa[3] = h2pack(s[o][2], s[o][3]);
                const int kpb = (c0 >> 1) + kc16*8;
                #pragma unroll
                for (int vt = 0; vt < 4; ++vt) {
                    const unsigned* vrow = Vs + (vt*8+gr)*PADH + kpb;
                    mma_f16(O[vt], pa, vrow[gc], vrow[gc+4]);
                }
            }
        }

        // deferred sum reduction across the quad
        sum0 += __shfl_xor_sync(0xffffffffu, sum0, 1);
        sum0 += __shfl_xor_sync(0xffffffffu, sum0, 2);
        sum1 += __shfl_xor_sync(0xffffffffu, sum1, 1);
        sum1 += __shfl_xor_sync(0xffffffffu, sum1, 2);
        const float inv0 = 1.f / sum0, inv1 = 1.f / sum1;

        const size_t orow0 = ((size_t)(b*NRES)+q0+gr)*CH + h*KD;
        const size_t orow1 = orow0 + (size_t)8*CH;
        #pragma unroll
        for (int vt = 0; vt < 4; ++vt) {
            const int cl = vt*8 + gc*2;
            const float2 g0 = h2unpack(*(const unsigned*)(g_g + orow0 + cl));
            const float2 g1 = h2unpack(*(const unsigned*)(g_g + orow1 + cl));
            *(unsigned*)(g_att + orow0 + cl) =
                h2pack(O[vt][0]*inv0*g0.x, O[vt][1]*inv0*g0.y);
            *(unsigned*)(g_att + orow1 + cl) =
                h2pack(O[vt][2]*inv1*g1.x, O[vt][3]*inv1*g1.y);
        }
    }
}

// ---------------- kernel 3: output projection (fp16 mma) ---------------------
__global__ __launch_bounds__(256, 3) void out_mma_kernel(
    const float* __restrict__ ob, float* __restrict__ out)
{
    extern __shared__ unsigned smu[];
    unsigned* xs = smu;               // [64][PADA2]
    unsigned* ws = smu + 64*PADA2;    // [64][PADB2]
    const int tid = threadIdx.x;
    const int warp = tid >> 5, lane = tid & 31;
    const int gr = lane >> 2, gc = lane & 3;
    const int mw = warp & 1, nw = warp >> 1;
    const int rw0 = mw * 32, nw0 = nw * 32;
    const int r0 = blockIdx.x * 64;

    // X staging: raw copy of fp16 g_att. One row = 128 halfs = 16 uint4.
    for (int i = tid; i < 64*16; i += 256) {
        const int r = i >> 4, c4 = i & 15;
        uint4 v = ((const uint4*)(g_att + (size_t)(r0 + r)*CH))[c4];
        unsigned* d = xs + r*PADA2 + c4*4;
        d[0]=v.x; d[1]=v.y; d[2]=v.z; d[3]=v.w;
    }
    // W staging: 64 k2-rows x 128 n-words = 2048 uint4 -> 64*32 iterations
    {
        const unsigned* Wh = g_wh + 4*8192;
        for (int i = tid; i < 64*32; i += 256) {
            const int k2 = i >> 5, c4 = i & 31;
            uint4 v = ((const uint4*)(Wh + k2*128))[c4];
            unsigned* d = ws + k2*PADB2 + c4*4;
            d[0]=v.x; d[1]=v.y; d[2]=v.z; d[3]=v.w;
        }
    }
    __syncthreads();

    float c[2][4][4];
    #pragma unroll
    for (int mi = 0; mi < 2; ++mi)
        #pragma unroll
        for (int ni = 0; ni < 4; ++ni)
            #pragma unroll
            for (int t = 0; t < 4; ++t) c[mi][ni][t] = 0.f;

    #pragma unroll
    for (int t = 0; t < 8; ++t) {
        const int p0 = t * 8;
        unsigned a[2][4];
        #pragma unroll
        for (int mi = 0; mi < 2; ++mi) {
            const int rb = rw0 + mi*16;
            a[mi][0] = xs[(rb+gr  )*PADA2 + p0+gc  ];
            a[mi][1] = xs[(rb+gr+8)*PADA2 + p0+gc  ];
            a[mi][2] = xs[(rb+gr  )*PADA2 + p0+gc+4];
            a[mi][3] = xs[(rb+gr+8)*PADA2 + p0+gc+4];
        }
        unsigned b[4][2];
        #pragma unroll
        for (int ni = 0; ni < 4; ++ni) {
            const int n0 = nw0 + ni*8 + gr;
            b[ni][0] = ws[(p0+gc  )*PADB2 + n0];
            b[ni][1] = ws[(p0+gc+4)*PADB2 + n0];
        }
        #pragma unroll
        for (int mi = 0; mi < 2; ++mi)
            #pragma unroll
            for (int ni = 0; ni < 4; ++ni)
                mma_f16(c[mi][ni], a[mi], b[ni][0], b[ni][1]);
    }

    #pragma unroll
    for (int mi = 0; mi < 2; ++mi) {
        const int row0 = r0 + rw0 + mi*16 + gr;
        #pragma unroll
        for (int ni = 0; ni < 4; ++ni) {
            const int col = nw0 + ni*8 + gc*2;
            const float2 bb = *(const float2*)(ob + col);
            *(float2*)(out + (size_t)row0*CH + col) =
                make_float2(c[mi][ni][0] + bb.x, c[mi][ni][1] + bb.y);
            *(float2*)(out + (size_t)(row0+8)*CH + col) =
                make_float2(c[mi][ni][2] + bb.x, c[mi][ni][3] + bb.y);
        }
    }
}

// ---------------- launcher ---------------------------------------------------
extern "C" void kernel_launch(void* const* d_in, const int* in_sizes, int n_in,
                              void* d_out, int out_size)
{
    const float* pact = (const float*)d_in[0];
    const float* mask = (const float*)d_in[1];
    const float* lns  = (const float*)d_in[2];
    const float* lnb  = (const float*)d_in[3];
    const float* f2w  = (const float*)d_in[4];
    const float* qw   = (const float*)d_in[5];
    const float* kw   = (const float*)d_in[6];
    const float* vw   = (const float*)d_in[7];
    const float* gw   = (const float*)d_in[8];
    const float* gb   = (const float*)d_in[9];
    const float* ow   = (const float*)d_in[10];
    const float* ob   = (const float*)d_in[11];
    float* out = (float*)d_out;

    const int GEMM_SMEM = (64*PADA2 + 64*PADB2) * 4;              // 52224
    const int ATTN_SMEM = (16*PADK2 + 32*PADH + NRES) * 4;        // 51712

    cudaFuncSetAttribute(lnproj_mma_kernel, cudaFuncAttributeMaxDynamicSharedMemorySize, GEMM_SMEM);
    cudaFuncSetAttribute(out_mma_kernel,    cudaFuncAttributeMaxDynamicSharedMemorySize, GEMM_SMEM);
    cudaFuncSetAttribute(attn_mma_kernel,   cudaFuncAttributeMaxDynamicSharedMemorySize, ATTN_SMEM);

    wpack_kernel<<<160, 256>>>(qw, kw, vw, gw, ow);
    lnproj_mma_kernel<<<NNPIX/64, 256, GEMM_SMEM>>>(pact, lns, lnb, f2w, gb);
    attn_mma_kernel<<<dim3(NRES, NH), 256, ATTN_SMEM>>>(mask);
    out_mma_kernel<<<NNPIX/64, 256, GEMM_SMEM>>>(ob, out);
}

// round 12
// speedup vs baseline: 9.1548x; 1.0014x over previous
#include <cuda_runtime.h>
#include <cuda_fp16.h>
#include <math.h>

#define NRES 384
#define NNPIX (NRES*NRES)          // 147456
#define CH 128
#define NH 4
#define KD 32
#define QSCALE 0.17677669529663689f  // 1/sqrt(32)
#define LOG2E 1.4426950408889634f

#define PADA2 68   // X half2 pad (words/row). rows offset 4 banks -> LDSM conflict-free
#define PADW  68   // W^T half2 pad (words/row), same property
#define PADK2 392  // K half2 pad: B-frag bank = 8*gc+gr -> conflict-free
#define PADH 196   // V half2 pad (key pairs): bank = 4*gr+gc -> conflict-free

// ---------------- scratch (fp16 intermediates) --------------------------------
__device__ __align__(16) __half  g_nb [(size_t)NH*NNPIX];
__device__ __align__(16) __half  g_q  [(size_t)NNPIX*CH];
__device__ __align__(16) __half  g_k  [(size_t)NNPIX*CH];
__device__ __align__(16) __half  g_v  [(size_t)NNPIX*CH];
__device__ __align__(16) __half  g_g  [(size_t)NNPIX*CH];
__device__ __align__(16) __half  g_att[(size_t)NNPIX*CH];
__device__ __align__(16) unsigned g_wt[5*128*64];   // 5 weight mats TRANSPOSED [n][k2] half2

// ---------------- helpers -----------------------------------------------------
__device__ __forceinline__ unsigned h2pack(float lo, float hi) {
    unsigned u;
    asm("cvt.rn.f16x2.f32 %0, %1, %2;" : "=r"(u) : "f"(hi), "f"(lo));
    return u;
}
__device__ __forceinline__ float2 h2unpack(unsigned u) {
    __half2 h = *(__half2*)&u;
    return __half22float2(h);
}
__device__ __forceinline__ float ex2(float x) {
    float y;
    asm("ex2.approx.ftz.f32 %0, %1;" : "=f"(y) : "f"(x));
    return y;
}
__device__ __forceinline__ void mma_f16(float c[4], const unsigned a[4], unsigned b0, unsigned b1) {
    asm volatile(
        "mma.sync.aligned.m16n8k16.row.col.f32.f16.f16.f32 "
        "{%0,%1,%2,%3}, {%4,%5,%6,%7}, {%8,%9}, {%0,%1,%2,%3};"
        : "+f"(c[0]), "+f"(c[1]), "+f"(c[2]), "+f"(c[3])
        : "r"(a[0]), "r"(a[1]), "r"(a[2]), "r"(a[3]), "r"(b0), "r"(b1));
}
__device__ __forceinline__ void ldsm_x4(unsigned r[4], unsigned addr) {
    asm volatile("ldmatrix.sync.aligned.m8n8.x4.shared.b16 {%0,%1,%2,%3}, [%4];"
        : "=r"(r[0]), "=r"(r[1]), "=r"(r[2]), "=r"(r[3]) : "r"(addr));
}
__device__ __forceinline__ unsigned smem_u32(const void* p) {
    return (unsigned)__cvta_generic_to_shared(p);
}

// ---------------- kernel 0: pack weights transposed [n][k2] half2 -------------
__global__ __launch_bounds__(256) void wpack_kernel(
    const float* __restrict__ qw, const float* __restrict__ kw,
    const float* __restrict__ vw, const float* __restrict__ gw,
    const float* __restrict__ ow)
{
    const int i = blockIdx.x * 256 + threadIdx.x;     // [0, 5*8192)
    const int m = i >> 13;
    const int r = i & 8191;
    const int n = r >> 6, k2 = r & 63;
    const float* W = (m==0) ? qw : (m==1) ? kw : (m==2) ? vw : (m==3) ? gw : ow;
    g_wt[i] = h2pack(W[(2*k2)*CH + n], W[(2*k2+1)*CH + n]);
}

// ---------------- kernel 1: fused LN + nb-bias + q/k/v/gate (fp16 mma) -------
__global__ __launch_bounds__(256, 3) void lnproj_mma_kernel(
    const float* __restrict__ pact, const float* __restrict__ lns,
    const float* __restrict__ lnb, const float* __restrict__ f2w,
    const float* __restrict__ gb)
{
    extern __shared__ unsigned smu[];
    unsigned* xs  = smu;               // [64 rows][PADA2] half2 (k-pairs)
    unsigned* wst = smu + 64*PADA2;    // [128 n][PADW] half2 (k-pairs), transposed W
    const int tid = threadIdx.x;
    const int warp = tid >> 5, lane = tid & 31;
    const int gr = lane >> 2, gc = lane & 3;
    const int mw = warp & 1, nw = warp >> 1;
    const int rw0 = mw * 32, nw0 = nw * 32;
    const int r0 = blockIdx.x * 64;

    // per-thread ldmatrix base addresses (byte offsets added per tile)
    const unsigned xs_sh  = smem_u32(xs);
    const unsigned wst_sh = smem_u32(wst);
    const int lrow = lane & 15, lchunk = (lane >> 4) * 16;
    const unsigned aAddr0 = xs_sh  + (rw0      + lrow)*PADA2*4 + lchunk;
    const unsigned aAddr1 = xs_sh  + (rw0 + 16 + lrow)*PADA2*4 + lchunk;
    const unsigned bAddr0 = wst_sh + (nw0      + lrow)*PADW*4  + lchunk;
    const unsigned bAddr1 = wst_sh + (nw0 + 16 + lrow)*PADW*4  + lchunk;

    // ---- stage 1: per-row LayerNorm + nb bias; write half2 X tile -----------
    {
        const float4 sc = ((const float4*)lns)[lane];
        const float4 bi = ((const float4*)lnb)[lane];
        const float4* w4 = (const float4*)f2w;
        const float4 w0 = w4[lane*4+0], w1 = w4[lane*4+1],
                     w2 = w4[lane*4+2], w3 = w4[lane*4+3];
        #pragma unroll 2
        for (int k = 0; k < 8; ++k) {
            const int r = k*8 + warp;
            const size_t p = (size_t)(r0 + r);
            float4 v = ((const float4*)(pact + p*CH))[lane];
            float s = v.x + v.y + v.z + v.w;
            #pragma unroll
            for (int o = 16; o; o >>= 1) s += __shfl_xor_sync(0xffffffffu, s, o);
            const float mu = s * (1.0f/CH);
            const float dx = v.x-mu, dy = v.y-mu, dz = v.z-mu, dw = v.w-mu;
            float ss = dx*dx + dy*dy + dz*dz + dw*dw;
            #pragma unroll
            for (int o = 16; o; o >>= 1) ss += __shfl_xor_sync(0xffffffffu, ss, o);
            const float inv = rsqrtf(ss * (1.0f/CH) + 1e-5f);
            float4 xn;
            xn.x = dx*inv*sc.x + bi.x;
            xn.y = dy*inv*sc.y + bi.y;
            xn.z = dz*inv*sc.z + bi.z;
            xn.w = dw*inv*sc.w + bi.w;
            *(uint2*)(xs + r*PADA2 + lane*2) =
                make_uint2(h2pack(xn.x, xn.y), h2pack(xn.z, xn.w));

            float n0 = xn.x*w0.x + xn.y*w1.x + xn.z*w2.x + xn.w*w3.x;
            float n1 = xn.x*w0.y + xn.y*w1.y + xn.z*w2.y + xn.w*w3.y;
            float n2 = xn.x*w0.z + xn.y*w1.z + xn.z*w2.z + xn.w*w3.z;
            float n3 = xn.x*w0.w + xn.y*w1.w + xn.z*w2.w + xn.w*w3.w;
            #pragma unroll
            for (int o = 16; o; o >>= 1) {
                n0 += __shfl_xor_sync(0xffffffffu, n0, o);
                n1 += __shfl_xor_sync(0xffffffffu, n1, o);
                n2 += __shfl_xor_sync(0xffffffffu, n2, o);
                n3 += __shfl_xor_sync(0xffffffffu, n3, o);
            }
            if (lane == 0) {     // nb scaled by log2e for exp2-based softmax
                g_nb[0*(size_t)NNPIX + p] = __float2half(n0*LOG2E);
                g_nb[1*(size_t)NNPIX + p] = __float2half(n1*LOG2E);
                g_nb[2*(size_t)NNPIX + p] = __float2half(n2*LOG2E);
                g_nb[3*(size_t)NNPIX + p] = __float2half(n3*LOG2E);
            }
        }
    }

    // ---- stage 2: four W passes (W^T pre-packed fp16; raw copy) -------------
    // tile = 128 n-rows x 64 k2-words = 128*16 uint4
    for (int m = 0; m < 4; ++m) {
        const unsigned* Wt = g_wt + m*8192;
        __syncthreads();
        for (int i = tid; i < 128*16; i += 256) {
            const int n = i >> 4, c4 = i & 15;
            uint4 v = ((const uint4*)(Wt + n*64))[c4];
            unsigned* d = wst + n*PADW + c4*4;
            d[0]=v.x; d[1]=v.y; d[2]=v.z; d[3]=v.w;
        }
        __syncthreads();

        float c[2][4][4];
        #pragma unroll
        for (int mi = 0; mi < 2; ++mi)
            #pragma unroll
            for (int ni = 0; ni < 4; ++ni)
                #pragma unroll
                for (int t = 0; t < 4; ++t) c[mi][ni][t] = 0.f;

        #pragma unroll
        for (int t = 0; t < 8; ++t) {
            const unsigned koff = t * 32;   // bytes: 8 k2-words per k16 tile
            unsigned a[2][4], bf[2][4];
            ldsm_x4(a[0], aAddr0 + koff);
            ldsm_x4(a[1], aAddr1 + koff);
            ldsm_x4(bf[0], bAddr0 + koff);  // {b0[0], b1[0], b0[1], b1[1]}
            ldsm_x4(bf[1], bAddr1 + koff);  // {b2[0], b3[0], b2[1], b3[1]}
            #pragma unroll
            for (int mi = 0; mi < 2; ++mi)
                #pragma unroll
                for (int ni = 0; ni < 4; ++ni)
                    mma_f16(c[mi][ni], a[mi], bf[ni>>1][ni&1], bf[ni>>1][2+(ni&1)]);
        }

        __half* outp = (m==0) ? g_q : (m==1) ? g_k : (m==2) ? g_v : g_g;
        #pragma unroll
        for (int mi = 0; mi < 2; ++mi) {
            const int row0 = r0 + rw0 + mi*16 + gr;
            #pragma unroll
            for (int ni = 0; ni < 4; ++ni) {
                const int col = nw0 + ni*8 + gc*2;
                float v0x = c[mi][ni][0], v0y = c[mi][ni][1];
                float v1x = c[mi][ni][2], v1y = c[mi][ni][3];
                if (m == 0) {    // q scaled by 1/sqrt(d) * log2e (exp2 softmax)
                    const float qs = QSCALE * LOG2E;
                    v0x*=qs; v0y*=qs; v1x*=qs; v1y*=qs;
                }
                if (m == 3) {
                    const float2 bb = *(const float2*)(gb + col);
                    v0x = 1.f/(1.f + __expf(-(v0x + bb.x)));
                    v0y = 1.f/(1.f + __expf(-(v0y + bb.y)));
                    v1x = 1.f/(1.f + __expf(-(v1x + bb.x)));
                    v1y = 1.f/(1.f + __expf(-(v1y + bb.y)));
                }
                *(unsigned*)(outp + (size_t)row0*CH + col)     = h2pack(v0x, v0y);
                *(unsigned*)(outp + (size_t)(row0+8)*CH + col) = h2pack(v1x, v1y);
            }
        }
    }
}

// ---------------- kernel 2: flash attention, fp16 mma, exp2 softmax ----------
__global__ __launch_bounds__(256, 3) void attn_mma_kernel(const float* __restrict__ mask)
{
    extern __shared__ unsigned sm_u[];
    unsigned* Kd2 = sm_u;                      // [16 d-pairs][PADK2] half2
    unsigned* Vs  = Kd2 + 16*PADK2;            // [32 d][PADH] half2 (key-pairs)
    float* mrow   = (float*)(Vs + 32*PADH);    // [384]
    const int b = blockIdx.x, h = blockIdx.y;
    const int tid = threadIdx.x, warp = tid >> 5, lane = tid & 31;
    const int gr = lane >> 2, gc = lane & 3;

    // stage K: d-pairs are adjacent halfs in memory -> raw uint4 copy
    for (int i = tid; i < 384*4; i += 256) {
        const int key = i >> 2, q4 = i & 3;
        const unsigned* kb = (const unsigned*)(g_k + ((size_t)(b*NRES)+key)*CH + h*KD);
        uint4 kv = ((const uint4*)kb)[q4];
        Kd2[(q4*4+0)*PADK2 + key] = kv.x;
        Kd2[(q4*4+1)*PADK2 + key] = kv.y;
        Kd2[(q4*4+2)*PADK2 + key] = kv.z;
        Kd2[(q4*4+3)*PADK2 + key] = kv.w;
    }
    // stage V: transpose to key-pair packing via byte permutes.
    for (int i = tid; i < 192*8; i += 256) {
        const int kp = i >> 3, c4 = i & 7;
        const unsigned* v0 = (const unsigned*)(g_v + ((size_t)(b*NRES)+2*kp)*CH + h*KD);
        const unsigned* v1 = (const unsigned*)(g_v + ((size_t)(b*NRES)+2*kp+1)*CH + h*KD);
        uint2 a  = ((const uint2*)v0)[c4];
        uint2 bb = ((const uint2*)v1)[c4];
        Vs[(4*c4+0)*PADH + kp] = __byte_perm(a.x, bb.x, 0x5410);
        Vs[(4*c4+1)*PADH + kp] = __byte_perm(a.x, bb.x, 0x7632);
        Vs[(4*c4+2)*PADH + kp] = __byte_perm(a.y, bb.y, 0x5410);
        Vs[(4*c4+3)*PADH + kp] = __byte_perm(a.y, bb.y, 0x7632);
    }
    for (int i = tid; i < NRES; i += 256)
        mrow[i] = (1e9f*LOG2E) * (mask[(size_t)b*NRES + i] - 1.f);
    __syncthreads();

    for (int p = 0; p < 3; ++p) {
        const int q0 = p*128 + warp*16;
        unsigned qa[2][4];
        const unsigned* qlo = (const unsigned*)(g_q + ((size_t)(b*NRES)+q0+gr)*CH + h*KD);
        const unsigned* qhi = (const unsigned*)(g_q + ((size_t)(b*NRES)+q0+gr+8)*CH + h*KD);
        #pragma unroll
        for (int kc = 0; kc < 2; ++kc) {
            qa[kc][0] = qlo[kc*8 + gc];
            qa[kc][1] = qhi[kc*8 + gc];
            qa[kc][2] = qlo[kc*8 + gc + 4];
            qa[kc][3] = qhi[kc*8 + gc + 4];
        }
        const __half* nb0 = g_nb + (size_t)h*NNPIX + (size_t)(q0+gr)*NRES;
        const __half* nb1 = nb0 + (size_t)8*NRES;

        float sum0 = 0.f, sum1 = 0.f;
        float O[4][4];
        #pragma unroll
        for (int vt = 0; vt < 4; ++vt)
            #pragma unroll
            for (int t = 0; t < 4; ++t) O[vt][t] = 0.f;

        for (int c = 0; c < 6; ++c) {
            const int c0 = c*64;
            float s[8][4];
            #pragma unroll
            for (int t = 0; t < 8; ++t)
                #pragma unroll
                for (int j = 0; j < 4; ++j) s[t][j] = 0.f;

            #pragma unroll
            for (int t = 0; t < 8; ++t) {
                const int n0 = c0 + t*8 + gr;
                #pragma unroll
                for (int kc = 0; kc < 2; ++kc) {
                    mma_f16(s[t], qa[kc],
                            Kd2[(kc*8+gc  )*PADK2 + n0],
                            Kd2[(kc*8+gc+4)*PADK2 + n0]);
                }
            }
            // bias + direct exp2 (logits pre-scaled by log2e; shift-free)
            #pragma unroll
            for (int t = 0; t < 8; ++t) {
                const int col = c0 + t*8 + gc*2;
                const float2 mr  = *(const float2*)(mrow + col);
                const float2 nlo = h2unpack(*(const unsigned*)(nb0 + col));
                const float2 nhi = h2unpack(*(const unsigned*)(nb1 + col));
                s[t][0] = ex2(s[t][0] + mr.x + nlo.x);
                s[t][1] = ex2(s[t][1] + mr.y + nlo.y);
                s[t][2] = ex2(s[t][2] + mr.x + nhi.x);
                s[t][3] = ex2(s[t][3] + mr.y + nhi.y);
                sum0 += s[t][0] + s[t][1];
                sum1 += s[t][2] + s[t][3];
            }

            // PV: P C-frags pack directly into fp16 A-frags
            #pragma unroll
            for (int kc16 = 0; kc16 < 4; ++kc16) {
                const int e = 2*kc16, o = e+1;
                unsigned pa[4];
                pa[0] = h2pack(s[e][0], s[e][1]);
                pa[1] = h2pack(s[e][2], s[e][3]);
                pa[2] = h2pack(s[o][0], s[o][1]);
                pa[3] = h2pack(s[o][2], s[o][3]);
                const int kpb = (c0 >> 1) + kc16*8;
                #pragma unroll
                for (int vt = 0; vt < 4; ++vt) {
                    const unsigned* vrow = Vs + (vt*8+gr)*PADH + kpb;
                    mma_f16(O[vt], pa, vrow[gc], vrow[gc+4]);
                }
            }
        }

        // deferred sum reduction across the quad
        sum0 += __shfl_xor_sync(0xffffffffu, sum0, 1);
        sum0 += __shfl_xor_sync(0xffffffffu, sum0, 2);
        sum1 += __shfl_xor_sync(0xffffffffu, sum1, 1);
        sum1 += __shfl_xor_sync(0xffffffffu, sum1, 2);
        const float inv0 = 1.f / sum0, inv1 = 1.f / sum1;

        const size_t orow0 = ((size_t)(b*NRES)+q0+gr)*CH + h*KD;
        const size_t orow1 = orow0 + (size_t)8*CH;
        #pragma unroll
        for (int vt = 0; vt < 4; ++vt) {
            const int cl = vt*8 + gc*2;
            const float2 g0 = h2unpack(*(const unsigned*)(g_g + orow0 + cl));
            const float2 g1 = h2unpack(*(const unsigned*)(g_g + orow1 + cl));
            *(unsigned*)(g_att + orow0 + cl) =
                h2pack(O[vt][0]*inv0*g0.x, O[vt][1]*inv0*g0.y);
            *(unsigned*)(g_att + orow1 + cl) =
                h2pack(O[vt][2]*inv1*g1.x, O[vt][3]*inv1*g1.y);
        }
    }
}

// ---------------- kernel 3: output projection (fp16 mma + ldmatrix) ----------
__global__ __launch_bounds__(256, 3) void out_mma_kernel(
    const float* __restrict__ ob, float* __restrict__ out)
{
    extern __shared__ unsigned smu[];
    unsigned* xs  = smu;               // [64][PADA2]
    unsigned* wst = smu + 64*PADA2;    // [128][PADW] transposed W
    const int tid = threadIdx.x;
    const int warp = tid >> 5, lane = tid & 31;
    const int gr = lane >> 2, gc = lane & 3;
    const int mw = warp & 1, nw = warp >> 1;
    const int rw0 = mw * 32, nw0 = nw * 32;
    const int r0 = blockIdx.x * 64;

    const unsigned xs_sh  = smem_u32(xs);
    const unsigned wst_sh = smem_u32(wst);
    const int lrow = lane & 15, lchunk = (lane >> 4) * 16;
    const unsigned aAddr0 = xs_sh  + (rw0      + lrow)*PADA2*4 + lchunk;
    const unsigned aAddr1 = xs_sh  + (rw0 + 16 + lrow)*PADA2*4 + lchunk;
    const unsigned bAddr0 = wst_sh + (nw0      + lrow)*PADW*4  + lchunk;
    const unsigned bAddr1 = wst_sh + (nw0 + 16 + lrow)*PADW*4  + lchunk;

    // X staging: raw copy of fp16 g_att. One row = 128 halfs = 16 uint4.
    for (int i = tid; i < 64*16; i += 256) {
        const int r = i >> 4, c4 = i & 15;
        uint4 v = ((const uint4*)(g_att + (size_t)(r0 + r)*CH))[c4];
        unsigned* d = xs + r*PADA2 + c4*4;
        d[0]=v.x; d[1]=v.y; d[2]=v.z; d[3]=v.w;
    }
    // W^T staging: 128 n-rows x 16 uint4
    {
        const unsigned* Wt = g_wt + 4*8192;
        for (int i = tid; i < 128*16; i += 256) {
            const int n = i >> 4, c4 = i & 15;
            uint4 v = ((const uint4*)(Wt + n*64))[c4];
            unsigned* d = wst + n*PADW + c4*4;
            d[0]=v.x; d[1]=v.y; d[2]=v.z; d[3]=v.w;
        }
    }
    __syncthreads();

    float c[2][4][4];
    #pragma unroll
    for (int mi = 0; mi < 2; ++mi)
        #pragma unroll
        for (int ni = 0; ni < 4; ++ni)
            #pragma unroll
            for (int t = 0; t < 4; ++t) c[mi][ni][t] = 0.f;

    #pragma unroll
    for (int t = 0; t < 8; ++t) {
        const unsigned koff = t * 32;
        unsigned a[2][4], bf[2][4];
        ldsm_x4(a[0], aAddr0 + koff);
        ldsm_x4(a[1], aAddr1 + koff);
        ldsm_x4(bf[0], bAddr0 + koff);
        ldsm_x4(bf[1], bAddr1 + koff);
        #pragma unroll
        for (int mi = 0; mi < 2; ++mi)
            #pragma unroll
            for (int ni = 0; ni < 4; ++ni)
                mma_f16(c[mi][ni], a[mi], bf[ni>>1][ni&1], bf[ni>>1][2+(ni&1)]);
    }

    #pragma unroll
    for (int mi = 0; mi < 2; ++mi) {
        const int row0 = r0 + rw0 + mi*16 + gr;
        #pragma unroll
        for (int ni = 0; ni < 4; ++ni) {
            const int col = nw0 + ni*8 + gc*2;
            const float2 bb = *(const float2*)(ob + col);
            *(float2*)(out + (size_t)row0*CH + col) =
                make_float2(c[mi][ni][0] + bb.x, c[mi][ni][1] + bb.y);
            *(float2*)(out + (size_t)(row0+8)*CH + col) =
                make_float2(c[mi][ni][2] + bb.x, c[mi][ni][3] + bb.y);
        }
    }
}

// ---------------- launcher ---------------------------------------------------
extern "C" void kernel_launch(void* const* d_in, const int* in_sizes, int n_in,
                              void* d_out, int out_size)
{
    const float* pact = (const float*)d_in[0];
    const float* mask = (const float*)d_in[1];
    const float* lns  = (const float*)d_in[2];
    const float* lnb  = (const float*)d_in[3];
    const float* f2w  = (const float*)d_in[4];
    const float* qw   = (const float*)d_in[5];
    const float* kw   = (const float*)d_in[6];
    const float* vw   = (const float*)d_in[7];
    const float* gw   = (const float*)d_in[8];
    const float* gb   = (const float*)d_in[9];
    const float* ow   = (const float*)d_in[10];
    const float* ob   = (const float*)d_in[11];
    float* out = (float*)d_out;

    const int GEMM_SMEM = (64*PADA2 + 128*PADW) * 4;              // 52224
    const int ATTN_SMEM = (16*PADK2 + 32*PADH + NRES) * 4;        // 51712

    cudaFuncSetAttribute(lnproj_mma_kernel, cudaFuncAttributeMaxDynamicSharedMemorySize, GEMM_SMEM);
    cudaFuncSetAttribute(out_mma_kernel,    cudaFuncAttributeMaxDynamicSharedMemorySize, GEMM_SMEM);
    cudaFuncSetAttribute(attn_mma_kernel,   cudaFuncAttributeMaxDynamicSharedMemorySize, ATTN_SMEM);

    wpack_kernel<<<160, 256>>>(qw, kw, vw, gw, ow);
    lnproj_mma_kernel<<<NNPIX/64, 256, GEMM_SMEM>>>(pact, lns, lnb, f2w, gb);
    attn_mma_kernel<<<dim3(NRES, NH), 256, ATTN_SMEM>>>(mask);
    out_mma_kernel<<<NNPIX/64, 256, GEMM_SMEM>>>(ob, out);
}

// round 13
// speedup vs baseline: 9.2206x; 1.0072x over previous
#include <cuda_runtime.h>
#include <cuda_fp16.h>
#include <math.h>

#define NRES 384
#define NNPIX (NRES*NRES)          // 147456
#define CH 128
#define NH 4
#define KD 32
#define QSCALE 0.17677669529663689f  // 1/sqrt(32)
#define LOG2E 1.4426950408889634f

#define PADA2 68   // X half2 pad (words/row). rows offset 4 banks -> LDSM conflict-free
#define PADW  68   // W^T half2 pad (words/row), same property
#define PADK2 392  // K half2 pad: B-frag bank = 8*gc+gr -> conflict-free
#define PADH 196   // V half2 pad (key pairs): bank = 4*gr+gc -> conflict-free

// ---------------- scratch (fp16 intermediates) --------------------------------
__device__ __align__(16) __half  g_nb [(size_t)NH*NNPIX];
__device__ __align__(16) __half  g_q  [(size_t)NNPIX*CH];
__device__ __align__(16) __half  g_k  [(size_t)NNPIX*CH];
__device__ __align__(16) __half  g_v  [(size_t)NNPIX*CH];
__device__ __align__(16) __half  g_g  [(size_t)NNPIX*CH];
__device__ __align__(16) __half  g_att[(size_t)NNPIX*CH];
__device__ __align__(16) unsigned g_wt[5*128*64];   // 5 weight mats TRANSPOSED [n][k2] half2

// ---------------- helpers -----------------------------------------------------
__device__ __forceinline__ unsigned h2pack(float lo, float hi) {
    unsigned u;
    asm("cvt.rn.f16x2.f32 %0, %1, %2;" : "=r"(u) : "f"(hi), "f"(lo));
    return u;
}
__device__ __forceinline__ float2 h2unpack(unsigned u) {
    __half2 h = *(__half2*)&u;
    return __half22float2(h);
}
__device__ __forceinline__ float ex2(float x) {
    float y;
    asm("ex2.approx.ftz.f32 %0, %1;" : "=f"(y) : "f"(x));
    return y;
}
__device__ __forceinline__ void mma_f16(float c[4], const unsigned a[4], unsigned b0, unsigned b1) {
    asm volatile(
        "mma.sync.aligned.m16n8k16.row.col.f32.f16.f16.f32 "
        "{%0,%1,%2,%3}, {%4,%5,%6,%7}, {%8,%9}, {%0,%1,%2,%3};"
        : "+f"(c[0]), "+f"(c[1]), "+f"(c[2]), "+f"(c[3])
        : "r"(a[0]), "r"(a[1]), "r"(a[2]), "r"(a[3]), "r"(b0), "r"(b1));
}
__device__ __forceinline__ void ldsm_x4(unsigned r[4], unsigned addr) {
    asm volatile("ldmatrix.sync.aligned.m8n8.x4.shared.b16 {%0,%1,%2,%3}, [%4];"
        : "=r"(r[0]), "=r"(r[1]), "=r"(r[2]), "=r"(r[3]) : "r"(addr));
}
__device__ __forceinline__ unsigned smem_u32(const void* p) {
    return (unsigned)__cvta_generic_to_shared(p);
}

// ---------------- kernel 0: pack weights transposed [n][k2] half2 -------------
__global__ __launch_bounds__(256) void wpack_kernel(
    const float* __restrict__ qw, const float* __restrict__ kw,
    const float* __restrict__ vw, const float* __restrict__ gw,
    const float* __restrict__ ow)
{
    const int i = blockIdx.x * 256 + threadIdx.x;     // [0, 5*8192)
    const int m = i >> 13;
    const int r = i & 8191;
    const int n = r >> 6, k2 = r & 63;
    const float* W = (m==0) ? qw : (m==1) ? kw : (m==2) ? vw : (m==3) ? gw : ow;
    g_wt[i] = h2pack(W[(2*k2)*CH + n], W[(2*k2+1)*CH + n]);
}

// ---------------- kernel 1: fused LN + nb-bias + q/k/v/gate (fp16 mma) -------
__global__ __launch_bounds__(256, 4) void lnproj_mma_kernel(
    const float* __restrict__ pact, const float* __restrict__ lns,
    const float* __restrict__ lnb, const float* __restrict__ f2w,
    const float* __restrict__ gb)
{
    extern __shared__ unsigned smu[];
    unsigned* xs  = smu;               // [64 rows][PADA2] half2 (k-pairs)
    unsigned* wst = smu + 64*PADA2;    // [128 n][PADW] half2 (k-pairs), transposed W
    const int tid = threadIdx.x;
    const int warp = tid >> 5, lane = tid & 31;
    const int gr = lane >> 2, gc = lane & 3;
    const int mw = warp & 1, nw = warp >> 1;
    const int rw0 = mw * 32, nw0 = nw * 32;
    const int r0 = blockIdx.x * 64;

    const unsigned xs_sh  = smem_u32(xs);
    const unsigned wst_sh = smem_u32(wst);
    const int lrow = lane & 15, lchunk = (lane >> 4) * 16;
    const unsigned aAddr0 = xs_sh  + (rw0      + lrow)*PADA2*4 + lchunk;
    const unsigned aAddr1 = xs_sh  + (rw0 + 16 + lrow)*PADA2*4 + lchunk;
    const unsigned bAddr0 = wst_sh + (nw0      + lrow)*PADW*4  + lchunk;
    const unsigned bAddr1 = wst_sh + (nw0 + 16 + lrow)*PADW*4  + lchunk;

    // ---- stage 1: LayerNorm (single-pass sum/sumsq) + nb bias ---------------
    {
        const float4 sc = ((const float4*)lns)[lane];
        const float4 bi = ((const float4*)lnb)[lane];
        const float4* w4 = (const float4*)f2w;
        const float4 w0 = w4[lane*4+0], w1 = w4[lane*4+1],
                     w2 = w4[lane*4+2], w3 = w4[lane*4+3];
        #pragma unroll 2
        for (int k = 0; k < 8; ++k) {
            const int r = k*8 + warp;
            const size_t p = (size_t)(r0 + r);
            float4 v = ((const float4*)(pact + p*CH))[lane];
            float s  = v.x + v.y + v.z + v.w;
            float ss = v.x*v.x + v.y*v.y + v.z*v.z + v.w*v.w;
            #pragma unroll
            for (int o = 16; o; o >>= 1) {          // one interleaved tree
                s  += __shfl_xor_sync(0xffffffffu, s,  o);
                ss += __shfl_xor_sync(0xffffffffu, ss, o);
            }
            const float mu  = s * (1.0f/CH);
            const float var = ss * (1.0f/CH) - mu*mu;
            const float inv = rsqrtf(var + 1e-5f);
            float4 xn;
            xn.x = (v.x-mu)*inv*sc.x + bi.x;
            xn.y = (v.y-mu)*inv*sc.y + bi.y;
            xn.z = (v.z-mu)*inv*sc.z + bi.z;
            xn.w = (v.w-mu)*inv*sc.w + bi.w;
            *(uint2*)(xs + r*PADA2 + lane*2) =
                make_uint2(h2pack(xn.x, xn.y), h2pack(xn.z, xn.w));

            float n0 = xn.x*w0.x + xn.y*w1.x + xn.z*w2.x + xn.w*w3.x;
            float n1 = xn.x*w0.y + xn.y*w1.y + xn.z*w2.y + xn.w*w3.y;
            float n2 = xn.x*w0.z + xn.y*w1.z + xn.z*w2.z + xn.w*w3.z;
            float n3 = xn.x*w0.w + xn.y*w1.w + xn.z*w2.w + xn.w*w3.w;
            #pragma unroll
            for (int o = 16; o; o >>= 1) {
                n0 += __shfl_xor_sync(0xffffffffu, n0, o);
                n1 += __shfl_xor_sync(0xffffffffu, n1, o);
                n2 += __shfl_xor_sync(0xffffffffu, n2, o);
                n3 += __shfl_xor_sync(0xffffffffu, n3, o);
            }
            if (lane == 0) {     // nb scaled by log2e for exp2-based softmax
                g_nb[0*(size_t)NNPIX + p] = __float2half(n0*LOG2E);
                g_nb[1*(size_t)NNPIX + p] = __float2half(n1*LOG2E);
                g_nb[2*(size_t)NNPIX + p] = __float2half(n2*LOG2E);
                g_nb[3*(size_t)NNPIX + p] = __float2half(n3*LOG2E);
            }
        }
    }

    // ---- stage 2: four W passes (W^T pre-packed fp16; raw copy) -------------
    for (int m = 0; m < 4; ++m) {
        const unsigned* Wt = g_wt + m*8192;
        __syncthreads();
        for (int i = tid; i < 128*16; i += 256) {
            const int n = i >> 4, c4 = i & 15;
            uint4 v = ((const uint4*)(Wt + n*64))[c4];
            unsigned* d = wst + n*PADW + c4*4;
            d[0]=v.x; d[1]=v.y; d[2]=v.z; d[3]=v.w;
        }
        __syncthreads();

        float c[2][4][4];
        #pragma unroll
        for (int mi = 0; mi < 2; ++mi)
            #pragma unroll
            for (int ni = 0; ni < 4; ++ni)
                #pragma unroll
                for (int t = 0; t < 4; ++t) c[mi][ni][t] = 0.f;

        #pragma unroll
        for (int t = 0; t < 8; ++t) {
            const unsigned koff = t * 32;
            unsigned a[2][4], bf[2][4];
            ldsm_x4(a[0], aAddr0 + koff);
            ldsm_x4(a[1], aAddr1 + koff);
            ldsm_x4(bf[0], bAddr0 + koff);
            ldsm_x4(bf[1], bAddr1 + koff);
            #pragma unroll
            for (int mi = 0; mi < 2; ++mi)
                #pragma unroll
                for (int ni = 0; ni < 4; ++ni)
                    mma_f16(c[mi][ni], a[mi], bf[ni>>1][ni&1], bf[ni>>1][2+(ni&1)]);
        }

        __half* outp = (m==0) ? g_q : (m==1) ? g_k : (m==2) ? g_v : g_g;
        #pragma unroll
        for (int mi = 0; mi < 2; ++mi) {
            const int row0 = r0 + rw0 + mi*16 + gr;
            #pragma unroll
            for (int ni = 0; ni < 4; ++ni) {
                const int col = nw0 + ni*8 + gc*2;
                float v0x = c[mi][ni][0], v0y = c[mi][ni][1];
                float v1x = c[mi][ni][2], v1y = c[mi][ni][3];
                if (m == 0) {
                    const float qs = QSCALE * LOG2E;
                    v0x*=qs; v0y*=qs; v1x*=qs; v1y*=qs;
                }
                if (m == 3) {
                    const float2 bb = *(const float2*)(gb + col);
                    v0x = 1.f/(1.f + __expf(-(v0x + bb.x)));
                    v0y = 1.f/(1.f + __expf(-(v0y + bb.y)));
                    v1x = 1.f/(1.f + __expf(-(v1x + bb.x)));
                    v1y = 1.f/(1.f + __expf(-(v1y + bb.y)));
                }
                *(unsigned*)(outp + (size_t)row0*CH + col)     = h2pack(v0x, v0y);
                *(unsigned*)(outp + (size_t)(row0+8)*CH + col) = h2pack(v1x, v1y);
            }
        }
    }
}

// ---------------- kernel 2: flash attention, fp16 mma, exp2 softmax ----------
__global__ __launch_bounds__(256, 3) void attn_mma_kernel(const float* __restrict__ mask)
{
    extern __shared__ unsigned sm_u[];
    unsigned* Kd2 = sm_u;                      // [16 d-pairs][PADK2] half2
    unsigned* Vs  = Kd2 + 16*PADK2;            // [32 d][PADH] half2 (key-pairs)
    float* mrow   = (float*)(Vs + 32*PADH);    // [384]
    const int b = blockIdx.x, h = blockIdx.y;
    const int tid = threadIdx.x, warp = tid >> 5, lane = tid & 31;
    const int gr = lane >> 2, gc = lane & 3;

    for (int i = tid; i < 384*4; i += 256) {
        const int key = i >> 2, q4 = i & 3;
        const unsigned* kb = (const unsigned*)(g_k + ((size_t)(b*NRES)+key)*CH + h*KD);
        uint4 kv = ((const uint4*)kb)[q4];
        Kd2[(q4*4+0)*PADK2 + key] = kv.x;
        Kd2[(q4*4+1)*PADK2 + key] = kv.y;
        Kd2[(q4*4+2)*PADK2 + key] = kv.z;
        Kd2[(q4*4+3)*PADK2 + key] = kv.w;
    }
    for (int i = tid; i < 192*8; i += 256) {
        const int kp = i >> 3, c4 = i & 7;
        const unsigned* v0 = (const unsigned*)(g_v + ((size_t)(b*NRES)+2*kp)*CH + h*KD);
        const unsigned* v1 = (const unsigned*)(g_v + ((size_t)(b*NRES)+2*kp+1)*CH + h*KD);
        uint2 a  = ((const uint2*)v0)[c4];
        uint2 bb = ((const uint2*)v1)[c4];
        Vs[(4*c4+0)*PADH + kp] = __byte_perm(a.x, bb.x, 0x5410);
        Vs[(4*c4+1)*PADH + kp] = __byte_perm(a.x, bb.x, 0x7632);
        Vs[(4*c4+2)*PADH + kp] = __byte_perm(a.y, bb.y, 0x5410);
        Vs[(4*c4+3)*PADH + kp] = __byte_perm(a.y, bb.y, 0x7632);
    }
    for (int i = tid; i < NRES; i += 256)
        mrow[i] = (1e9f*LOG2E) * (mask[(size_t)b*NRES + i] - 1.f);
    __syncthreads();

    for (int p = 0; p < 3; ++p) {
        const int q0 = p*128 + warp*16;
        unsigned qa[2][4];
        const unsigned* qlo = (const unsigned*)(g_q + ((size_t)(b*NRES)+q0+gr)*CH + h*KD);
        const unsigned* qhi = (const unsigned*)(g_q + ((size_t)(b*NRES)+q0+gr+8)*CH + h*KD);
        #pragma unroll
        for (int kc = 0; kc < 2; ++kc) {
            qa[kc][0] = qlo[kc*8 + gc];
            qa[kc][1] = qhi[kc*8 + gc];
            qa[kc][2] = qlo[kc*8 + gc + 4];
            qa[kc][3] = qhi[kc*8 + gc + 4];
        }
        const __half* nb0 = g_nb + (size_t)h*NNPIX + (size_t)(q0+gr)*NRES;
        const __half* nb1 = nb0 + (size_t)8*NRES;

        float sum0 = 0.f, sum1 = 0.f;
        float O[4][4];
        #pragma unroll
        for (int vt = 0; vt < 4; ++vt)
            #pragma unroll
            for (int t = 0; t < 4; ++t) O[vt][t] = 0.f;

        for (int c = 0; c < 6; ++c) {
            const int c0 = c*64;
            float s[8][4];
            #pragma unroll
            for (int t = 0; t < 8; ++t)
                #pragma unroll
                for (int j = 0; j < 4; ++j) s[t][j] = 0.f;

            #pragma unroll
            for (int t = 0; t < 8; ++t) {
                const int n0 = c0 + t*8 + gr;
                #pragma unroll
                for (int kc = 0; kc < 2; ++kc) {
                    mma_f16(s[t], qa[kc],
                            Kd2[(kc*8+gc  )*PADK2 + n0],
                            Kd2[(kc*8+gc+4)*PADK2 + n0]);
                }
            }
            #pragma unroll
            for (int t = 0; t < 8; ++t) {
                const int col = c0 + t*8 + gc*2;
                const float2 mr  = *(const float2*)(mrow + col);
                const float2 nlo = h2unpack(*(const unsigned*)(nb0 + col));
                const float2 nhi = h2unpack(*(const unsigned*)(nb1 + col));
                s[t][0] = ex2(s[t][0] + mr.x + nlo.x);
                s[t][1] = ex2(s[t][1] + mr.y + nlo.y);
                s[t][2] = ex2(s[t][2] + mr.x + nhi.x);
                s[t][3] = ex2(s[t][3] + mr.y + nhi.y);
                sum0 += s[t][0] + s[t][1];
                sum1 += s[t][2] + s[t][3];
            }

            #pragma unroll
            for (int kc16 = 0; kc16 < 4; ++kc16) {
                const int e = 2*kc16, o = e+1;
                unsigned pa[4];
                pa[0] = h2pack(s[e][0], s[e][1]);
                pa[1] = h2pack(s[e][2], s[e][3]);
                pa[2] = h2pack(s[o][0], s[o][1]);
                pa[3] = h2pack(s[o][2], s[o][3]);
                const int kpb = (c0 >> 1) + kc16*8;
                #pragma unroll
                for (int vt = 0; vt < 4; ++vt) {
                    const unsigned* vrow = Vs + (vt*8+gr)*PADH + kpb;
                    mma_f16(O[vt], pa, vrow[gc], vrow[gc+4]);
                }
            }
        }

        sum0 += __shfl_xor_sync(0xffffffffu, sum0, 1);
        sum0 += __shfl_xor_sync(0xffffffffu, sum0, 2);
        sum1 += __shfl_xor_sync(0xffffffffu, sum1, 1);
        sum1 += __shfl_xor_sync(0xffffffffu, sum1, 2);
        const float inv0 = 1.f / sum0, inv1 = 1.f / sum1;

        const size_t orow0 = ((size_t)(b*NRES)+q0+gr)*CH + h*KD;
        const size_t orow1 = orow0 + (size_t)8*CH;
        #pragma unroll
        for (int vt = 0; vt < 4; ++vt) {
            const int cl = vt*8 + gc*2;
            const float2 g0 = h2unpack(*(const unsigned*)(g_g + orow0 + cl));
            const float2 g1 = h2unpack(*(const unsigned*)(g_g + orow1 + cl));
            *(unsigned*)(g_att + orow0 + cl) =
                h2pack(O[vt][0]*inv0*g0.x, O[vt][1]*inv0*g0.y);
            *(unsigned*)(g_att + orow1 + cl) =
                h2pack(O[vt][2]*inv1*g1.x, O[vt][3]*inv1*g1.y);
        }
    }
}

// ---------------- kernel 3: output projection (fp16 mma + ldmatrix) ----------
__global__ __launch_bounds__(256, 4) void out_mma_kernel(
    const float* __restrict__ ob, float* __restrict__ out)
{
    extern __shared__ unsigned smu[];
    unsigned* xs  = smu;               // [64][PADA2]
    unsigned* wst = smu + 64*PADA2;    // [128][PADW] transposed W
    const int tid = threadIdx.x;
    const int warp = tid >> 5, lane = tid & 31;
    const int gr = lane >> 2, gc = lane & 3;
    const int mw = warp & 1, nw = warp >> 1;
    const int rw0 = mw * 32, nw0 = nw * 32;
    const int r0 = blockIdx.x * 64;

    const unsigned xs_sh  = smem_u32(xs);
    const unsigned wst_sh = smem_u32(wst);
    const int lrow = lane & 15, lchunk = (lane >> 4) * 16;
    const unsigned aAddr0 = xs_sh  + (rw0      + lrow)*PADA2*4 + lchunk;
    const unsigned aAddr1 = xs_sh  + (rw0 + 16 + lrow)*PADA2*4 + lchunk;
    const unsigned bAddr0 = wst_sh + (nw0      + lrow)*PADW*4  + lchunk;
    const unsigned bAddr1 = wst_sh + (nw0 + 16 + lrow)*PADW*4  + lchunk;

    for (int i = tid; i < 64*16; i += 256) {
        const int r = i >> 4, c4 = i & 15;
        uint4 v = ((const uint4*)(g_att + (size_t)(r0 + r)*CH))[c4];
        unsigned* d = xs + r*PADA2 + c4*4;
        d[0]=v.x; d[1]=v.y; d[2]=v.z; d[3]=v.w;
    }
    {
        const unsigned* Wt = g_wt + 4*8192;
        for (int i = tid; i < 128*16; i += 256) {
            const int n = i >> 4, c4 = i & 15;
            uint4 v = ((const uint4*)(Wt + n*64))[c4];
            unsigned* d = wst + n*PADW + c4*4;
            d[0]=v.x; d[1]=v.y; d[2]=v.z; d[3]=v.w;
        }
    }
    __syncthreads();

    float c[2][4][4];
    #pragma unroll
    for (int mi = 0; mi < 2; ++mi)
        #pragma unroll
        for (int ni = 0; ni < 4; ++ni)
            #pragma unroll
            for (int t = 0; t < 4; ++t) c[mi][ni][t] = 0.f;

    #pragma unroll
    for (int t = 0; t < 8; ++t) {
        const unsigned koff = t * 32;
        unsigned a[2][4], bf[2][4];
        ldsm_x4(a[0], aAddr0 + koff);
        ldsm_x4(a[1], aAddr1 + koff);
        ldsm_x4(bf[0], bAddr0 + koff);
        ldsm_x4(bf[1], bAddr1 + koff);
        #pragma unroll
        for (int mi = 0; mi < 2; ++mi)
            #pragma unroll
            for (int ni = 0; ni < 4; ++ni)
                mma_f16(c[mi][ni], a[mi], bf[ni>>1][ni&1], bf[ni>>1][2+(ni&1)]);
    }

    #pragma unroll
    for (int mi = 0; mi < 2; ++mi) {
        const int row0 = r0 + rw0 + mi*16 + gr;
        #pragma unroll
        for (int ni = 0; ni < 4; ++ni) {
            const int col = nw0 + ni*8 + gc*2;
            const float2 bb = *(const float2*)(ob + col);
            *(float2*)(out + (size_t)row0*CH + col) =
                make_float2(c[mi][ni][0] + bb.x, c[mi][ni][1] + bb.y);
            *(float2*)(out + (size_t)(row0+8)*CH + col) =
                make_float2(c[mi][ni][2] + bb.x, c[mi][ni][3] + bb.y);
        }
    }
}

// ---------------- launcher ---------------------------------------------------
extern "C" void kernel_launch(void* const* d_in, const int* in_sizes, int n_in,
                              void* d_out, int out_size)
{
    const float* pact = (const float*)d_in[0];
    const float* mask = (const float*)d_in[1];
    const float* lns  = (const float*)d_in[2];
    const float* lnb  = (const float*)d_in[3];
    const float* f2w  = (const float*)d_in[4];
    const float* qw   = (const float*)d_in[5];
    const float* kw   = (const float*)d_in[6];
    const float* vw   = (const float*)d_in[7];
    const float* gw   = (const float*)d_in[8];
    const float* gb   = (const float*)d_in[9];
    const float* ow   = (const float*)d_in[10];
    const float* ob   = (const float*)d_in[11];
    float* out = (float*)d_out;

    const int GEMM_SMEM = (64*PADA2 + 128*PADW) * 4;              // 52224
    const int ATTN_SMEM = (16*PADK2 + 32*PADH + NRES) * 4;        // 51712

    cudaFuncSetAttribute(lnproj_mma_kernel, cudaFuncAttributeMaxDynamicSharedMemorySize, GEMM_SMEM);
    cudaFuncSetAttribute(out_mma_kernel,    cudaFuncAttributeMaxDynamicSharedMemorySize, GEMM_SMEM);
    cudaFuncSetAttribute(attn_mma_kernel,   cudaFuncAttributeMaxDynamicSharedMemorySize, ATTN_SMEM);

    wpack_kernel<<<160, 256>>>(qw, kw, vw, gw, ow);
    lnproj_mma_kernel<<<NNPIX/64, 256, GEMM_SMEM>>>(pact, lns, lnb, f2w, gb);
    attn_mma_kernel<<<dim3(NRES, NH), 256, ATTN_SMEM>>>(mask);
    out_mma_kernel<<<NNPIX/64, 256, GEMM_SMEM>>>(ob, out);
}

// round 14
// speedup vs baseline: 9.7438x; 1.0567x over previous
#include <cuda_runtime.h>
#include <cuda_fp16.h>
#include <math.h>

#define NRES 384
#define NNPIX (NRES*NRES)          // 147456
#define CH 128
#define NH 4
#define KD 32
#define QSCALE 0.17677669529663689f  // 1/sqrt(32)
#define LOG2E 1.4426950408889634f

#define PADA2 68   // X half2 pad (words/row). rows offset 4 banks -> LDSM conflict-free
#define PADW  68   // W^T half2 pad (words/row), same property
#define PADK2 392  // K half2 pad: B-frag bank = 8*gc+gr -> conflict-free
#define PADH 196   // V half2 pad (key pairs): bank = 4*gr+gc -> conflict-free

// ---------------- scratch (fp16 intermediates) --------------------------------
__device__ __align__(16) __half  g_nb [(size_t)NH*NNPIX];
__device__ __align__(16) __half  g_q  [(size_t)NNPIX*CH];
__device__ __align__(16) __half  g_k  [(size_t)NNPIX*CH];
__device__ __align__(16) __half  g_v  [(size_t)NNPIX*CH];
__device__ __align__(16) __half  g_g  [(size_t)NNPIX*CH];
__device__ __align__(16) __half  g_att[(size_t)NNPIX*CH];
__device__ __align__(16) unsigned g_wt[5*128*64];   // 5 weight mats TRANSPOSED [n][k2] half2

// ---------------- helpers -----------------------------------------------------
__device__ __forceinline__ unsigned h2pack(float lo, float hi) {
    unsigned u;
    asm("cvt.rn.f16x2.f32 %0, %1, %2;" : "=r"(u) : "f"(hi), "f"(lo));
    return u;
}
__device__ __forceinline__ float2 h2unpack(unsigned u) {
    __half2 h = *(__half2*)&u;
    return __half22float2(h);
}
__device__ __forceinline__ float ex2(float x) {
    float y;
    asm("ex2.approx.ftz.f32 %0, %1;" : "=f"(y) : "f"(x));
    return y;
}
__device__ __forceinline__ void mma_f16(float c[4], const unsigned a[4], unsigned b0, unsigned b1) {
    asm volatile(
        "mma.sync.aligned.m16n8k16.row.col.f32.f16.f16.f32 "
        "{%0,%1,%2,%3}, {%4,%5,%6,%7}, {%8,%9}, {%0,%1,%2,%3};"
        : "+f"(c[0]), "+f"(c[1]), "+f"(c[2]), "+f"(c[3])
        : "r"(a[0]), "r"(a[1]), "r"(a[2]), "r"(a[3]), "r"(b0), "r"(b1));
}
__device__ __forceinline__ void ldsm_x4(unsigned r[4], unsigned addr) {
    asm volatile("ldmatrix.sync.aligned.m8n8.x4.shared.b16 {%0,%1,%2,%3}, [%4];"
        : "=r"(r[0]), "=r"(r[1]), "=r"(r[2]), "=r"(r[3]) : "r"(addr));
}
__device__ __forceinline__ unsigned smem_u32(const void* p) {
    return (unsigned)__cvta_generic_to_shared(p);
}
__device__ __forceinline__ void cp16(unsigned dst_sh, const void* src) {
    asm volatile("cp.async.cg.shared.global [%0], [%1], 16;" :: "r"(dst_sh), "l"(src));
}
__device__ __forceinline__ void cp_commit() {
    asm volatile("cp.async.commit_group;");
}
__device__ __forceinline__ void cp_wait0() {
    asm volatile("cp.async.wait_group 0;" ::: "memory");
}

// ---------------- kernel 0: pack weights transposed [n][k2] half2 -------------
__global__ __launch_bounds__(256) void wpack_kernel(
    const float* __restrict__ qw, const float* __restrict__ kw,
    const float* __restrict__ vw, const float* __restrict__ gw,
    const float* __restrict__ ow)
{
    const int i = blockIdx.x * 256 + threadIdx.x;     // [0, 5*8192)
    const int m = i >> 13;
    const int r = i & 8191;
    const int n = r >> 6, k2 = r & 63;
    const float* W = (m==0) ? qw : (m==1) ? kw : (m==2) ? vw : (m==3) ? gw : ow;
    g_wt[i] = h2pack(W[(2*k2)*CH + n], W[(2*k2+1)*CH + n]);
}

// ---------------- kernel 1: fused LN + nb-bias + q/k/v/gate (fp16 mma) -------
__global__ __launch_bounds__(256, 4) void lnproj_mma_kernel(
    const float* __restrict__ pact, const float* __restrict__ lns,
    const float* __restrict__ lnb, const float* __restrict__ f2w,
    const float* __restrict__ gb)
{
    extern __shared__ unsigned smu[];
    unsigned* xs  = smu;               // [64 rows][PADA2] half2 (k-pairs)
    unsigned* wst = smu + 64*PADA2;    // [128 n][PADW] half2 (k-pairs), transposed W
    const int tid = threadIdx.x;
    const int warp = tid >> 5, lane = tid & 31;
    const int gr = lane >> 2, gc = lane & 3;
    const int mw = warp & 1, nw = warp >> 1;
    const int rw0 = mw * 32, nw0 = nw * 32;
    const int r0 = blockIdx.x * 64;

    const unsigned xs_sh  = smem_u32(xs);
    const unsigned wst_sh = smem_u32(wst);
    const int lrow = lane & 15, lchunk = (lane >> 4) * 16;
    const unsigned aAddr0 = xs_sh  + (rw0      + lrow)*PADA2*4 + lchunk;
    const unsigned aAddr1 = xs_sh  + (rw0 + 16 + lrow)*PADA2*4 + lchunk;
    const unsigned bAddr0 = wst_sh + (nw0      + lrow)*PADW*4  + lchunk;
    const unsigned bAddr1 = wst_sh + (nw0 + 16 + lrow)*PADW*4  + lchunk;

    // ---- prefetch W[0] via cp.async: hidden behind the whole LN stage -------
    for (int i = tid; i < 128*16; i += 256) {
        const int n = i >> 4, c4 = i & 15;
        cp16(wst_sh + (n*PADW + c4*4)*4, g_wt + n*64 + c4*4);
    }
    cp_commit();

    // ---- stage 1: LayerNorm (single-pass sum/sumsq) + nb bias ---------------
    {
        const float4 sc = ((const float4*)lns)[lane];
        const float4 bi = ((const float4*)lnb)[lane];
        const float4* w4 = (const float4*)f2w;
        const float4 w0 = w4[lane*4+0], w1 = w4[lane*4+1],
                     w2 = w4[lane*4+2], w3 = w4[lane*4+3];
        #pragma unroll 2
        for (int k = 0; k < 8; ++k) {
            const int r = k*8 + warp;
            const size_t p = (size_t)(r0 + r);
            float4 v = ((const float4*)(pact + p*CH))[lane];
            float s  = v.x + v.y + v.z + v.w;
            float ss = v.x*v.x + v.y*v.y + v.z*v.z + v.w*v.w;
            #pragma unroll
            for (int o = 16; o; o >>= 1) {
                s  += __shfl_xor_sync(0xffffffffu, s,  o);
                ss += __shfl_xor_sync(0xffffffffu, ss, o);
            }
            const float mu  = s * (1.0f/CH);
            const float var = ss * (1.0f/CH) - mu*mu;
            const float inv = rsqrtf(var + 1e-5f);
            float4 xn;
            xn.x = (v.x-mu)*inv*sc.x + bi.x;
            xn.y = (v.y-mu)*inv*sc.y + bi.y;
            xn.z = (v.z-mu)*inv*sc.z + bi.z;
            xn.w = (v.w-mu)*inv*sc.w + bi.w;
            *(uint2*)(xs + r*PADA2 + lane*2) =
                make_uint2(h2pack(xn.x, xn.y), h2pack(xn.z, xn.w));

            float n0 = xn.x*w0.x + xn.y*w1.x + xn.z*w2.x + xn.w*w3.x;
            float n1 = xn.x*w0.y + xn.y*w1.y + xn.z*w2.y + xn.w*w3.y;
            float n2 = xn.x*w0.z + xn.y*w1.z + xn.z*w2.z + xn.w*w3.z;
            float n3 = xn.x*w0.w + xn.y*w1.w + xn.z*w2.w + xn.w*w3.w;
            #pragma unroll
            for (int o = 16; o; o >>= 1) {
                n0 += __shfl_xor_sync(0xffffffffu, n0, o);
                n1 += __shfl_xor_sync(0xffffffffu, n1, o);
                n2 += __shfl_xor_sync(0xffffffffu, n2, o);
                n3 += __shfl_xor_sync(0xffffffffu, n3, o);
            }
            if (lane == 0) {     // nb scaled by log2e for exp2-based softmax
                g_nb[0*(size_t)NNPIX + p] = __float2half(n0*LOG2E);
                g_nb[1*(size_t)NNPIX + p] = __float2half(n1*LOG2E);
                g_nb[2*(size_t)NNPIX + p] = __float2half(n2*LOG2E);
                g_nb[3*(size_t)NNPIX + p] = __float2half(n3*LOG2E);
            }
        }
    }

    // ---- stage 2: four W passes, cp.async pipelined --------------------------
    for (int m = 0; m < 4; ++m) {
        cp_wait0();
        __syncthreads();          // W[m] staged + (m==0) xs visible

        float c[2][4][4];
        #pragma unroll
        for (int mi = 0; mi < 2; ++mi)
            #pragma unroll
            for (int ni = 0; ni < 4; ++ni)
                #pragma unroll
                for (int t = 0; t < 4; ++t) c[mi][ni][t] = 0.f;

        #pragma unroll
        for (int t = 0; t < 8; ++t) {
            const unsigned koff = t * 32;
            unsigned a[2][4], bf[2][4];
            ldsm_x4(a[0], aAddr0 + koff);
            ldsm_x4(a[1], aAddr1 + koff);
            ldsm_x4(bf[0], bAddr0 + koff);
            ldsm_x4(bf[1], bAddr1 + koff);
            #pragma unroll
            for (int mi = 0; mi < 2; ++mi)
                #pragma unroll
                for (int ni = 0; ni < 4; ++ni)
                    mma_f16(c[mi][ni], a[mi], bf[ni>>1][ni&1], bf[ni>>1][2+(ni&1)]);
        }

        __syncthreads();          // everyone done reading W[m]
        if (m < 3) {              // launch W[m+1] load; overlaps epilogue
            const unsigned* Wt = g_wt + (m+1)*8192;
            for (int i = tid; i < 128*16; i += 256) {
                const int n = i >> 4, c4 = i & 15;
                cp16(wst_sh + (n*PADW + c4*4)*4, Wt + n*64 + c4*4);
            }
            cp_commit();
        }

        __half* outp = (m==0) ? g_q : (m==1) ? g_k : (m==2) ? g_v : g_g;
        #pragma unroll
        for (int mi = 0; mi < 2; ++mi) {
            const int row0 = r0 + rw0 + mi*16 + gr;
            #pragma unroll
            for (int ni = 0; ni < 4; ++ni) {
                const int col = nw0 + ni*8 + gc*2;
                float v0x = c[mi][ni][0], v0y = c[mi][ni][1];
                float v1x = c[mi][ni][2], v1y = c[mi][ni][3];
                if (m == 0) {
                    const float qs = QSCALE * LOG2E;
                    v0x*=qs; v0y*=qs; v1x*=qs; v1y*=qs;
                }
                if (m == 3) {
                    const float2 bb = *(const float2*)(gb + col);
                    v0x = 1.f/(1.f + __expf(-(v0x + bb.x)));
                    v0y = 1.f/(1.f + __expf(-(v0y + bb.y)));
                    v1x = 1.f/(1.f + __expf(-(v1x + bb.x)));
                    v1y = 1.f/(1.f + __expf(-(v1y + bb.y)));
                }
                *(unsigned*)(outp + (size_t)row0*CH + col)     = h2pack(v0x, v0y);
                *(unsigned*)(outp + (size_t)(row0+8)*CH + col) = h2pack(v1x, v1y);
            }
        }
    }
}

// ---------------- kernel 2: flash attention, fp16 mma, exp2 softmax ----------
__global__ __launch_bounds__(256, 3) void attn_mma_kernel(const float* __restrict__ mask)
{
    extern __shared__ unsigned sm_u[];
    unsigned* Kd2 = sm_u;                      // [16 d-pairs][PADK2] half2
    unsigned* Vs  = Kd2 + 16*PADK2;            // [32 d][PADH] half2 (key-pairs)
    float* mrow   = (float*)(Vs + 32*PADH);    // [384]
    const int b = blockIdx.x, h = blockIdx.y;
    const int tid = threadIdx.x, warp = tid >> 5, lane = tid & 31;
    const int gr = lane >> 2, gc = lane & 3;

    for (int i = tid; i < 384*4; i += 256) {
        const int key = i >> 2, q4 = i & 3;
        const unsigned* kb = (const unsigned*)(g_k + ((size_t)(b*NRES)+key)*CH + h*KD);
        uint4 kv = ((const uint4*)kb)[q4];
        Kd2[(q4*4+0)*PADK2 + key] = kv.x;
        Kd2[(q4*4+1)*PADK2 + key] = kv.y;
        Kd2[(q4*4+2)*PADK2 + key] = kv.z;
        Kd2[(q4*4+3)*PADK2 + key] = kv.w;
    }
    for (int i = tid; i < 192*8; i += 256) {
        const int kp = i >> 3, c4 = i & 7;
        const unsigned* v0 = (const unsigned*)(g_v + ((size_t)(b*NRES)+2*kp)*CH + h*KD);
        const unsigned* v1 = (const unsigned*)(g_v + ((size_t)(b*NRES)+2*kp+1)*CH + h*KD);
        uint2 a  = ((const uint2*)v0)[c4];
        uint2 bb = ((const uint2*)v1)[c4];
        Vs[(4*c4+0)*PADH + kp] = __byte_perm(a.x, bb.x, 0x5410);
        Vs[(4*c4+1)*PADH + kp] = __byte_perm(a.x, bb.x, 0x7632);
        Vs[(4*c4+2)*PADH + kp] = __byte_perm(a.y, bb.y, 0x5410);
        Vs[(4*c4+3)*PADH + kp] = __byte_perm(a.y, bb.y, 0x7632);
    }
    for (int i = tid; i < NRES; i += 256)
        mrow[i] = (1e9f*LOG2E) * (mask[(size_t)b*NRES + i] - 1.f);
    __syncthreads();

    for (int p = 0; p < 3; ++p) {
        const int q0 = p*128 + warp*16;
        unsigned qa[2][4];
        const unsigned* qlo = (const unsigned*)(g_q + ((size_t)(b*NRES)+q0+gr)*CH + h*KD);
        const unsigned* qhi = (const unsigned*)(g_q + ((size_t)(b*NRES)+q0+gr+8)*CH + h*KD);
        #pragma unroll
        for (int kc = 0; kc < 2; ++kc) {
            qa[kc][0] = qlo[kc*8 + gc];
            qa[kc][1] = qhi[kc*8 + gc];
            qa[kc][2] = qlo[kc*8 + gc + 4];
            qa[kc][3] = qhi[kc*8 + gc + 4];
        }
        const __half* nb0 = g_nb + (size_t)h*NNPIX + (size_t)(q0+gr)*NRES;
        const __half* nb1 = nb0 + (size_t)8*NRES;

        float sum0 = 0.f, sum1 = 0.f;
        float O[4][4];
        #pragma unroll
        for (int vt = 0; vt < 4; ++vt)
            #pragma unroll
            for (int t = 0; t < 4; ++t) O[vt][t] = 0.f;

        for (int c = 0; c < 6; ++c) {
            const int c0 = c*64;
            float s[8][4];
            #pragma unroll
            for (int t = 0; t < 8; ++t)
                #pragma unroll
                for (int j = 0; j < 4; ++j) s[t][j] = 0.f;

            #pragma unroll
            for (int t = 0; t < 8; ++t) {
                const int n0 = c0 + t*8 + gr;
                #pragma unroll
                for (int kc = 0; kc < 2; ++kc) {
                    mma_f16(s[t], qa[kc],
                            Kd2[(kc*8+gc  )*PADK2 + n0],
                            Kd2[(kc*8+gc+4)*PADK2 + n0]);
                }
            }
            #pragma unroll
            for (int t = 0; t < 8; ++t) {
                const int col = c0 + t*8 + gc*2;
                const float2 mr  = *(const float2*)(mrow + col);
                const float2 nlo = h2unpack(*(const unsigned*)(nb0 + col));
                const float2 nhi = h2unpack(*(const unsigned*)(nb1 + col));
                s[t][0] = ex2(s[t][0] + mr.x + nlo.x);
                s[t][1] = ex2(s[t][1] + mr.y + nlo.y);
                s[t][2] = ex2(s[t][2] + mr.x + nhi.x);
                s[t][3] = ex2(s[t][3] + mr.y + nhi.y);
                sum0 += s[t][0] + s[t][1];
                sum1 += s[t][2] + s[t][3];
            }

            #pragma unroll
            for (int kc16 = 0; kc16 < 4; ++kc16) {
                const int e = 2*kc16, o = e+1;
                unsigned pa[4];
                pa[0] = h2pack(s[e][0], s[e][1]);
                pa[1] = h2pack(s[e][2], s[e][3]);
                pa[2] = h2pack(s[o][0], s[o][1]);
                pa[3] = h2pack(s[o][2], s[o][3]);
                const int kpb = (c0 >> 1) + kc16*8;
                #pragma unroll
                for (int vt = 0; vt < 4; ++vt) {
                    const unsigned* vrow = Vs + (vt*8+gr)*PADH + kpb;
                    mma_f16(O[vt], pa, vrow[gc], vrow[gc+4]);
                }
            }
        }

        sum0 += __shfl_xor_sync(0xffffffffu, sum0, 1);
        sum0 += __shfl_xor_sync(0xffffffffu, sum0, 2);
        sum1 += __shfl_xor_sync(0xffffffffu, sum1, 1);
        sum1 += __shfl_xor_sync(0xffffffffu, sum1, 2);
        const float inv0 = 1.f / sum0, inv1 = 1.f / sum1;

        const size_t orow0 = ((size_t)(b*NRES)+q0+gr)*CH + h*KD;
        const size_t orow1 = orow0 + (size_t)8*CH;
        #pragma unroll
        for (int vt = 0; vt < 4; ++vt) {
            const int cl = vt*8 + gc*2;
            const float2 g0 = h2unpack(*(const unsigned*)(g_g + orow0 + cl));
            const float2 g1 = h2unpack(*(const unsigned*)(g_g + orow1 + cl));
            *(unsigned*)(g_att + orow0 + cl) =
                h2pack(O[vt][0]*inv0*g0.x, O[vt][1]*inv0*g0.y);
            *(unsigned*)(g_att + orow1 + cl) =
                h2pack(O[vt][2]*inv1*g1.x, O[vt][3]*inv1*g1.y);
        }
    }
}

// ---------------- kernel 3: output projection (fp16 mma + ldmatrix) ----------
__global__ __launch_bounds__(256, 4) void out_mma_kernel(
    const float* __restrict__ ob, float* __restrict__ out)
{
    extern __shared__ unsigned smu[];
    unsigned* xs  = smu;               // [64][PADA2]
    unsigned* wst = smu + 64*PADA2;    // [128][PADW] transposed W
    const int tid = threadIdx.x;
    const int warp = tid >> 5, lane = tid & 31;
    const int gr = lane >> 2, gc = lane & 3;
    const int mw = warp & 1, nw = warp >> 1;
    const int rw0 = mw * 32, nw0 = nw * 32;
    const int r0 = blockIdx.x * 64;

    const unsigned xs_sh  = smem_u32(xs);
    const unsigned wst_sh = smem_u32(wst);
    const int lrow = lane & 15, lchunk = (lane >> 4) * 16;
    const unsigned aAddr0 = xs_sh  + (rw0      + lrow)*PADA2*4 + lchunk;
    const unsigned aAddr1 = xs_sh  + (rw0 + 16 + lrow)*PADA2*4 + lchunk;
    const unsigned bAddr0 = wst_sh + (nw0      + lrow)*PADW*4  + lchunk;
    const unsigned bAddr1 = wst_sh + (nw0 + 16 + lrow)*PADW*4  + lchunk;

    // X + W staging via cp.async (issue everything, wait once)
    for (int i = tid; i < 64*16; i += 256) {
        const int r = i >> 4, c4 = i & 15;
        cp16(xs_sh + (r*PADA2 + c4*4)*4,
             (const char*)(g_att + (size_t)(r0 + r)*CH) + c4*16);
    }
    {
        const unsigned* Wt = g_wt + 4*8192;
        for (int i = tid; i < 128*16; i += 256) {
            const int n = i >> 4, c4 = i & 15;
            cp16(wst_sh + (n*PADW + c4*4)*4, Wt + n*64 + c4*4);
        }
    }
    cp_commit();
    cp_wait0();
    __syncthreads();

    float c[2][4][4];
    #pragma unroll
    for (int mi = 0; mi < 2; ++mi)
        #pragma unroll
        for (int ni = 0; ni < 4; ++ni)
            #pragma unroll
            for (int t = 0; t < 4; ++t) c[mi][ni][t] = 0.f;

    #pragma unroll
    for (int t = 0; t < 8; ++t) {
        const unsigned koff = t * 32;
        unsigned a[2][4], bf[2][4];
        ldsm_x4(a[0], aAddr0 + koff);
        ldsm_x4(a[1], aAddr1 + koff);
        ldsm_x4(bf[0], bAddr0 + koff);
        ldsm_x4(bf[1], bAddr1 + koff);
        #pragma unroll
        for (int mi = 0; mi < 2; ++mi)
            #pragma unroll
            for (int ni = 0; ni < 4; ++ni)
                mma_f16(c[mi][ni], a[mi], bf[ni>>1][ni&1], bf[ni>>1][2+(ni&1)]);
    }

    #pragma unroll
    for (int mi = 0; mi < 2; ++mi) {
        const int row0 = r0 + rw0 + mi*16 + gr;
        #pragma unroll
        for (int ni = 0; ni < 4; ++ni) {
            const int col = nw0 + ni*8 + gc*2;
            const float2 bb = *(const float2*)(ob + col);
            *(float2*)(out + (size_t)row0*CH + col) =
                make_float2(c[mi][ni][0] + bb.x, c[mi][ni][1] + bb.y);
            *(float2*)(out + (size_t)(row0+8)*CH + col) =
                make_float2(c[mi][ni][2] + bb.x, c[mi][ni][3] + bb.y);
        }
    }
}

// ---------------- launcher ---------------------------------------------------
extern "C" void kernel_launch(void* const* d_in, const int* in_sizes, int n_in,
                              void* d_out, int out_size)
{
    const float* pact = (const float*)d_in[0];
    const float* mask = (const float*)d_in[1];
    const float* lns  = (const float*)d_in[2];
    const float* lnb  = (const float*)d_in[3];
    const float* f2w  = (const float*)d_in[4];
    const float* qw   = (const float*)d_in[5];
    const float* kw   = (const float*)d_in[6];
    const float* vw   = (const float*)d_in[7];
    const float* gw   = (const float*)d_in[8];
    const float* gb   = (const float*)d_in[9];
    const float* ow   = (const float*)d_in[10];
    const float* ob   = (const float*)d_in[11];
    float* out = (float*)d_out;

    const int GEMM_SMEM = (64*PADA2 + 128*PADW) * 4;              // 52224
    const int ATTN_SMEM = (16*PADK2 + 32*PADH + NRES) * 4;        // 51712

    cudaFuncSetAttribute(lnproj_mma_kernel, cudaFuncAttributeMaxDynamicSharedMemorySize, GEMM_SMEM);
    cudaFuncSetAttribute(out_mma_kernel,    cudaFuncAttributeMaxDynamicSharedMemorySize, GEMM_SMEM);
    cudaFuncSetAttribute(attn_mma_kernel,   cudaFuncAttributeMaxDynamicSharedMemorySize, ATTN_SMEM);

    wpack_kernel<<<160, 256>>>(qw, kw, vw, gw, ow);
    lnproj_mma_kernel<<<NNPIX/64, 256, GEMM_SMEM>>>(pact, lns, lnb, f2w, gb);
    attn_mma_kernel<<<dim3(NRES, NH), 256, ATTN_SMEM>>>(mask);
    out_mma_kernel<<<NNPIX/64, 256, GEMM_SMEM>>>(ob, out);
}